// round 1
// baseline (speedup 1.0000x reference)
#include <cuda_runtime.h>

#define N_SNP  100000
#define N_GENE 20000
#define N_ALL  120000
#define HID    128
#define NEG    0.2f

#define ACT_NONE    0
#define ACT_RELU    1
#define ACT_TANHSUM 2

// ---------------- device scratch (static, allocation-free) ----------------
__device__ float    g_hs[N_SNP * HID];
__device__ float    g_hg[N_GENE * HID];
__device__ float    g_ssrc_sg[N_SNP * 8];
__device__ float    g_sdst_gs[N_SNP * 8];
__device__ float    g_sdst_sg[N_GENE * 8];
__device__ float    g_ssrc_gs[N_GENE * 8];
__device__ float    g_ssrc_gg[N_GENE * 8];
__device__ float    g_sdst_gg[N_GENE * 8];
__device__ unsigned g_m_sg[N_GENE * 8];
__device__ unsigned g_m_gs[N_SNP * 8];
__device__ unsigned g_m_gg[N_GENE * 8];
__device__ float    g_sum_sg[N_GENE * 8];
__device__ float    g_sum_gs[N_SNP * 8];
__device__ float    g_sum_gg[N_GENE * 8];
__device__ float    g_o_sg[N_GENE * HID];
__device__ float    g_o_gs[N_SNP * HID];
__device__ float    g_o_gg[N_GENE * HID];
__device__ float    g_out_s0[N_SNP * HID];
__device__ float    g_out_s1[N_SNP * HID];
__device__ float    g_out_g0[N_GENE * HID];
__device__ float    g_out_g1[N_GENE * HID];
__device__ float    g_sem[2 * HID];
__device__ float    g_attn[2];
__device__ float    g_buf1[N_ALL * HID];
__device__ float    g_buf2[N_ALL * HID];

// ---------------- helpers ----------------
__device__ __forceinline__ unsigned encf(float f) {
    unsigned u = __float_as_uint(f);
    return (u & 0x80000000u) ? ~u : (u | 0x80000000u);
}
__device__ __forceinline__ float decf(unsigned u) {
    return __uint_as_float((u & 0x80000000u) ? (u & 0x7fffffffu) : ~u);
}

__global__ void fill_f4(float4* p, float v, int n4) {
    int i = blockIdx.x * blockDim.x + threadIdx.x;
    if (i < n4) p[i] = make_float4(v, v, v, v);
}
__global__ void fill_u32k(unsigned* p, unsigned v, int n) {
    int i = blockIdx.x * blockDim.x + threadIdx.x;
    if (i < n) p[i] = v;
}

// ---------------- GEMM: C[M,128] = act(A[M,128] @ W[128,128] + b) ----------------
// 256 threads, 32 rows/block (M always multiple of 32). W + A tile in dyn smem (80KB).
__global__ void gemm128(const float* __restrict__ A, const float* __restrict__ W,
                        const float* __restrict__ bias, float* __restrict__ C,
                        float* __restrict__ colsum, int act)
{
    extern __shared__ float sm[];
    float* sW = sm;               // 128*128
    float* sA = sm + 128 * 128;   // 32*128
    const int tid = threadIdx.x;

    const float4* W4 = (const float4*)W;
    float4* sW4 = (float4*)sW;
#pragma unroll
    for (int i = 0; i < 16; i++) sW4[tid + 256 * i] = W4[tid + 256 * i];

    const float4* A4 = (const float4*)(A + (size_t)blockIdx.x * 32 * 128);
    float4* sA4 = (float4*)sA;
#pragma unroll
    for (int i = 0; i < 4; i++) {
        float4 v = A4[tid + 256 * i];
        if (act == ACT_TANHSUM) {
            v.x = fmaxf(v.x, 0.f); v.y = fmaxf(v.y, 0.f);
            v.z = fmaxf(v.z, 0.f); v.w = fmaxf(v.w, 0.f);
        }
        sA4[tid + 256 * i] = v;
    }
    __syncthreads();

    const int warp = tid >> 5, lane = tid & 31;
    const float* ar = sA + warp * 4 * 128;
    const float* wp = sW + lane;

    float acc[4][4];
#pragma unroll
    for (int r = 0; r < 4; r++)
#pragma unroll
        for (int j = 0; j < 4; j++) acc[r][j] = 0.f;

#pragma unroll 4
    for (int k = 0; k < 128; ++k) {
        float w0 = wp[k * 128], w1 = wp[k * 128 + 32];
        float w2 = wp[k * 128 + 64], w3 = wp[k * 128 + 96];
#pragma unroll
        for (int r = 0; r < 4; r++) {
            float xv = ar[r * 128 + k];
            acc[r][0] = fmaf(xv, w0, acc[r][0]);
            acc[r][1] = fmaf(xv, w1, acc[r][1]);
            acc[r][2] = fmaf(xv, w2, acc[r][2]);
            acc[r][3] = fmaf(xv, w3, acc[r][3]);
        }
    }

    float b0 = bias[lane], b1 = bias[lane + 32], b2 = bias[lane + 64], b3 = bias[lane + 96];
    size_t row0 = (size_t)blockIdx.x * 32 + warp * 4;

    if (act == ACT_TANHSUM) {
        float cs0 = 0, cs1 = 0, cs2 = 0, cs3 = 0;
#pragma unroll
        for (int r = 0; r < 4; r++) {
            cs0 += tanhf(acc[r][0] + b0);
            cs1 += tanhf(acc[r][1] + b1);
            cs2 += tanhf(acc[r][2] + b2);
            cs3 += tanhf(acc[r][3] + b3);
        }
        atomicAdd(colsum + lane, cs0);
        atomicAdd(colsum + lane + 32, cs1);
        atomicAdd(colsum + lane + 64, cs2);
        atomicAdd(colsum + lane + 96, cs3);
    } else {
#pragma unroll
        for (int r = 0; r < 4; r++) {
            float v0 = acc[r][0] + b0, v1 = acc[r][1] + b1;
            float v2 = acc[r][2] + b2, v3 = acc[r][3] + b3;
            if (act == ACT_RELU) {
                v0 = fmaxf(v0, 0.f); v1 = fmaxf(v1, 0.f);
                v2 = fmaxf(v2, 0.f); v3 = fmaxf(v3, 0.f);
            }
            float* cp = C + (row0 + r) * 128;
            cp[lane] = v0; cp[lane + 32] = v1; cp[lane + 64] = v2; cp[lane + 96] = v3;
        }
    }
}

// ---------------- per-node attention score dots ----------------
__global__ void scores2(const float* __restrict__ h, int N,
                        const float* __restrict__ a0, const float* __restrict__ a1,
                        float* __restrict__ s0, float* __restrict__ s1)
{
    int idx = blockIdx.x * blockDim.x + threadIdx.x;
    if (idx >= N * 8) return;
    int n = idx >> 3, hd = idx & 7;
    const float4* hp = (const float4*)(h + (size_t)n * 128 + hd * 16);
    const float4* p0 = (const float4*)(a0 + hd * 16);
    const float4* p1 = (const float4*)(a1 + hd * 16);
    float d0 = 0, d1 = 0;
#pragma unroll
    for (int i = 0; i < 4; i++) {
        float4 hv = hp[i];
        float4 av = p0[i];
        d0 += hv.x * av.x + hv.y * av.y + hv.z * av.z + hv.w * av.w;
        av = p1[i];
        d1 += hv.x * av.x + hv.y * av.y + hv.z * av.z + hv.w * av.w;
    }
    s0[idx] = d0; s1[idx] = d1;
}

__global__ void scores4(const float* __restrict__ h, int N,
                        const float* __restrict__ a0, const float* __restrict__ a1,
                        const float* __restrict__ a2, const float* __restrict__ a3,
                        float* __restrict__ s0, float* __restrict__ s1,
                        float* __restrict__ s2, float* __restrict__ s3)
{
    int idx = blockIdx.x * blockDim.x + threadIdx.x;
    if (idx >= N * 8) return;
    int n = idx >> 3, hd = idx & 7;
    const float4* hp = (const float4*)(h + (size_t)n * 128 + hd * 16);
    const float4* p0 = (const float4*)(a0 + hd * 16);
    const float4* p1 = (const float4*)(a1 + hd * 16);
    const float4* p2 = (const float4*)(a2 + hd * 16);
    const float4* p3 = (const float4*)(a3 + hd * 16);
    float d0 = 0, d1 = 0, d2 = 0, d3 = 0;
#pragma unroll
    for (int i = 0; i < 4; i++) {
        float4 hv = hp[i];
        float4 av = p0[i];
        d0 += hv.x * av.x + hv.y * av.y + hv.z * av.z + hv.w * av.w;
        av = p1[i];
        d1 += hv.x * av.x + hv.y * av.y + hv.z * av.z + hv.w * av.w;
        av = p2[i];
        d2 += hv.x * av.x + hv.y * av.y + hv.z * av.z + hv.w * av.w;
        av = p3[i];
        d3 += hv.x * av.x + hv.y * av.y + hv.z * av.z + hv.w * av.w;
    }
    s0[idx] = d0; s1[idx] = d1; s2[idx] = d2; s3[idx] = d3;
}

// ---------------- edge softmax passes ----------------
__global__ void attn_max(const float* __restrict__ ssrc, const float* __restrict__ sdst,
                         const int* __restrict__ src, const int* __restrict__ dst,
                         int E, unsigned* __restrict__ mbuf)
{
    int idx = blockIdx.x * blockDim.x + threadIdx.x;
    if (idx >= E * 8) return;
    int e = idx >> 3, hd = idx & 7;
    int s = src[e], d = dst[e];
    float a = ssrc[s * 8 + hd] + sdst[d * 8 + hd];
    a = a > 0.f ? a : NEG * a;
    atomicMax(mbuf + d * 8 + hd, encf(a));
}

__global__ void attn_sum(const float* __restrict__ ssrc, const float* __restrict__ sdst,
                         const int* __restrict__ src, const int* __restrict__ dst,
                         int E, const unsigned* __restrict__ mbuf, float* __restrict__ sumbuf)
{
    int idx = blockIdx.x * blockDim.x + threadIdx.x;
    if (idx >= E * 8) return;
    int e = idx >> 3, hd = idx & 7;
    int s = src[e], d = dst[e];
    float a = ssrc[s * 8 + hd] + sdst[d * 8 + hd];
    a = a > 0.f ? a : NEG * a;
    float m = decf(mbuf[d * 8 + hd]);
    atomicAdd(sumbuf + d * 8 + hd, __expf(a - m));
}

// ---------------- weighted message aggregation (vector red) ----------------
__global__ void msg_k(const float* __restrict__ hsrc,
                      const float* __restrict__ ssrc, const float* __restrict__ sdst,
                      const int* __restrict__ src, const int* __restrict__ dst, int E,
                      const unsigned* __restrict__ mbuf, const float* __restrict__ sumbuf,
                      float* __restrict__ out)
{
    int idx = blockIdx.x * blockDim.x + threadIdx.x;
    if (idx >= E * 32) return;
    int e = idx >> 5, lane = idx & 31;
    int s = src[e], d = dst[e];
    int hd = lane >> 2;
    float a = ssrc[s * 8 + hd] + sdst[d * 8 + hd];
    a = a > 0.f ? a : NEG * a;
    float m = decf(mbuf[d * 8 + hd]);
    float w = __expf(a - m) / (sumbuf[d * 8 + hd] + 1e-16f);
    float4 v = *((const float4*)(hsrc + (size_t)s * 128) + lane);
    v.x *= w; v.y *= w; v.z *= w; v.w *= w;
    float* p = out + (size_t)d * 128 + lane * 4;
    unsigned long long gp = (unsigned long long)__cvta_generic_to_global(p);
    asm volatile("red.global.add.v4.f32 [%0], {%1,%2,%3,%4};"
                 :: "l"(gp), "f"(v.x), "f"(v.y), "f"(v.z), "f"(v.w) : "memory");
}

// ---------------- semantic softmax (2 metapaths) ----------------
__global__ void sem_softmax(const float* __restrict__ q, const float* __restrict__ cs,
                            float* __restrict__ attn)
{
    __shared__ float sc[2];
    int m = threadIdx.x >> 5, lane = threadIdx.x & 31;
    float s = 0;
#pragma unroll
    for (int i = 0; i < 4; i++) s += q[lane + 32 * i] * cs[m * 128 + lane + 32 * i];
#pragma unroll
    for (int o = 16; o; o >>= 1) s += __shfl_xor_sync(0xffffffffu, s, o);
    if (lane == 0) sc[m] = s / 20000.f;
    __syncthreads();
    if (threadIdx.x == 0) {
        float mx = fmaxf(sc[0], sc[1]);
        float e0 = __expf(sc[0] - mx), e1 = __expf(sc[1] - mx);
        float inv = 1.f / (e0 + e1);
        attn[0] = e0 * inv; attn[1] = e1 * inv;
    }
}

// ---------------- relu + (semantic combine) + LayerNorm (warp per row) ----------------
__global__ void combine_ln(const float* __restrict__ o1, const float* __restrict__ o2,
                           const float* __restrict__ attn,
                           const float* __restrict__ g, const float* __restrict__ b,
                           float* __restrict__ out, int N)
{
    int idx = blockIdx.x * blockDim.x + threadIdx.x;
    int n = idx >> 5, lane = idx & 31;
    if (n >= N) return;
    float4 v = *((const float4*)(o1 + (size_t)n * 128) + lane);
    v.x = fmaxf(v.x, 0.f); v.y = fmaxf(v.y, 0.f); v.z = fmaxf(v.z, 0.f); v.w = fmaxf(v.w, 0.f);
    if (o2) {
        float a0 = attn[0], a1 = attn[1];
        float4 u = *((const float4*)(o2 + (size_t)n * 128) + lane);
        u.x = fmaxf(u.x, 0.f); u.y = fmaxf(u.y, 0.f); u.z = fmaxf(u.z, 0.f); u.w = fmaxf(u.w, 0.f);
        v.x = a0 * v.x + a1 * u.x;
        v.y = a0 * v.y + a1 * u.y;
        v.z = a0 * v.z + a1 * u.z;
        v.w = a0 * v.w + a1 * u.w;
    }
    float s = v.x + v.y + v.z + v.w;
#pragma unroll
    for (int o = 16; o; o >>= 1) s += __shfl_xor_sync(0xffffffffu, s, o);
    float mu = s * (1.f / 128.f);
    float dx = v.x - mu, dy = v.y - mu, dz = v.z - mu, dw = v.w - mu;
    float qv = dx * dx + dy * dy + dz * dz + dw * dw;
#pragma unroll
    for (int o = 16; o; o >>= 1) qv += __shfl_xor_sync(0xffffffffu, qv, o);
    float rs = rsqrtf(qv * (1.f / 128.f) + 1e-5f);
    float4 g4 = *((const float4*)g + lane);
    float4 b4 = *((const float4*)b + lane);
    float4 r;
    r.x = dx * rs * g4.x + b4.x;
    r.y = dy * rs * g4.y + b4.y;
    r.z = dz * rs * g4.z + b4.z;
    r.w = dw * rs * g4.w + b4.w;
    *((float4*)(out + (size_t)n * 128) + lane) = r;
}

// ---------------- fusion over 2 layers ----------------
__global__ void fuse_k(const float* __restrict__ s0, const float* __restrict__ s1,
                       const float* __restrict__ g0, const float* __restrict__ g1,
                       const float* __restrict__ fw, float* __restrict__ z)
{
    int idx = blockIdx.x * blockDim.x + threadIdx.x;
    if (idx >= N_ALL * 32) return;
    int n = idx >> 5, c = idx & 31;
    float w0 = fw[0], w1 = fw[1];
    float inv = 1.f / (w0 + w1);
    float4 a, b;
    if (n < N_SNP) {
        a = ((const float4*)(s0 + (size_t)n * 128))[c];
        b = ((const float4*)(s1 + (size_t)n * 128))[c];
    } else {
        int m = n - N_SNP;
        a = ((const float4*)(g0 + (size_t)m * 128))[c];
        b = ((const float4*)(g1 + (size_t)m * 128))[c];
    }
    float4 r;
    r.x = (w0 * a.x + w1 * b.x) * inv;
    r.y = (w0 * a.y + w1 * b.y) * inv;
    r.z = (w0 * a.z + w1 * b.z) * inv;
    r.w = (w0 * a.w + w1 * b.w) * inv;
    ((float4*)(z + (size_t)n * 128))[c] = r;
}

// ---------------- final 128->2 projection ----------------
__global__ void out_k(const float* __restrict__ A, const float* __restrict__ W,
                      const float* __restrict__ b, float* __restrict__ out, int M)
{
    int idx = blockIdx.x * blockDim.x + threadIdx.x;
    int n = idx >> 5, lane = idx & 31;
    if (n >= M) return;
    const float* ar = A + (size_t)n * 128;
    float a0 = 0, a1 = 0;
#pragma unroll
    for (int i = 0; i < 4; i++) {
        float v = ar[lane + 32 * i];
        a0 += v * W[(lane + 32 * i) * 2];
        a1 += v * W[(lane + 32 * i) * 2 + 1];
    }
#pragma unroll
    for (int o = 16; o; o >>= 1) {
        a0 += __shfl_xor_sync(0xffffffffu, a0, o);
        a1 += __shfl_xor_sync(0xffffffffu, a1, o);
    }
    if (lane == 0) { out[(size_t)n * 2] = a0 + b[0]; out[(size_t)n * 2 + 1] = a1 + b[1]; }
}

static inline int cdiv(long a, int b) { return (int)((a + b - 1) / b); }

extern "C" void kernel_launch(void* const* d_in, const int* in_sizes, int n_in,
                              void* d_out, int out_size)
{
    const float* x_snp  = (const float*)d_in[0];
    const float* x_gene = (const float*)d_in[1];
    const float* Wp_snp = (const float*)d_in[2];
    const float* bp_snp = (const float*)d_in[3];
    const float* Wp_gene= (const float*)d_in[4];
    const float* bp_gene= (const float*)d_in[5];
    const float* a_src  = (const float*)d_in[6];
    const float* a_dst  = (const float*)d_in[7];
    const float* Wk     = (const float*)d_in[8];
    const float* bk     = (const float*)d_in[9];
    const float* qvp    = (const float*)d_in[10];
    const float* ln_g   = (const float*)d_in[11];
    const float* ln_b   = (const float*)d_in[12];
    const float* fw     = (const float*)d_in[13];
    const float* Wfp    = (const float*)d_in[14];
    const float* bfp    = (const float*)d_in[15];
    const float* Wo1    = (const float*)d_in[16];
    const float* bo1    = (const float*)d_in[17];
    const float* Wo2    = (const float*)d_in[18];
    const float* bo2    = (const float*)d_in[19];
    const int* sg_s = (const int*)d_in[20];
    const int* sg_d = (const int*)d_in[21];
    const int* gs_s = (const int*)d_in[22];
    const int* gs_d = (const int*)d_in[23];
    const int* gg_s = (const int*)d_in[24];
    const int* gg_d = (const int*)d_in[25];
    const int E_sg = in_sizes[20], E_gs = in_sizes[22], E_gg = in_sizes[24];

    float *hs, *hg, *ssrc_sg, *sdst_gs, *sdst_sg, *ssrc_gs, *ssrc_gg, *sdst_gg;
    unsigned *m_sg, *m_gs, *m_gg;
    float *sum_sg, *sum_gs, *sum_gg, *o_sg, *o_gs, *o_gg;
    float *out_s0, *out_s1, *out_g0, *out_g1, *sem, *attn, *buf1, *buf2;
    cudaGetSymbolAddress((void**)&hs, g_hs);
    cudaGetSymbolAddress((void**)&hg, g_hg);
    cudaGetSymbolAddress((void**)&ssrc_sg, g_ssrc_sg);
    cudaGetSymbolAddress((void**)&sdst_gs, g_sdst_gs);
    cudaGetSymbolAddress((void**)&sdst_sg, g_sdst_sg);
    cudaGetSymbolAddress((void**)&ssrc_gs, g_ssrc_gs);
    cudaGetSymbolAddress((void**)&ssrc_gg, g_ssrc_gg);
    cudaGetSymbolAddress((void**)&sdst_gg, g_sdst_gg);
    cudaGetSymbolAddress((void**)&m_sg, g_m_sg);
    cudaGetSymbolAddress((void**)&m_gs, g_m_gs);
    cudaGetSymbolAddress((void**)&m_gg, g_m_gg);
    cudaGetSymbolAddress((void**)&sum_sg, g_sum_sg);
    cudaGetSymbolAddress((void**)&sum_gs, g_sum_gs);
    cudaGetSymbolAddress((void**)&sum_gg, g_sum_gg);
    cudaGetSymbolAddress((void**)&o_sg, g_o_sg);
    cudaGetSymbolAddress((void**)&o_gs, g_o_gs);
    cudaGetSymbolAddress((void**)&o_gg, g_o_gg);
    cudaGetSymbolAddress((void**)&out_s0, g_out_s0);
    cudaGetSymbolAddress((void**)&out_s1, g_out_s1);
    cudaGetSymbolAddress((void**)&out_g0, g_out_g0);
    cudaGetSymbolAddress((void**)&out_g1, g_out_g1);
    cudaGetSymbolAddress((void**)&sem, g_sem);
    cudaGetSymbolAddress((void**)&attn, g_attn);
    cudaGetSymbolAddress((void**)&buf1, g_buf1);
    cudaGetSymbolAddress((void**)&buf2, g_buf2);

    const int SMEM = (128 * 128 + 32 * 128) * 4;  // 80 KB
    cudaFuncSetAttribute(gemm128, cudaFuncAttributeMaxDynamicSharedMemorySize, SMEM);

    const unsigned ENC_NINF = 0x007fffffu;  // encf(-inf)

    for (int l = 0; l < 2; ++l) {
        const float* ins = l ? out_s0 : x_snp;
        const float* ing = l ? out_g0 : x_gene;

        gemm128<<<N_SNP / 32, 256, SMEM>>>(ins, Wp_snp + l * 128 * 128, bp_snp + l * 128,
                                           hs, nullptr, ACT_NONE);
        gemm128<<<N_GENE / 32, 256, SMEM>>>(ing, Wp_gene + l * 128 * 128, bp_gene + l * 128,
                                            hg, nullptr, ACT_NONE);

        scores2<<<cdiv((long)N_SNP * 8, 256), 256>>>(hs, N_SNP,
            a_src + (l * 3 + 0) * 128, a_dst + (l * 3 + 1) * 128, ssrc_sg, sdst_gs);
        scores4<<<cdiv((long)N_GENE * 8, 256), 256>>>(hg, N_GENE,
            a_dst + (l * 3 + 0) * 128, a_src + (l * 3 + 1) * 128,
            a_src + (l * 3 + 2) * 128, a_dst + (l * 3 + 2) * 128,
            sdst_sg, ssrc_gs, ssrc_gg, sdst_gg);

        fill_u32k<<<cdiv((long)N_GENE * 8, 256), 256>>>(m_sg, ENC_NINF, N_GENE * 8);
        fill_u32k<<<cdiv((long)N_SNP * 8, 256), 256>>>(m_gs, ENC_NINF, N_SNP * 8);
        fill_u32k<<<cdiv((long)N_GENE * 8, 256), 256>>>(m_gg, ENC_NINF, N_GENE * 8);
        fill_f4<<<cdiv((long)N_GENE * 2, 256), 256>>>((float4*)sum_sg, 0.f, N_GENE * 2);
        fill_f4<<<cdiv((long)N_SNP * 2, 256), 256>>>((float4*)sum_gs, 0.f, N_SNP * 2);
        fill_f4<<<cdiv((long)N_GENE * 2, 256), 256>>>((float4*)sum_gg, 0.f, N_GENE * 2);
        fill_f4<<<cdiv((long)N_GENE * 32, 256), 256>>>((float4*)o_sg, 0.f, N_GENE * 32);
        fill_f4<<<cdiv((long)N_SNP * 32, 256), 256>>>((float4*)o_gs, 0.f, N_SNP * 32);
        fill_f4<<<cdiv((long)N_GENE * 32, 256), 256>>>((float4*)o_gg, 0.f, N_GENE * 32);

        attn_max<<<cdiv((long)E_sg * 8, 256), 256>>>(ssrc_sg, sdst_sg, sg_s, sg_d, E_sg, m_sg);
        attn_max<<<cdiv((long)E_gs * 8, 256), 256>>>(ssrc_gs, sdst_gs, gs_s, gs_d, E_gs, m_gs);
        attn_max<<<cdiv((long)E_gg * 8, 256), 256>>>(ssrc_gg, sdst_gg, gg_s, gg_d, E_gg, m_gg);

        attn_sum<<<cdiv((long)E_sg * 8, 256), 256>>>(ssrc_sg, sdst_sg, sg_s, sg_d, E_sg, m_sg, sum_sg);
        attn_sum<<<cdiv((long)E_gs * 8, 256), 256>>>(ssrc_gs, sdst_gs, gs_s, gs_d, E_gs, m_gs, sum_gs);
        attn_sum<<<cdiv((long)E_gg * 8, 256), 256>>>(ssrc_gg, sdst_gg, gg_s, gg_d, E_gg, m_gg, sum_gg);

        msg_k<<<cdiv((long)E_sg * 32, 256), 256>>>(hs, ssrc_sg, sdst_sg, sg_s, sg_d, E_sg, m_sg, sum_sg, o_sg);
        msg_k<<<cdiv((long)E_gs * 32, 256), 256>>>(hg, ssrc_gs, sdst_gs, gs_s, gs_d, E_gs, m_gs, sum_gs, o_gs);
        msg_k<<<cdiv((long)E_gg * 32, 256), 256>>>(hg, ssrc_gg, sdst_gg, gg_s, gg_d, E_gg, m_gg, sum_gg, o_gg);

        fill_f4<<<1, 64>>>((float4*)sem, 0.f, 64);
        gemm128<<<N_GENE / 32, 256, SMEM>>>(o_sg, Wk + l * 128 * 128, bk + l * 128,
                                            nullptr, sem, ACT_TANHSUM);
        gemm128<<<N_GENE / 32, 256, SMEM>>>(o_gg, Wk + l * 128 * 128, bk + l * 128,
                                            nullptr, sem + 128, ACT_TANHSUM);
        sem_softmax<<<1, 64>>>(qvp + l * 128, sem, attn);

        float* og = l ? out_g1 : out_g0;
        float* os = l ? out_s1 : out_s0;
        combine_ln<<<cdiv((long)N_GENE * 32, 256), 256>>>(o_sg, o_gg, attn,
            ln_g + l * 128, ln_b + l * 128, og, N_GENE);
        combine_ln<<<cdiv((long)N_SNP * 32, 256), 256>>>(o_gs, nullptr, nullptr,
            ln_g + l * 128, ln_b + l * 128, os, N_SNP);
    }

    fuse_k<<<cdiv((long)N_ALL * 32, 256), 256>>>(out_s0, out_s1, out_g0, out_g1, fw, buf1);
    gemm128<<<N_ALL / 32, 256, SMEM>>>(buf1, Wfp, bfp, buf2, nullptr, ACT_RELU);
    gemm128<<<N_ALL / 32, 256, SMEM>>>(buf2, Wo1, bo1, buf1, nullptr, ACT_RELU);
    out_k<<<cdiv((long)N_ALL * 32, 256), 256>>>(buf1, Wo2, bo2, (float*)d_out, N_ALL);
}

// round 2
// speedup vs baseline: 1.1493x; 1.1493x over previous
#include <cuda_runtime.h>

#define N_SNP  100000
#define N_GENE 20000
#define N_ALL  120000
#define HID    128
#define NEG    0.2f

#define ACT_NONE    0
#define ACT_RELU    1
#define ACT_TANHSUM 2

// ---------------- device scratch (static, allocation-free) ----------------
__device__ float    g_hs[N_SNP * HID];
__device__ float    g_hg[N_GENE * HID];
__device__ float    g_ssrc_sg[N_SNP * 8];
__device__ float    g_sdst_gs[N_SNP * 8];
__device__ float    g_sdst_sg[N_GENE * 8];
__device__ float    g_ssrc_gs[N_GENE * 8];
__device__ float    g_ssrc_gg[N_GENE * 8];
__device__ float    g_sdst_gg[N_GENE * 8];
__device__ float    g_sum_sg[N_GENE * 8];
__device__ float    g_sum_gs[N_SNP * 8];
__device__ float    g_sum_gg[N_GENE * 8];
__device__ float    g_o_sg[N_GENE * HID];
__device__ float    g_o_gs[N_SNP * HID];
__device__ float    g_o_gg[N_GENE * HID];
__device__ float    g_out_s0[N_SNP * HID];
__device__ float    g_out_s1[N_SNP * HID];
__device__ float    g_out_g0[N_GENE * HID];
__device__ float    g_out_g1[N_GENE * HID];
__device__ float    g_sem[2 * HID];
__device__ float    g_attn[2];
__device__ float    g_buf1[N_ALL * HID];
__device__ float    g_buf2[N_ALL * HID];

__global__ void fill_f4(float4* p, float v, int n4) {
    int i = blockIdx.x * blockDim.x + threadIdx.x;
    if (i < n4) p[i] = make_float4(v, v, v, v);
}

// ---------------- GEMM: C[M,128] = act(A[M,128] @ W[128,128] + b) ----------------
// 256 threads, 32 rows/block. W + A tile in dyn smem (80KB).
// For ACT_TANHSUM, A is pre-normalized per (row, head) by asum and relu'd.
__global__ void gemm128(const float* __restrict__ A, const float* __restrict__ W,
                        const float* __restrict__ bias, float* __restrict__ C,
                        float* __restrict__ colsum, const float* __restrict__ asum,
                        int act)
{
    extern __shared__ float sm[];
    float* sW = sm;               // 128*128
    float* sA = sm + 128 * 128;   // 32*128
    const int tid = threadIdx.x;
    const int rowbase = blockIdx.x * 32;

    const float4* W4 = (const float4*)W;
    float4* sW4 = (float4*)sW;
#pragma unroll
    for (int i = 0; i < 16; i++) sW4[tid + 256 * i] = W4[tid + 256 * i];

    const float4* A4 = (const float4*)(A + (size_t)rowbase * 128);
    float4* sA4 = (float4*)sA;
#pragma unroll
    for (int i = 0; i < 4; i++) {
        int idx = tid + 256 * i;
        float4 v = A4[idx];
        if (act == ACT_TANHSUM) {
            int rl = idx >> 5, head = (idx & 31) >> 2;
            float sc = 1.f / (asum[(size_t)(rowbase + rl) * 8 + head] + 1e-16f);
            v.x = fmaxf(v.x, 0.f) * sc; v.y = fmaxf(v.y, 0.f) * sc;
            v.z = fmaxf(v.z, 0.f) * sc; v.w = fmaxf(v.w, 0.f) * sc;
        }
        sA4[idx] = v;
    }
    __syncthreads();

    const int warp = tid >> 5, lane = tid & 31;
    const float* ar = sA + warp * 4 * 128;
    const float* wp = sW + lane;

    float acc[4][4];
#pragma unroll
    for (int r = 0; r < 4; r++)
#pragma unroll
        for (int j = 0; j < 4; j++) acc[r][j] = 0.f;

#pragma unroll 4
    for (int k = 0; k < 128; ++k) {
        float w0 = wp[k * 128], w1 = wp[k * 128 + 32];
        float w2 = wp[k * 128 + 64], w3 = wp[k * 128 + 96];
#pragma unroll
        for (int r = 0; r < 4; r++) {
            float xv = ar[r * 128 + k];
            acc[r][0] = fmaf(xv, w0, acc[r][0]);
            acc[r][1] = fmaf(xv, w1, acc[r][1]);
            acc[r][2] = fmaf(xv, w2, acc[r][2]);
            acc[r][3] = fmaf(xv, w3, acc[r][3]);
        }
    }

    float b0 = bias[lane], b1 = bias[lane + 32], b2 = bias[lane + 64], b3 = bias[lane + 96];
    size_t row0 = (size_t)rowbase + warp * 4;

    if (act == ACT_TANHSUM) {
        float cs0 = 0, cs1 = 0, cs2 = 0, cs3 = 0;
#pragma unroll
        for (int r = 0; r < 4; r++) {
            cs0 += tanhf(acc[r][0] + b0);
            cs1 += tanhf(acc[r][1] + b1);
            cs2 += tanhf(acc[r][2] + b2);
            cs3 += tanhf(acc[r][3] + b3);
        }
        atomicAdd(colsum + lane, cs0);
        atomicAdd(colsum + lane + 32, cs1);
        atomicAdd(colsum + lane + 64, cs2);
        atomicAdd(colsum + lane + 96, cs3);
    } else {
#pragma unroll
        for (int r = 0; r < 4; r++) {
            float v0 = acc[r][0] + b0, v1 = acc[r][1] + b1;
            float v2 = acc[r][2] + b2, v3 = acc[r][3] + b3;
            if (act == ACT_RELU) {
                v0 = fmaxf(v0, 0.f); v1 = fmaxf(v1, 0.f);
                v2 = fmaxf(v2, 0.f); v3 = fmaxf(v3, 0.f);
            }
            float* cp = C + (row0 + r) * 128;
            cp[lane] = v0; cp[lane + 32] = v1; cp[lane + 64] = v2; cp[lane + 96] = v3;
        }
    }
}

// ---------------- per-node attention score dots ----------------
__global__ void scores2(const float* __restrict__ h, int N,
                        const float* __restrict__ a0, const float* __restrict__ a1,
                        float* __restrict__ s0, float* __restrict__ s1)
{
    int idx = blockIdx.x * blockDim.x + threadIdx.x;
    if (idx >= N * 8) return;
    int n = idx >> 3, hd = idx & 7;
    const float4* hp = (const float4*)(h + (size_t)n * 128 + hd * 16);
    const float4* p0 = (const float4*)(a0 + hd * 16);
    const float4* p1 = (const float4*)(a1 + hd * 16);
    float d0 = 0, d1 = 0;
#pragma unroll
    for (int i = 0; i < 4; i++) {
        float4 hv = hp[i];
        float4 av = p0[i];
        d0 += hv.x * av.x + hv.y * av.y + hv.z * av.z + hv.w * av.w;
        av = p1[i];
        d1 += hv.x * av.x + hv.y * av.y + hv.z * av.z + hv.w * av.w;
    }
    s0[idx] = d0; s1[idx] = d1;
}

__global__ void scores4(const float* __restrict__ h, int N,
                        const float* __restrict__ a0, const float* __restrict__ a1,
                        const float* __restrict__ a2, const float* __restrict__ a3,
                        float* __restrict__ s0, float* __restrict__ s1,
                        float* __restrict__ s2, float* __restrict__ s3)
{
    int idx = blockIdx.x * blockDim.x + threadIdx.x;
    if (idx >= N * 8) return;
    int n = idx >> 3, hd = idx & 7;
    const float4* hp = (const float4*)(h + (size_t)n * 128 + hd * 16);
    const float4* p0 = (const float4*)(a0 + hd * 16);
    const float4* p1 = (const float4*)(a1 + hd * 16);
    const float4* p2 = (const float4*)(a2 + hd * 16);
    const float4* p3 = (const float4*)(a3 + hd * 16);
    float d0 = 0, d1 = 0, d2 = 0, d3 = 0;
#pragma unroll
    for (int i = 0; i < 4; i++) {
        float4 hv = hp[i];
        float4 av = p0[i];
        d0 += hv.x * av.x + hv.y * av.y + hv.z * av.z + hv.w * av.w;
        av = p1[i];
        d1 += hv.x * av.x + hv.y * av.y + hv.z * av.z + hv.w * av.w;
        av = p2[i];
        d2 += hv.x * av.x + hv.y * av.y + hv.z * av.z + hv.w * av.w;
        av = p3[i];
        d3 += hv.x * av.x + hv.y * av.y + hv.z * av.z + hv.w * av.w;
    }
    s0[idx] = d0; s1[idx] = d1; s2[idx] = d2; s3[idx] = d3;
}

// ---------------- fused edge pass: unnormalized softmax accumulation ----------------
// One warp per edge. Accumulates sum[d,h] += exp(a) and o[d,:] += exp(a)*h_src[:].
__global__ void edge_k(const float* __restrict__ hsrc,
                       const float* __restrict__ ssrc, const float* __restrict__ sdst,
                       const int* __restrict__ src, const int* __restrict__ dst, int E,
                       float* __restrict__ sumbuf, float* __restrict__ out)
{
    int e = blockIdx.x * 8 + (threadIdx.x >> 5);
    if (e >= E) return;
    int lane = threadIdx.x & 31;
    int s = __ldg(src + e), d = __ldg(dst + e);
    int hd = lane >> 2;
    float a = __ldg(ssrc + s * 8 + hd) + __ldg(sdst + d * 8 + hd);
    a = a > 0.f ? a : NEG * a;
    float ex = __expf(a);

    // message accumulation: lane handles cols [4*lane, 4*lane+4)
    float4 v = *((const float4*)(hsrc + (size_t)s * 128) + lane);
    v.x *= ex; v.y *= ex; v.z *= ex; v.w *= ex;
    float* p = out + (size_t)d * 128 + lane * 4;
    unsigned long long gp = (unsigned long long)__cvta_generic_to_global(p);
    asm volatile("red.global.add.v4.f32 [%0], {%1,%2,%3,%4};"
                 :: "l"(gp), "f"(v.x), "f"(v.y), "f"(v.z), "f"(v.w) : "memory");

    // exp-sum accumulation: lanes 0 and 16 gather 4 head-values each, vector red
    int base = lane & 16;
    float s0 = __shfl_sync(0xffffffffu, ex, base + 0);
    float s1 = __shfl_sync(0xffffffffu, ex, base + 4);
    float s2 = __shfl_sync(0xffffffffu, ex, base + 8);
    float s3 = __shfl_sync(0xffffffffu, ex, base + 12);
    if (lane == 0 || lane == 16) {
        float* sp = sumbuf + d * 8 + (lane >> 2);
        unsigned long long gs = (unsigned long long)__cvta_generic_to_global(sp);
        asm volatile("red.global.add.v4.f32 [%0], {%1,%2,%3,%4};"
                     :: "l"(gs), "f"(s0), "f"(s1), "f"(s2), "f"(s3) : "memory");
    }
}

// ---------------- semantic softmax (2 metapaths) ----------------
__global__ void sem_softmax(const float* __restrict__ q, const float* __restrict__ cs,
                            float* __restrict__ attn)
{
    __shared__ float sc[2];
    int m = threadIdx.x >> 5, lane = threadIdx.x & 31;
    float s = 0;
#pragma unroll
    for (int i = 0; i < 4; i++) s += q[lane + 32 * i] * cs[m * 128 + lane + 32 * i];
#pragma unroll
    for (int o = 16; o; o >>= 1) s += __shfl_xor_sync(0xffffffffu, s, o);
    if (lane == 0) sc[m] = s / 20000.f;
    __syncthreads();
    if (threadIdx.x == 0) {
        float mx = fmaxf(sc[0], sc[1]);
        float e0 = __expf(sc[0] - mx), e1 = __expf(sc[1] - mx);
        float inv = 1.f / (e0 + e1);
        attn[0] = e0 * inv; attn[1] = e1 * inv;
    }
}

// ---------------- normalize + relu + (semantic combine) + LayerNorm ----------------
__global__ void combine_ln(const float* __restrict__ o1, const float* __restrict__ sum1,
                           const float* __restrict__ o2, const float* __restrict__ sum2,
                           const float* __restrict__ attn,
                           const float* __restrict__ g, const float* __restrict__ b,
                           float* __restrict__ out, int N)
{
    int idx = blockIdx.x * blockDim.x + threadIdx.x;
    int n = idx >> 5, lane = idx & 31;
    if (n >= N) return;
    int head = lane >> 2;
    float sc1 = 1.f / (sum1[(size_t)n * 8 + head] + 1e-16f);
    float4 v = *((const float4*)(o1 + (size_t)n * 128) + lane);
    v.x = fmaxf(v.x, 0.f) * sc1; v.y = fmaxf(v.y, 0.f) * sc1;
    v.z = fmaxf(v.z, 0.f) * sc1; v.w = fmaxf(v.w, 0.f) * sc1;
    if (o2) {
        float a0 = attn[0], a1 = attn[1];
        float sc2 = 1.f / (sum2[(size_t)n * 8 + head] + 1e-16f);
        float4 u = *((const float4*)(o2 + (size_t)n * 128) + lane);
        u.x = fmaxf(u.x, 0.f) * sc2; u.y = fmaxf(u.y, 0.f) * sc2;
        u.z = fmaxf(u.z, 0.f) * sc2; u.w = fmaxf(u.w, 0.f) * sc2;
        v.x = a0 * v.x + a1 * u.x;
        v.y = a0 * v.y + a1 * u.y;
        v.z = a0 * v.z + a1 * u.z;
        v.w = a0 * v.w + a1 * u.w;
    }
    float s = v.x + v.y + v.z + v.w;
#pragma unroll
    for (int o = 16; o; o >>= 1) s += __shfl_xor_sync(0xffffffffu, s, o);
    float mu = s * (1.f / 128.f);
    float dx = v.x - mu, dy = v.y - mu, dz = v.z - mu, dw = v.w - mu;
    float qv = dx * dx + dy * dy + dz * dz + dw * dw;
#pragma unroll
    for (int o = 16; o; o >>= 1) qv += __shfl_xor_sync(0xffffffffu, qv, o);
    float rs = rsqrtf(qv * (1.f / 128.f) + 1e-5f);
    float4 g4 = *((const float4*)g + lane);
    float4 b4 = *((const float4*)b + lane);
    float4 r;
    r.x = dx * rs * g4.x + b4.x;
    r.y = dy * rs * g4.y + b4.y;
    r.z = dz * rs * g4.z + b4.z;
    r.w = dw * rs * g4.w + b4.w;
    *((float4*)(out + (size_t)n * 128) + lane) = r;
}

// ---------------- fusion over 2 layers ----------------
__global__ void fuse_k(const float* __restrict__ s0, const float* __restrict__ s1,
                       const float* __restrict__ g0, const float* __restrict__ g1,
                       const float* __restrict__ fw, float* __restrict__ z)
{
    int idx = blockIdx.x * blockDim.x + threadIdx.x;
    if (idx >= N_ALL * 32) return;
    int n = idx >> 5, c = idx & 31;
    float w0 = fw[0], w1 = fw[1];
    float inv = 1.f / (w0 + w1);
    float4 a, b;
    if (n < N_SNP) {
        a = ((const float4*)(s0 + (size_t)n * 128))[c];
        b = ((const float4*)(s1 + (size_t)n * 128))[c];
    } else {
        int m = n - N_SNP;
        a = ((const float4*)(g0 + (size_t)m * 128))[c];
        b = ((const float4*)(g1 + (size_t)m * 128))[c];
    }
    float4 r;
    r.x = (w0 * a.x + w1 * b.x) * inv;
    r.y = (w0 * a.y + w1 * b.y) * inv;
    r.z = (w0 * a.z + w1 * b.z) * inv;
    r.w = (w0 * a.w + w1 * b.w) * inv;
    ((float4*)(z + (size_t)n * 128))[c] = r;
}

// ---------------- final 128->2 projection ----------------
__global__ void out_k(const float* __restrict__ A, const float* __restrict__ W,
                      const float* __restrict__ b, float* __restrict__ out, int M)
{
    int idx = blockIdx.x * blockDim.x + threadIdx.x;
    int n = idx >> 5, lane = idx & 31;
    if (n >= M) return;
    const float* ar = A + (size_t)n * 128;
    float a0 = 0, a1 = 0;
#pragma unroll
    for (int i = 0; i < 4; i++) {
        float v = ar[lane + 32 * i];
        a0 += v * W[(lane + 32 * i) * 2];
        a1 += v * W[(lane + 32 * i) * 2 + 1];
    }
#pragma unroll
    for (int o = 16; o; o >>= 1) {
        a0 += __shfl_xor_sync(0xffffffffu, a0, o);
        a1 += __shfl_xor_sync(0xffffffffu, a1, o);
    }
    if (lane == 0) { out[(size_t)n * 2] = a0 + b[0]; out[(size_t)n * 2 + 1] = a1 + b[1]; }
}

static inline int cdiv(long a, int b) { return (int)((a + b - 1) / b); }

extern "C" void kernel_launch(void* const* d_in, const int* in_sizes, int n_in,
                              void* d_out, int out_size)
{
    const float* x_snp  = (const float*)d_in[0];
    const float* x_gene = (const float*)d_in[1];
    const float* Wp_snp = (const float*)d_in[2];
    const float* bp_snp = (const float*)d_in[3];
    const float* Wp_gene= (const float*)d_in[4];
    const float* bp_gene= (const float*)d_in[5];
    const float* a_src  = (const float*)d_in[6];
    const float* a_dst  = (const float*)d_in[7];
    const float* Wk     = (const float*)d_in[8];
    const float* bk     = (const float*)d_in[9];
    const float* qvp    = (const float*)d_in[10];
    const float* ln_g   = (const float*)d_in[11];
    const float* ln_b   = (const float*)d_in[12];
    const float* fw     = (const float*)d_in[13];
    const float* Wfp    = (const float*)d_in[14];
    const float* bfp    = (const float*)d_in[15];
    const float* Wo1    = (const float*)d_in[16];
    const float* bo1    = (const float*)d_in[17];
    const float* Wo2    = (const float*)d_in[18];
    const float* bo2    = (const float*)d_in[19];
    const int* sg_s = (const int*)d_in[20];
    const int* sg_d = (const int*)d_in[21];
    const int* gs_s = (const int*)d_in[22];
    const int* gs_d = (const int*)d_in[23];
    const int* gg_s = (const int*)d_in[24];
    const int* gg_d = (const int*)d_in[25];
    const int E_sg = in_sizes[20], E_gs = in_sizes[22], E_gg = in_sizes[24];

    float *hs, *hg, *ssrc_sg, *sdst_gs, *sdst_sg, *ssrc_gs, *ssrc_gg, *sdst_gg;
    float *sum_sg, *sum_gs, *sum_gg, *o_sg, *o_gs, *o_gg;
    float *out_s0, *out_s1, *out_g0, *out_g1, *sem, *attn, *buf1, *buf2;
    cudaGetSymbolAddress((void**)&hs, g_hs);
    cudaGetSymbolAddress((void**)&hg, g_hg);
    cudaGetSymbolAddress((void**)&ssrc_sg, g_ssrc_sg);
    cudaGetSymbolAddress((void**)&sdst_gs, g_sdst_gs);
    cudaGetSymbolAddress((void**)&sdst_sg, g_sdst_sg);
    cudaGetSymbolAddress((void**)&ssrc_gs, g_ssrc_gs);
    cudaGetSymbolAddress((void**)&ssrc_gg, g_ssrc_gg);
    cudaGetSymbolAddress((void**)&sdst_gg, g_sdst_gg);
    cudaGetSymbolAddress((void**)&sum_sg, g_sum_sg);
    cudaGetSymbolAddress((void**)&sum_gs, g_sum_gs);
    cudaGetSymbolAddress((void**)&sum_gg, g_sum_gg);
    cudaGetSymbolAddress((void**)&o_sg, g_o_sg);
    cudaGetSymbolAddress((void**)&o_gs, g_o_gs);
    cudaGetSymbolAddress((void**)&o_gg, g_o_gg);
    cudaGetSymbolAddress((void**)&out_s0, g_out_s0);
    cudaGetSymbolAddress((void**)&out_s1, g_out_s1);
    cudaGetSymbolAddress((void**)&out_g0, g_out_g0);
    cudaGetSymbolAddress((void**)&out_g1, g_out_g1);
    cudaGetSymbolAddress((void**)&sem, g_sem);
    cudaGetSymbolAddress((void**)&attn, g_attn);
    cudaGetSymbolAddress((void**)&buf1, g_buf1);
    cudaGetSymbolAddress((void**)&buf2, g_buf2);

    const int SMEM = (128 * 128 + 32 * 128) * 4;  // 80 KB
    cudaFuncSetAttribute(gemm128, cudaFuncAttributeMaxDynamicSharedMemorySize, SMEM);

    for (int l = 0; l < 2; ++l) {
        const float* ins = l ? out_s0 : x_snp;
        const float* ing = l ? out_g0 : x_gene;

        gemm128<<<N_SNP / 32, 256, SMEM>>>(ins, Wp_snp + l * 128 * 128, bp_snp + l * 128,
                                           hs, nullptr, nullptr, ACT_NONE);
        gemm128<<<N_GENE / 32, 256, SMEM>>>(ing, Wp_gene + l * 128 * 128, bp_gene + l * 128,
                                            hg, nullptr, nullptr, ACT_NONE);

        scores2<<<cdiv((long)N_SNP * 8, 256), 256>>>(hs, N_SNP,
            a_src + (l * 3 + 0) * 128, a_dst + (l * 3 + 1) * 128, ssrc_sg, sdst_gs);
        scores4<<<cdiv((long)N_GENE * 8, 256), 256>>>(hg, N_GENE,
            a_dst + (l * 3 + 0) * 128, a_src + (l * 3 + 1) * 128,
            a_src + (l * 3 + 2) * 128, a_dst + (l * 3 + 2) * 128,
            sdst_sg, ssrc_gs, ssrc_gg, sdst_gg);

        fill_f4<<<cdiv((long)N_GENE * 2, 256), 256>>>((float4*)sum_sg, 0.f, N_GENE * 2);
        fill_f4<<<cdiv((long)N_SNP * 2, 256), 256>>>((float4*)sum_gs, 0.f, N_SNP * 2);
        fill_f4<<<cdiv((long)N_GENE * 2, 256), 256>>>((float4*)sum_gg, 0.f, N_GENE * 2);
        fill_f4<<<cdiv((long)N_GENE * 32, 256), 256>>>((float4*)o_sg, 0.f, N_GENE * 32);
        fill_f4<<<cdiv((long)N_SNP * 32, 256), 256>>>((float4*)o_gs, 0.f, N_SNP * 32);
        fill_f4<<<cdiv((long)N_GENE * 32, 256), 256>>>((float4*)o_gg, 0.f, N_GENE * 32);

        edge_k<<<cdiv(E_sg, 8), 256>>>(hs, ssrc_sg, sdst_sg, sg_s, sg_d, E_sg, sum_sg, o_sg);
        edge_k<<<cdiv(E_gs, 8), 256>>>(hg, ssrc_gs, sdst_gs, gs_s, gs_d, E_gs, sum_gs, o_gs);
        edge_k<<<cdiv(E_gg, 8), 256>>>(hg, ssrc_gg, sdst_gg, gg_s, gg_d, E_gg, sum_gg, o_gg);

        fill_f4<<<1, 64>>>((float4*)sem, 0.f, 64);
        gemm128<<<N_GENE / 32, 256, SMEM>>>(o_sg, Wk + l * 128 * 128, bk + l * 128,
                                            nullptr, sem, sum_sg, ACT_TANHSUM);
        gemm128<<<N_GENE / 32, 256, SMEM>>>(o_gg, Wk + l * 128 * 128, bk + l * 128,
                                            nullptr, sem + 128, sum_gg, ACT_TANHSUM);
        sem_softmax<<<1, 64>>>(qvp + l * 128, sem, attn);

        float* og = l ? out_g1 : out_g0;
        float* os = l ? out_s1 : out_s0;
        combine_ln<<<cdiv((long)N_GENE * 32, 256), 256>>>(o_sg, sum_sg, o_gg, sum_gg, attn,
            ln_g + l * 128, ln_b + l * 128, og, N_GENE);
        combine_ln<<<cdiv((long)N_SNP * 32, 256), 256>>>(o_gs, sum_gs, nullptr, nullptr, nullptr,
            ln_g + l * 128, ln_b + l * 128, os, N_SNP);
    }

    fuse_k<<<cdiv((long)N_ALL * 32, 256), 256>>>(out_s0, out_s1, out_g0, out_g1, fw, buf1);
    gemm128<<<N_ALL / 32, 256, SMEM>>>(buf1, Wfp, bfp, buf2, nullptr, nullptr, ACT_RELU);
    gemm128<<<N_ALL / 32, 256, SMEM>>>(buf2, Wo1, bo1, buf1, nullptr, nullptr, ACT_RELU);
    out_k<<<cdiv((long)N_ALL * 32, 256), 256>>>(buf1, Wo2, bo2, (float*)d_out, N_ALL);
}

// round 4
// speedup vs baseline: 1.4725x; 1.2812x over previous
#include <cuda_runtime.h>
#include <cuda_bf16.h>
#include <cstdint>

#define N_SNP  100000
#define N_GENE 20000
#define N_ALL  120000
#define HID    128
#define NEG    0.2f

#define ACT_NONE    0
#define ACT_RELU    1
#define ACT_TANHSUM 2

// weight image geometry: [n][k] row-major bf16, padded row stride 272B,
// hi image at 0, lo image at 34816; total 69632 bytes per weight.
#define WROW   272
#define WLO    34816
#define WIMGSZ 69632

// ---------------- device scratch (static, allocation-free) ----------------
__device__ float    g_hs[N_SNP * HID];
__device__ float    g_hg[N_GENE * HID];
__device__ float    g_ssrc_sg[N_SNP * 8];
__device__ float    g_sdst_gs[N_SNP * 8];
__device__ float    g_sdst_sg[N_GENE * 8];
__device__ float    g_ssrc_gs[N_GENE * 8];
__device__ float    g_ssrc_gg[N_GENE * 8];
__device__ float    g_sdst_gg[N_GENE * 8];
__device__ float    g_sum_sg[N_GENE * 8];
__device__ float    g_sum_gs[N_SNP * 8];
__device__ float    g_sum_gg[N_GENE * 8];
__device__ float    g_o_sg[N_GENE * HID];
__device__ float    g_o_gs[N_SNP * HID];
__device__ float    g_o_gg[N_GENE * HID];
__device__ float    g_out_s0[N_SNP * HID];
__device__ float    g_out_s1[N_SNP * HID];
__device__ float    g_out_g0[N_GENE * HID];
__device__ float    g_out_g1[N_GENE * HID];
__device__ float    g_sem[2 * HID];
__device__ float    g_attn[2];
__device__ float    g_buf1[N_ALL * HID];
__device__ float    g_buf2[N_ALL * HID];
__device__ __align__(16) unsigned char g_wimg[8 * WIMGSZ];

__device__ __forceinline__ uint32_t pack_bf(float x, float y) {
    __nv_bfloat162 t = __floats2bfloat162_rn(x, y);
    return *(uint32_t*)&t;
}
__device__ __forceinline__ void mma_bf16(float4& c, uint32_t a0, uint32_t a1,
                                         uint32_t a2, uint32_t a3,
                                         uint32_t b0, uint32_t b1) {
    asm volatile("mma.sync.aligned.m16n8k16.row.col.f32.bf16.bf16.f32 "
                 "{%0,%1,%2,%3}, {%4,%5,%6,%7}, {%8,%9}, {%0,%1,%2,%3};"
                 : "+f"(c.x), "+f"(c.y), "+f"(c.z), "+f"(c.w)
                 : "r"(a0), "r"(a1), "r"(a2), "r"(a3), "r"(b0), "r"(b1));
}

// ---------------- weight prep: fp32 W[128,128] -> padded bf16 hi/lo images ----------
__global__ void wprep(const float* __restrict__ W, unsigned char* __restrict__ img) {
    int i = blockIdx.x * 256 + threadIdx.x;   // 0..16383
    int n = i >> 7, k = i & 127;              // Bimg[n][k] = W[k][n]
    float w = W[k * 128 + n];
    __nv_bfloat16 h = __float2bfloat16(w);
    __nv_bfloat16 l = __float2bfloat16(w - __bfloat162float(h));
    *(uint16_t*)(img + n * WROW + k * 2) = __bfloat16_as_ushort(h);
    *(uint16_t*)(img + WLO + n * WROW + k * 2) = __bfloat16_as_ushort(l);
}

// ---------------- tensor-core GEMM (mma.sync bf16 split) ----------------
// C[M,128] = act(A[M,128] @ W + b). 256 threads, 128 rows/CTA, warp = 16 rows.
#define TG_SMEM_TOTAL (WIMGSZ + 512)

__global__ void __launch_bounds__(256) tgemm(
    const float* __restrict__ A, const unsigned char* __restrict__ Bimg,
    const float* __restrict__ bias, float* __restrict__ C,
    float* __restrict__ colsum, const float* __restrict__ asum,
    int M, int act)
{
    extern __shared__ unsigned char smem[];
    float* scs = (float*)(smem + WIMGSZ);
    const int tid = threadIdx.x, wid = tid >> 5, lane = tid & 31;
    const int g = lane >> 2, tig = lane & 3;

    // copy B images (69632B) linearly
    {
        const uint4* src = (const uint4*)Bimg;
        uint4* dst = (uint4*)smem;
#pragma unroll
        for (int i = 0; i < 17; i++) {
            int idx = tid + 256 * i;
            if (idx < WIMGSZ / 16) dst[idx] = src[idx];
        }
    }
    if (act == ACT_TANHSUM && tid < 128) scs[tid] = 0.f;
    __syncthreads();

    const int rowA = blockIdx.x * 128 + wid * 16 + g;
    const int rowB = rowA + 8;
    const bool vA = rowA < M, vB = rowB < M;

    float4 acc[16];
#pragma unroll
    for (int nt = 0; nt < 16; nt++) acc[nt] = make_float4(0.f, 0.f, 0.f, 0.f);

    const float* ArA = A + (size_t)rowA * 128;
    const float* ArB = A + (size_t)rowB * 128;

#pragma unroll
    for (int ks = 0; ks < 8; ks++) {
        const int k0 = ks * 16;
        float2 p00 = make_float2(0.f, 0.f), p01 = p00, p10 = p00, p11 = p00;
        if (vA) {
            p00 = *(const float2*)(ArA + k0 + 2 * tig);
            p01 = *(const float2*)(ArA + k0 + 2 * tig + 8);
        }
        if (vB) {
            p10 = *(const float2*)(ArB + k0 + 2 * tig);
            p11 = *(const float2*)(ArB + k0 + 2 * tig + 8);
        }
        if (act == ACT_TANHSUM) {
            float scA = vA ? 1.f / (asum[(size_t)rowA * 8 + ks] + 1e-16f) : 0.f;
            float scB = vB ? 1.f / (asum[(size_t)rowB * 8 + ks] + 1e-16f) : 0.f;
            p00.x = fmaxf(p00.x, 0.f) * scA; p00.y = fmaxf(p00.y, 0.f) * scA;
            p01.x = fmaxf(p01.x, 0.f) * scA; p01.y = fmaxf(p01.y, 0.f) * scA;
            p10.x = fmaxf(p10.x, 0.f) * scB; p10.y = fmaxf(p10.y, 0.f) * scB;
            p11.x = fmaxf(p11.x, 0.f) * scB; p11.y = fmaxf(p11.y, 0.f) * scB;
        }
        // hi fragments
        uint32_t ah0 = pack_bf(p00.x, p00.y), ah1 = pack_bf(p10.x, p10.y);
        uint32_t ah2 = pack_bf(p01.x, p01.y), ah3 = pack_bf(p11.x, p11.y);
        // lo fragments
        __nv_bfloat162 h00 = *(__nv_bfloat162*)&ah0, h10 = *(__nv_bfloat162*)&ah1;
        __nv_bfloat162 h01 = *(__nv_bfloat162*)&ah2, h11 = *(__nv_bfloat162*)&ah3;
        uint32_t al0 = pack_bf(p00.x - __bfloat162float(h00.x), p00.y - __bfloat162float(h00.y));
        uint32_t al1 = pack_bf(p10.x - __bfloat162float(h10.x), p10.y - __bfloat162float(h10.y));
        uint32_t al2 = pack_bf(p01.x - __bfloat162float(h01.x), p01.y - __bfloat162float(h01.y));
        uint32_t al3 = pack_bf(p11.x - __bfloat162float(h11.x), p11.y - __bfloat162float(h11.y));

        const unsigned char* bh = smem + (size_t)g * WROW + (k0 + 2 * tig) * 2;
#pragma unroll
        for (int nt = 0; nt < 16; nt++) {
            uint32_t bh0 = *(const uint32_t*)(bh + nt * 8 * WROW);
            uint32_t bh1 = *(const uint32_t*)(bh + nt * 8 * WROW + 16);
            mma_bf16(acc[nt], ah0, ah1, ah2, ah3, bh0, bh1);
            mma_bf16(acc[nt], al0, al1, al2, al3, bh0, bh1);
            uint32_t bl0 = *(const uint32_t*)(bh + WLO + nt * 8 * WROW);
            uint32_t bl1 = *(const uint32_t*)(bh + WLO + nt * 8 * WROW + 16);
            mma_bf16(acc[nt], ah0, ah1, ah2, ah3, bl0, bl1);
        }
    }

    if (act == ACT_TANHSUM) {
#pragma unroll
        for (int nt = 0; nt < 16; nt++) {
            int col = nt * 8 + 2 * tig;
            float b0 = bias[col], b1 = bias[col + 1];
            float s0 = 0.f, s1 = 0.f;
            if (vA) { s0 += tanhf(acc[nt].x + b0); s1 += tanhf(acc[nt].y + b1); }
            if (vB) { s0 += tanhf(acc[nt].z + b0); s1 += tanhf(acc[nt].w + b1); }
            atomicAdd(scs + col, s0);
            atomicAdd(scs + col + 1, s1);
        }
        __syncthreads();
        if (tid < 128) atomicAdd(colsum + tid, scs[tid]);
    } else {
#pragma unroll
        for (int nt = 0; nt < 16; nt++) {
            int col = nt * 8 + 2 * tig;
            float b0 = bias[col], b1 = bias[col + 1];
            float2 oA = make_float2(acc[nt].x + b0, acc[nt].y + b1);
            float2 oB = make_float2(acc[nt].z + b0, acc[nt].w + b1);
            if (act == ACT_RELU) {
                oA.x = fmaxf(oA.x, 0.f); oA.y = fmaxf(oA.y, 0.f);
                oB.x = fmaxf(oB.x, 0.f); oB.y = fmaxf(oB.y, 0.f);
            }
            if (vA) *(float2*)(C + (size_t)rowA * 128 + col) = oA;
            if (vB) *(float2*)(C + (size_t)rowB * 128 + col) = oB;
        }
    }
}

// ---------------- fills ----------------
__global__ void fill_f4(float4* p, float v, int n4) {
    int i = blockIdx.x * blockDim.x + threadIdx.x;
    if (i < n4) p[i] = make_float4(v, v, v, v);
}

// ---------------- per-node attention score dots ----------------
__global__ void scores2(const float* __restrict__ h, int N,
                        const float* __restrict__ a0, const float* __restrict__ a1,
                        float* __restrict__ s0, float* __restrict__ s1)
{
    int idx = blockIdx.x * blockDim.x + threadIdx.x;
    if (idx >= N * 8) return;
    int n = idx >> 3, hd = idx & 7;
    const float4* hp = (const float4*)(h + (size_t)n * 128 + hd * 16);
    const float4* p0 = (const float4*)(a0 + hd * 16);
    const float4* p1 = (const float4*)(a1 + hd * 16);
    float d0 = 0, d1 = 0;
#pragma unroll
    for (int i = 0; i < 4; i++) {
        float4 hv = hp[i];
        float4 av = p0[i];
        d0 += hv.x * av.x + hv.y * av.y + hv.z * av.z + hv.w * av.w;
        av = p1[i];
        d1 += hv.x * av.x + hv.y * av.y + hv.z * av.z + hv.w * av.w;
    }
    s0[idx] = d0; s1[idx] = d1;
}

__global__ void scores4(const float* __restrict__ h, int N,
                        const float* __restrict__ a0, const float* __restrict__ a1,
                        const float* __restrict__ a2, const float* __restrict__ a3,
                        float* __restrict__ s0, float* __restrict__ s1,
                        float* __restrict__ s2, float* __restrict__ s3)
{
    int idx = blockIdx.x * blockDim.x + threadIdx.x;
    if (idx >= N * 8) return;
    int n = idx >> 3, hd = idx & 7;
    const float4* hp = (const float4*)(h + (size_t)n * 128 + hd * 16);
    const float4* p0 = (const float4*)(a0 + hd * 16);
    const float4* p1 = (const float4*)(a1 + hd * 16);
    const float4* p2 = (const float4*)(a2 + hd * 16);
    const float4* p3 = (const float4*)(a3 + hd * 16);
    float d0 = 0, d1 = 0, d2 = 0, d3 = 0;
#pragma unroll
    for (int i = 0; i < 4; i++) {
        float4 hv = hp[i];
        float4 av = p0[i];
        d0 += hv.x * av.x + hv.y * av.y + hv.z * av.z + hv.w * av.w;
        av = p1[i];
        d1 += hv.x * av.x + hv.y * av.y + hv.z * av.z + hv.w * av.w;
        av = p2[i];
        d2 += hv.x * av.x + hv.y * av.y + hv.z * av.z + hv.w * av.w;
        av = p3[i];
        d3 += hv.x * av.x + hv.y * av.y + hv.z * av.z + hv.w * av.w;
    }
    s0[idx] = d0; s1[idx] = d1; s2[idx] = d2; s3[idx] = d3;
}

// ---------------- fused edge pass: unnormalized softmax accumulation ----------------
__global__ void edge_k(const float* __restrict__ hsrc,
                       const float* __restrict__ ssrc, const float* __restrict__ sdst,
                       const int* __restrict__ src, const int* __restrict__ dst, int E,
                       float* __restrict__ sumbuf, float* __restrict__ out)
{
    int e = blockIdx.x * 8 + (threadIdx.x >> 5);
    if (e >= E) return;
    int lane = threadIdx.x & 31;
    int s = __ldg(src + e), d = __ldg(dst + e);
    int hd = lane >> 2;
    float a = __ldg(ssrc + s * 8 + hd) + __ldg(sdst + d * 8 + hd);
    a = a > 0.f ? a : NEG * a;
    float ex = __expf(a);

    float4 v = *((const float4*)(hsrc + (size_t)s * 128) + lane);
    v.x *= ex; v.y *= ex; v.z *= ex; v.w *= ex;
    float* p = out + (size_t)d * 128 + lane * 4;
    unsigned long long gp = (unsigned long long)__cvta_generic_to_global(p);
    asm volatile("red.global.add.v4.f32 [%0], {%1,%2,%3,%4};"
                 :: "l"(gp), "f"(v.x), "f"(v.y), "f"(v.z), "f"(v.w) : "memory");

    int base = lane & 16;
    float s0 = __shfl_sync(0xffffffffu, ex, base + 0);
    float s1 = __shfl_sync(0xffffffffu, ex, base + 4);
    float s2 = __shfl_sync(0xffffffffu, ex, base + 8);
    float s3 = __shfl_sync(0xffffffffu, ex, base + 12);
    if (lane == 0 || lane == 16) {
        float* sp = sumbuf + d * 8 + (lane >> 2);
        unsigned long long gs = (unsigned long long)__cvta_generic_to_global(sp);
        asm volatile("red.global.add.v4.f32 [%0], {%1,%2,%3,%4};"
                     :: "l"(gs), "f"(s0), "f"(s1), "f"(s2), "f"(s3) : "memory");
    }
}

// ---------------- semantic softmax (2 metapaths) ----------------
__global__ void sem_softmax(const float* __restrict__ q, const float* __restrict__ cs,
                            float* __restrict__ attn)
{
    __shared__ float sc[2];
    int m = threadIdx.x >> 5, lane = threadIdx.x & 31;
    float s = 0;
#pragma unroll
    for (int i = 0; i < 4; i++) s += q[lane + 32 * i] * cs[m * 128 + lane + 32 * i];
#pragma unroll
    for (int o = 16; o; o >>= 1) s += __shfl_xor_sync(0xffffffffu, s, o);
    if (lane == 0) sc[m] = s / 20000.f;
    __syncthreads();
    if (threadIdx.x == 0) {
        float mx = fmaxf(sc[0], sc[1]);
        float e0 = __expf(sc[0] - mx), e1 = __expf(sc[1] - mx);
        float inv = 1.f / (e0 + e1);
        attn[0] = e0 * inv; attn[1] = e1 * inv;
    }
}

// ---------------- normalize + relu + (semantic combine) + LayerNorm ----------------
__global__ void combine_ln(const float* __restrict__ o1, const float* __restrict__ sum1,
                           const float* __restrict__ o2, const float* __restrict__ sum2,
                           const float* __restrict__ attn,
                           const float* __restrict__ g, const float* __restrict__ b,
                           float* __restrict__ out, int N)
{
    int idx = blockIdx.x * blockDim.x + threadIdx.x;
    int n = idx >> 5, lane = idx & 31;
    if (n >= N) return;
    int head = lane >> 2;
    float sc1 = 1.f / (sum1[(size_t)n * 8 + head] + 1e-16f);
    float4 v = *((const float4*)(o1 + (size_t)n * 128) + lane);
    v.x = fmaxf(v.x, 0.f) * sc1; v.y = fmaxf(v.y, 0.f) * sc1;
    v.z = fmaxf(v.z, 0.f) * sc1; v.w = fmaxf(v.w, 0.f) * sc1;
    if (o2) {
        float a0 = attn[0], a1 = attn[1];
        float sc2 = 1.f / (sum2[(size_t)n * 8 + head] + 1e-16f);
        float4 u = *((const float4*)(o2 + (size_t)n * 128) + lane);
        u.x = fmaxf(u.x, 0.f) * sc2; u.y = fmaxf(u.y, 0.f) * sc2;
        u.z = fmaxf(u.z, 0.f) * sc2; u.w = fmaxf(u.w, 0.f) * sc2;
        v.x = a0 * v.x + a1 * u.x;
        v.y = a0 * v.y + a1 * u.y;
        v.z = a0 * v.z + a1 * u.z;
        v.w = a0 * v.w + a1 * u.w;
    }
    float s = v.x + v.y + v.z + v.w;
#pragma unroll
    for (int o = 16; o; o >>= 1) s += __shfl_xor_sync(0xffffffffu, s, o);
    float mu = s * (1.f / 128.f);
    float dx = v.x - mu, dy = v.y - mu, dz = v.z - mu, dw = v.w - mu;
    float qv = dx * dx + dy * dy + dz * dz + dw * dw;
#pragma unroll
    for (int o = 16; o; o >>= 1) qv += __shfl_xor_sync(0xffffffffu, qv, o);
    float rs = rsqrtf(qv * (1.f / 128.f) + 1e-5f);
    float4 g4 = *((const float4*)g + lane);
    float4 b4 = *((const float4*)b + lane);
    float4 r;
    r.x = dx * rs * g4.x + b4.x;
    r.y = dy * rs * g4.y + b4.y;
    r.z = dz * rs * g4.z + b4.z;
    r.w = dw * rs * g4.w + b4.w;
    *((float4*)(out + (size_t)n * 128) + lane) = r;
}

// ---------------- fusion over 2 layers ----------------
__global__ void fuse_k(const float* __restrict__ s0, const float* __restrict__ s1,
                       const float* __restrict__ g0, const float* __restrict__ g1,
                       const float* __restrict__ fw, float* __restrict__ z)
{
    int idx = blockIdx.x * blockDim.x + threadIdx.x;
    if (idx >= N_ALL * 32) return;
    int n = idx >> 5, c = idx & 31;
    float w0 = fw[0], w1 = fw[1];
    float inv = 1.f / (w0 + w1);
    float4 a, b;
    if (n < N_SNP) {
        a = ((const float4*)(s0 + (size_t)n * 128))[c];
        b = ((const float4*)(s1 + (size_t)n * 128))[c];
    } else {
        int m = n - N_SNP;
        a = ((const float4*)(g0 + (size_t)m * 128))[c];
        b = ((const float4*)(g1 + (size_t)m * 128))[c];
    }
    float4 r;
    r.x = (w0 * a.x + w1 * b.x) * inv;
    r.y = (w0 * a.y + w1 * b.y) * inv;
    r.z = (w0 * a.z + w1 * b.z) * inv;
    r.w = (w0 * a.w + w1 * b.w) * inv;
    ((float4*)(z + (size_t)n * 128))[c] = r;
}

// ---------------- final 128->2 projection ----------------
__global__ void out_k(const float* __restrict__ A, const float* __restrict__ W,
                      const float* __restrict__ b, float* __restrict__ out, int M)
{
    int idx = blockIdx.x * blockDim.x + threadIdx.x;
    int n = idx >> 5, lane = idx & 31;
    if (n >= M) return;
    const float* ar = A + (size_t)n * 128;
    float a0 = 0, a1 = 0;
#pragma unroll
    for (int i = 0; i < 4; i++) {
        float v = ar[lane + 32 * i];
        a0 += v * W[(lane + 32 * i) * 2];
        a1 += v * W[(lane + 32 * i) * 2 + 1];
    }
#pragma unroll
    for (int o = 16; o; o >>= 1) {
        a0 += __shfl_xor_sync(0xffffffffu, a0, o);
        a1 += __shfl_xor_sync(0xffffffffu, a1, o);
    }
    if (lane == 0) { out[(size_t)n * 2] = a0 + b[0]; out[(size_t)n * 2 + 1] = a1 + b[1]; }
}

static inline int cdiv(long a, int b) { return (int)((a + b - 1) / b); }

extern "C" void kernel_launch(void* const* d_in, const int* in_sizes, int n_in,
                              void* d_out, int out_size)
{
    const float* x_snp  = (const float*)d_in[0];
    const float* x_gene = (const float*)d_in[1];
    const float* Wp_snp = (const float*)d_in[2];
    const float* bp_snp = (const float*)d_in[3];
    const float* Wp_gene= (const float*)d_in[4];
    const float* bp_gene= (const float*)d_in[5];
    const float* a_src  = (const float*)d_in[6];
    const float* a_dst  = (const float*)d_in[7];
    const float* Wk     = (const float*)d_in[8];
    const float* bk     = (const float*)d_in[9];
    const float* qvp    = (const float*)d_in[10];
    const float* ln_g   = (const float*)d_in[11];
    const float* ln_b   = (const float*)d_in[12];
    const float* fw     = (const float*)d_in[13];
    const float* Wfp    = (const float*)d_in[14];
    const float* bfp    = (const float*)d_in[15];
    const float* Wo1    = (const float*)d_in[16];
    const float* bo1    = (const float*)d_in[17];
    const float* Wo2    = (const float*)d_in[18];
    const float* bo2    = (const float*)d_in[19];
    const int* sg_s = (const int*)d_in[20];
    const int* sg_d = (const int*)d_in[21];
    const int* gs_s = (const int*)d_in[22];
    const int* gs_d = (const int*)d_in[23];
    const int* gg_s = (const int*)d_in[24];
    const int* gg_d = (const int*)d_in[25];
    const int E_sg = in_sizes[20], E_gs = in_sizes[22], E_gg = in_sizes[24];

    float *hs, *hg, *ssrc_sg, *sdst_gs, *sdst_sg, *ssrc_gs, *ssrc_gg, *sdst_gg;
    float *sum_sg, *sum_gs, *sum_gg, *o_sg, *o_gs, *o_gg;
    float *out_s0, *out_s1, *out_g0, *out_g1, *sem, *attn, *buf1, *buf2;
    unsigned char* wimg;
    cudaGetSymbolAddress((void**)&hs, g_hs);
    cudaGetSymbolAddress((void**)&hg, g_hg);
    cudaGetSymbolAddress((void**)&ssrc_sg, g_ssrc_sg);
    cudaGetSymbolAddress((void**)&sdst_gs, g_sdst_gs);
    cudaGetSymbolAddress((void**)&sdst_sg, g_sdst_sg);
    cudaGetSymbolAddress((void**)&ssrc_gs, g_ssrc_gs);
    cudaGetSymbolAddress((void**)&ssrc_gg, g_ssrc_gg);
    cudaGetSymbolAddress((void**)&sdst_gg, g_sdst_gg);
    cudaGetSymbolAddress((void**)&sum_sg, g_sum_sg);
    cudaGetSymbolAddress((void**)&sum_gs, g_sum_gs);
    cudaGetSymbolAddress((void**)&sum_gg, g_sum_gg);
    cudaGetSymbolAddress((void**)&o_sg, g_o_sg);
    cudaGetSymbolAddress((void**)&o_gs, g_o_gs);
    cudaGetSymbolAddress((void**)&o_gg, g_o_gg);
    cudaGetSymbolAddress((void**)&out_s0, g_out_s0);
    cudaGetSymbolAddress((void**)&out_s1, g_out_s1);
    cudaGetSymbolAddress((void**)&out_g0, g_out_g0);
    cudaGetSymbolAddress((void**)&out_g1, g_out_g1);
    cudaGetSymbolAddress((void**)&sem, g_sem);
    cudaGetSymbolAddress((void**)&attn, g_attn);
    cudaGetSymbolAddress((void**)&buf1, g_buf1);
    cudaGetSymbolAddress((void**)&buf2, g_buf2);
    cudaGetSymbolAddress((void**)&wimg, g_wimg);

    cudaFuncSetAttribute(tgemm, cudaFuncAttributeMaxDynamicSharedMemorySize, TG_SMEM_TOTAL);

    // weight images: 0,1: Wp_snp l0/l1; 2,3: Wp_gene; 4,5: Wk; 6: Wfp; 7: Wo1
    wprep<<<64, 256>>>(Wp_snp,          wimg + 0 * WIMGSZ);
    wprep<<<64, 256>>>(Wp_snp + 16384,  wimg + 1 * WIMGSZ);
    wprep<<<64, 256>>>(Wp_gene,         wimg + 2 * WIMGSZ);
    wprep<<<64, 256>>>(Wp_gene + 16384, wimg + 3 * WIMGSZ);
    wprep<<<64, 256>>>(Wk,              wimg + 4 * WIMGSZ);
    wprep<<<64, 256>>>(Wk + 16384,      wimg + 5 * WIMGSZ);
    wprep<<<64, 256>>>(Wfp,             wimg + 6 * WIMGSZ);
    wprep<<<64, 256>>>(Wo1,             wimg + 7 * WIMGSZ);

    const int TS = cdiv(N_SNP, 128), TG = cdiv(N_GENE, 128), TA = cdiv(N_ALL, 128);

    for (int l = 0; l < 2; ++l) {
        const float* ins = l ? out_s0 : x_snp;
        const float* ing = l ? out_g0 : x_gene;

        tgemm<<<TS, 256, TG_SMEM_TOTAL>>>(ins, wimg + (0 + l) * WIMGSZ, bp_snp + l * 128,
                                          hs, nullptr, nullptr, N_SNP, ACT_NONE);
        tgemm<<<TG, 256, TG_SMEM_TOTAL>>>(ing, wimg + (2 + l) * WIMGSZ, bp_gene + l * 128,
                                          hg, nullptr, nullptr, N_GENE, ACT_NONE);

        scores2<<<cdiv((long)N_SNP * 8, 256), 256>>>(hs, N_SNP,
            a_src + (l * 3 + 0) * 128, a_dst + (l * 3 + 1) * 128, ssrc_sg, sdst_gs);
        scores4<<<cdiv((long)N_GENE * 8, 256), 256>>>(hg, N_GENE,
            a_dst + (l * 3 + 0) * 128, a_src + (l * 3 + 1) * 128,
            a_src + (l * 3 + 2) * 128, a_dst + (l * 3 + 2) * 128,
            sdst_sg, ssrc_gs, ssrc_gg, sdst_gg);

        fill_f4<<<cdiv((long)N_GENE * 2, 256), 256>>>((float4*)sum_sg, 0.f, N_GENE * 2);
        fill_f4<<<cdiv((long)N_SNP * 2, 256), 256>>>((float4*)sum_gs, 0.f, N_SNP * 2);
        fill_f4<<<cdiv((long)N_GENE * 2, 256), 256>>>((float4*)sum_gg, 0.f, N_GENE * 2);
        fill_f4<<<cdiv((long)N_GENE * 32, 256), 256>>>((float4*)o_sg, 0.f, N_GENE * 32);
        fill_f4<<<cdiv((long)N_SNP * 32, 256), 256>>>((float4*)o_gs, 0.f, N_SNP * 32);
        fill_f4<<<cdiv((long)N_GENE * 32, 256), 256>>>((float4*)o_gg, 0.f, N_GENE * 32);

        edge_k<<<cdiv(E_sg, 8), 256>>>(hs, ssrc_sg, sdst_sg, sg_s, sg_d, E_sg, sum_sg, o_sg);
        edge_k<<<cdiv(E_gs, 8), 256>>>(hg, ssrc_gs, sdst_gs, gs_s, gs_d, E_gs, sum_gs, o_gs);
        edge_k<<<cdiv(E_gg, 8), 256>>>(hg, ssrc_gg, sdst_gg, gg_s, gg_d, E_gg, sum_gg, o_gg);

        fill_f4<<<1, 64>>>((float4*)sem, 0.f, 64);
        tgemm<<<TG, 256, TG_SMEM_TOTAL>>>(o_sg, wimg + (4 + l) * WIMGSZ, bk + l * 128,
                                          nullptr, sem, sum_sg, N_GENE, ACT_TANHSUM);
        tgemm<<<TG, 256, TG_SMEM_TOTAL>>>(o_gg, wimg + (4 + l) * WIMGSZ, bk + l * 128,
                                          nullptr, sem + 128, sum_gg, N_GENE, ACT_TANHSUM);
        sem_softmax<<<1, 64>>>(qvp + l * 128, sem, attn);

        float* og = l ? out_g1 : out_g0;
        float* os = l ? out_s1 : out_s0;
        combine_ln<<<cdiv((long)N_GENE * 32, 256), 256>>>(o_sg, sum_sg, o_gg, sum_gg, attn,
            ln_g + l * 128, ln_b + l * 128, og, N_GENE);
        combine_ln<<<cdiv((long)N_SNP * 32, 256), 256>>>(o_gs, sum_gs, nullptr, nullptr, nullptr,
            ln_g + l * 128, ln_b + l * 128, os, N_SNP);
    }

    fuse_k<<<cdiv((long)N_ALL * 32, 256), 256>>>(out_s0, out_s1, out_g0, out_g1, fw, buf1);
    tgemm<<<TA, 256, TG_SMEM_TOTAL>>>(buf1, wimg + 6 * WIMGSZ, bfp, buf2, nullptr, nullptr, N_ALL, ACT_RELU);
    tgemm<<<TA, 256, TG_SMEM_TOTAL>>>(buf2, wimg + 7 * WIMGSZ, bo1, buf1, nullptr, nullptr, N_ALL, ACT_RELU);
    out_k<<<cdiv((long)N_ALL * 32, 256), 256>>>(buf1, Wo2, bo2, (float*)d_out, N_ALL);
}

// round 5
// speedup vs baseline: 1.8556x; 1.2602x over previous
#include <cuda_runtime.h>
#include <cuda_bf16.h>
#include <cstdint>

#define N_SNP  100000
#define N_GENE 20000
#define N_ALL  120000
#define HID    128
#define NEG    0.2f

#define ACT_NONE    0
#define ACT_RELU    1
#define ACT_TANHSUM 2

#define E_SG_MAX 500000
#define E_GS_MAX 500000
#define E_GG_MAX 150000

// weight image geometry: [n][k] row-major bf16, padded row stride 272B,
// hi image at 0, lo image at 34816; total 69632 bytes per weight.
#define WROW   272
#define WLO    34816
#define WIMGSZ 69632

// ---------------- device scratch (static, allocation-free) ----------------
__device__ float    g_hs[N_SNP * HID];
__device__ float    g_hg[N_GENE * HID];
__device__ float    g_ssrc_sg[N_SNP * 8];
__device__ float    g_sdst_gs[N_SNP * 8];
__device__ float    g_sdst_sg[N_GENE * 8];
__device__ float    g_ssrc_gs[N_GENE * 8];
__device__ float    g_ssrc_gg[N_GENE * 8];
__device__ float    g_sdst_gg[N_GENE * 8];
__device__ float    g_o_sg[N_GENE * HID];
__device__ float    g_o_gs[N_SNP * HID];
__device__ float    g_o_gg[N_GENE * HID];
__device__ float    g_out_s0[N_SNP * HID];
__device__ float    g_out_s1[N_SNP * HID];
__device__ float    g_out_g0[N_GENE * HID];
__device__ float    g_out_g1[N_GENE * HID];
__device__ float    g_sem[2 * HID];
__device__ float    g_attn[2];
__device__ float    g_buf1[N_ALL * HID];
__device__ float    g_buf2[N_ALL * HID];
__device__ __align__(16) unsigned char g_wimg[8 * WIMGSZ];
// CSR build scratch
__device__ int g_rp_sg[N_GENE + 1];
__device__ int g_rp_gs[N_SNP + 1];
__device__ int g_rp_gg[N_GENE + 1];
__device__ int g_deg[N_SNP];
__device__ int g_cur[N_SNP];
__device__ int g_bsum[128];
__device__ int g_ss_sg[E_SG_MAX];
__device__ int g_ss_gs[E_GS_MAX];
__device__ int g_ss_gg[E_GG_MAX];

__device__ __forceinline__ uint32_t pack_bf(float x, float y) {
    __nv_bfloat162 t = __floats2bfloat162_rn(x, y);
    return *(uint32_t*)&t;
}
__device__ __forceinline__ void mma_bf16(float4& c, uint32_t a0, uint32_t a1,
                                         uint32_t a2, uint32_t a3,
                                         uint32_t b0, uint32_t b1) {
    asm volatile("mma.sync.aligned.m16n8k16.row.col.f32.bf16.bf16.f32 "
                 "{%0,%1,%2,%3}, {%4,%5,%6,%7}, {%8,%9}, {%0,%1,%2,%3};"
                 : "+f"(c.x), "+f"(c.y), "+f"(c.z), "+f"(c.w)
                 : "r"(a0), "r"(a1), "r"(a2), "r"(a3), "r"(b0), "r"(b1));
}

// ---------------- CSR build ----------------
__global__ void zero_i(int* p, int n) {
    int i = blockIdx.x * blockDim.x + threadIdx.x;
    if (i < n) p[i] = 0;
}
__global__ void hist_k(const int* __restrict__ dst, int E, int* __restrict__ deg) {
    int i = blockIdx.x * blockDim.x + threadIdx.x;
    if (i < E) atomicAdd(deg + dst[i], 1);
}
__global__ void bsum_k(const int* __restrict__ deg, int n, int* __restrict__ bsum) {
    __shared__ int sw[32];
    int i = blockIdx.x * 1024 + threadIdx.x;
    int v = (i < n) ? deg[i] : 0;
#pragma unroll
    for (int o = 16; o; o >>= 1) v += __shfl_xor_sync(0xffffffffu, v, o);
    if ((threadIdx.x & 31) == 0) sw[threadIdx.x >> 5] = v;
    __syncthreads();
    if (threadIdx.x < 32) {
        int t = sw[threadIdx.x];
#pragma unroll
        for (int o = 16; o; o >>= 1) t += __shfl_xor_sync(0xffffffffu, t, o);
        if (threadIdx.x == 0) bsum[blockIdx.x] = t;
    }
}
__global__ void bscan_k(int* bsum, int nb) {
    if (threadIdx.x == 0) {
        int c = 0;
        for (int i = 0; i < nb; i++) { int v = bsum[i]; bsum[i] = c; c += v; }
    }
}
__global__ void scan_k(const int* __restrict__ deg, const int* __restrict__ bsum,
                       int n, int* __restrict__ rp) {
    __shared__ int sm[1024];
    int tid = threadIdx.x;
    int i = blockIdx.x * 1024 + tid;
    int v = (i < n) ? deg[i] : 0;
    sm[tid] = v;
    __syncthreads();
#pragma unroll
    for (int off = 1; off < 1024; off <<= 1) {
        int t = (tid >= off) ? sm[tid - off] : 0;
        __syncthreads();
        sm[tid] += t;
        __syncthreads();
    }
    int incl = sm[tid];
    int base = bsum[blockIdx.x];
    if (i < n) rp[i] = base + incl - v;
    if (i == n - 1) rp[n] = base + incl;
}
__global__ void scatter_k(const int* __restrict__ src, const int* __restrict__ dst, int E,
                          const int* __restrict__ rp, int* __restrict__ cur,
                          int* __restrict__ out) {
    int e = blockIdx.x * blockDim.x + threadIdx.x;
    if (e >= E) return;
    int d = dst[e];
    int pos = rp[d] + atomicAdd(cur + d, 1);
    out[pos] = src[e];
}

// ---------------- weight prep ----------------
__global__ void wprep(const float* __restrict__ W, unsigned char* __restrict__ img) {
    int i = blockIdx.x * 256 + threadIdx.x;   // 0..16383
    int n = i >> 7, k = i & 127;              // Bimg[n][k] = W[k][n]
    float w = W[k * 128 + n];
    __nv_bfloat16 h = __float2bfloat16(w);
    __nv_bfloat16 l = __float2bfloat16(w - __bfloat162float(h));
    *(uint16_t*)(img + n * WROW + k * 2) = __bfloat16_as_ushort(h);
    *(uint16_t*)(img + WLO + n * WROW + k * 2) = __bfloat16_as_ushort(l);
}

// ---------------- tensor-core GEMM (mma.sync bf16 split) ----------------
#define TG_SMEM_TOTAL (WIMGSZ + 512)

__global__ void __launch_bounds__(256) tgemm(
    const float* __restrict__ A, const unsigned char* __restrict__ Bimg,
    const float* __restrict__ bias, float* __restrict__ C,
    float* __restrict__ colsum, int M, int act)
{
    extern __shared__ unsigned char smem[];
    float* scs = (float*)(smem + WIMGSZ);
    const int tid = threadIdx.x, wid = tid >> 5, lane = tid & 31;
    const int g = lane >> 2, tig = lane & 3;

    {
        const uint4* src = (const uint4*)Bimg;
        uint4* dst = (uint4*)smem;
#pragma unroll
        for (int i = 0; i < 17; i++) {
            int idx = tid + 256 * i;
            if (idx < WIMGSZ / 16) dst[idx] = src[idx];
        }
    }
    if (act == ACT_TANHSUM && tid < 128) scs[tid] = 0.f;
    __syncthreads();

    const int rowA = blockIdx.x * 128 + wid * 16 + g;
    const int rowB = rowA + 8;
    const bool vA = rowA < M, vB = rowB < M;

    float4 acc[16];
#pragma unroll
    for (int nt = 0; nt < 16; nt++) acc[nt] = make_float4(0.f, 0.f, 0.f, 0.f);

    const float* ArA = A + (size_t)rowA * 128;
    const float* ArB = A + (size_t)rowB * 128;

#pragma unroll
    for (int ks = 0; ks < 8; ks++) {
        const int k0 = ks * 16;
        float2 p00 = make_float2(0.f, 0.f), p01 = p00, p10 = p00, p11 = p00;
        if (vA) {
            p00 = *(const float2*)(ArA + k0 + 2 * tig);
            p01 = *(const float2*)(ArA + k0 + 2 * tig + 8);
        }
        if (vB) {
            p10 = *(const float2*)(ArB + k0 + 2 * tig);
            p11 = *(const float2*)(ArB + k0 + 2 * tig + 8);
        }
        uint32_t ah0 = pack_bf(p00.x, p00.y), ah1 = pack_bf(p10.x, p10.y);
        uint32_t ah2 = pack_bf(p01.x, p01.y), ah3 = pack_bf(p11.x, p11.y);
        __nv_bfloat162 h00 = *(__nv_bfloat162*)&ah0, h10 = *(__nv_bfloat162*)&ah1;
        __nv_bfloat162 h01 = *(__nv_bfloat162*)&ah2, h11 = *(__nv_bfloat162*)&ah3;
        uint32_t al0 = pack_bf(p00.x - __bfloat162float(h00.x), p00.y - __bfloat162float(h00.y));
        uint32_t al1 = pack_bf(p10.x - __bfloat162float(h10.x), p10.y - __bfloat162float(h10.y));
        uint32_t al2 = pack_bf(p01.x - __bfloat162float(h01.x), p01.y - __bfloat162float(h01.y));
        uint32_t al3 = pack_bf(p11.x - __bfloat162float(h11.x), p11.y - __bfloat162float(h11.y));

        const unsigned char* bh = smem + (size_t)g * WROW + (k0 + 2 * tig) * 2;
#pragma unroll
        for (int nt = 0; nt < 16; nt++) {
            uint32_t bh0 = *(const uint32_t*)(bh + nt * 8 * WROW);
            uint32_t bh1 = *(const uint32_t*)(bh + nt * 8 * WROW + 16);
            mma_bf16(acc[nt], ah0, ah1, ah2, ah3, bh0, bh1);
            mma_bf16(acc[nt], al0, al1, al2, al3, bh0, bh1);
            uint32_t bl0 = *(const uint32_t*)(bh + WLO + nt * 8 * WROW);
            uint32_t bl1 = *(const uint32_t*)(bh + WLO + nt * 8 * WROW + 16);
            mma_bf16(acc[nt], ah0, ah1, ah2, ah3, bl0, bl1);
        }
    }

    if (act == ACT_TANHSUM) {
#pragma unroll
        for (int nt = 0; nt < 16; nt++) {
            int col = nt * 8 + 2 * tig;
            float b0 = bias[col], b1 = bias[col + 1];
            float s0 = 0.f, s1 = 0.f;
            if (vA) { s0 += tanhf(acc[nt].x + b0); s1 += tanhf(acc[nt].y + b1); }
            if (vB) { s0 += tanhf(acc[nt].z + b0); s1 += tanhf(acc[nt].w + b1); }
            atomicAdd(scs + col, s0);
            atomicAdd(scs + col + 1, s1);
        }
        __syncthreads();
        if (tid < 128) atomicAdd(colsum + tid, scs[tid]);
    } else {
#pragma unroll
        for (int nt = 0; nt < 16; nt++) {
            int col = nt * 8 + 2 * tig;
            float b0 = bias[col], b1 = bias[col + 1];
            float2 oA = make_float2(acc[nt].x + b0, acc[nt].y + b1);
            float2 oB = make_float2(acc[nt].z + b0, acc[nt].w + b1);
            if (act == ACT_RELU) {
                oA.x = fmaxf(oA.x, 0.f); oA.y = fmaxf(oA.y, 0.f);
                oB.x = fmaxf(oB.x, 0.f); oB.y = fmaxf(oB.y, 0.f);
            }
            if (vA) *(float2*)(C + (size_t)rowA * 128 + col) = oA;
            if (vB) *(float2*)(C + (size_t)rowB * 128 + col) = oB;
        }
    }
}

// ---------------- fills ----------------
__global__ void fill_f4(float4* p, float v, int n4) {
    int i = blockIdx.x * blockDim.x + threadIdx.x;
    if (i < n4) p[i] = make_float4(v, v, v, v);
}

// ---------------- per-node attention score dots ----------------
__global__ void scores2(const float* __restrict__ h, int N,
                        const float* __restrict__ a0, const float* __restrict__ a1,
                        float* __restrict__ s0, float* __restrict__ s1)
{
    int idx = blockIdx.x * blockDim.x + threadIdx.x;
    if (idx >= N * 8) return;
    int n = idx >> 3, hd = idx & 7;
    const float4* hp = (const float4*)(h + (size_t)n * 128 + hd * 16);
    const float4* p0 = (const float4*)(a0 + hd * 16);
    const float4* p1 = (const float4*)(a1 + hd * 16);
    float d0 = 0, d1 = 0;
#pragma unroll
    for (int i = 0; i < 4; i++) {
        float4 hv = hp[i];
        float4 av = p0[i];
        d0 += hv.x * av.x + hv.y * av.y + hv.z * av.z + hv.w * av.w;
        av = p1[i];
        d1 += hv.x * av.x + hv.y * av.y + hv.z * av.z + hv.w * av.w;
    }
    s0[idx] = d0; s1[idx] = d1;
}

__global__ void scores4(const float* __restrict__ h, int N,
                        const float* __restrict__ a0, const float* __restrict__ a1,
                        const float* __restrict__ a2, const float* __restrict__ a3,
                        float* __restrict__ s0, float* __restrict__ s1,
                        float* __restrict__ s2, float* __restrict__ s3)
{
    int idx = blockIdx.x * blockDim.x + threadIdx.x;
    if (idx >= N * 8) return;
    int n = idx >> 3, hd = idx & 7;
    const float4* hp = (const float4*)(h + (size_t)n * 128 + hd * 16);
    const float4* p0 = (const float4*)(a0 + hd * 16);
    const float4* p1 = (const float4*)(a1 + hd * 16);
    const float4* p2 = (const float4*)(a2 + hd * 16);
    const float4* p3 = (const float4*)(a3 + hd * 16);
    float d0 = 0, d1 = 0, d2 = 0, d3 = 0;
#pragma unroll
    for (int i = 0; i < 4; i++) {
        float4 hv = hp[i];
        float4 av = p0[i];
        d0 += hv.x * av.x + hv.y * av.y + hv.z * av.z + hv.w * av.w;
        av = p1[i];
        d1 += hv.x * av.x + hv.y * av.y + hv.z * av.z + hv.w * av.w;
        av = p2[i];
        d2 += hv.x * av.x + hv.y * av.y + hv.z * av.z + hv.w * av.w;
        av = p3[i];
        d3 += hv.x * av.x + hv.y * av.y + hv.z * av.z + hv.w * av.w;
    }
    s0[idx] = d0; s1[idx] = d1; s2[idx] = d2; s3[idx] = d3;
}

// ---------------- CSR aggregation: warp per destination node ----------------
// out[d] = relu( (sum_e exp(a_e) * h_src[e]) / (sum_e exp(a_e) + 1e-16) )
__global__ void __launch_bounds__(256) agg_k(
    const float* __restrict__ hsrc, const float* __restrict__ ssrc,
    const float* __restrict__ sdst, const int* __restrict__ rp,
    const int* __restrict__ srcs, float* __restrict__ out, int Ndst)
{
    int d = blockIdx.x * 8 + (threadIdx.x >> 5);
    if (d >= Ndst) return;
    int lane = threadIdx.x & 31, hd = lane >> 2;
    float sdh = __ldg(sdst + d * 8 + hd);
    int beg = __ldg(rp + d), end = __ldg(rp + d + 1);

    float4 acc = make_float4(0.f, 0.f, 0.f, 0.f);
    float se = 0.f;
    int s = (beg < end) ? __ldg(srcs + beg) : 0;
    for (int i = beg; i < end; i++) {
        int sn = (i + 1 < end) ? __ldg(srcs + i + 1) : 0;
        float a = __ldg(ssrc + s * 8 + hd) + sdh;
        a = a > 0.f ? a : NEG * a;
        float ex = __expf(a);
        float4 h = *((const float4*)(hsrc + (size_t)s * 128) + lane);
        acc.x = fmaf(ex, h.x, acc.x);
        acc.y = fmaf(ex, h.y, acc.y);
        acc.z = fmaf(ex, h.z, acc.z);
        acc.w = fmaf(ex, h.w, acc.w);
        se += ex;
        s = sn;
    }
    float inv = 1.f / (se + 1e-16f);
    float4 r;
    r.x = fmaxf(acc.x * inv, 0.f);
    r.y = fmaxf(acc.y * inv, 0.f);
    r.z = fmaxf(acc.z * inv, 0.f);
    r.w = fmaxf(acc.w * inv, 0.f);
    *((float4*)(out + (size_t)d * 128) + lane) = r;
}

// ---------------- semantic softmax (2 metapaths) ----------------
__global__ void sem_softmax(const float* __restrict__ q, const float* __restrict__ cs,
                            float* __restrict__ attn)
{
    __shared__ float sc[2];
    int m = threadIdx.x >> 5, lane = threadIdx.x & 31;
    float s = 0;
#pragma unroll
    for (int i = 0; i < 4; i++) s += q[lane + 32 * i] * cs[m * 128 + lane + 32 * i];
#pragma unroll
    for (int o = 16; o; o >>= 1) s += __shfl_xor_sync(0xffffffffu, s, o);
    if (lane == 0) sc[m] = s / 20000.f;
    __syncthreads();
    if (threadIdx.x == 0) {
        float mx = fmaxf(sc[0], sc[1]);
        float e0 = __expf(sc[0] - mx), e1 = __expf(sc[1] - mx);
        float inv = 1.f / (e0 + e1);
        attn[0] = e0 * inv; attn[1] = e1 * inv;
    }
}

// ---------------- (semantic combine) + LayerNorm; inputs already relu-normalized ----
__global__ void combine_ln(const float* __restrict__ o1, const float* __restrict__ o2,
                           const float* __restrict__ attn,
                           const float* __restrict__ g, const float* __restrict__ b,
                           float* __restrict__ out, int N)
{
    int idx = blockIdx.x * blockDim.x + threadIdx.x;
    int n = idx >> 5, lane = idx & 31;
    if (n >= N) return;
    float4 v = *((const float4*)(o1 + (size_t)n * 128) + lane);
    if (o2) {
        float a0 = attn[0], a1 = attn[1];
        float4 u = *((const float4*)(o2 + (size_t)n * 128) + lane);
        v.x = a0 * v.x + a1 * u.x;
        v.y = a0 * v.y + a1 * u.y;
        v.z = a0 * v.z + a1 * u.z;
        v.w = a0 * v.w + a1 * u.w;
    }
    float s = v.x + v.y + v.z + v.w;
#pragma unroll
    for (int o = 16; o; o >>= 1) s += __shfl_xor_sync(0xffffffffu, s, o);
    float mu = s * (1.f / 128.f);
    float dx = v.x - mu, dy = v.y - mu, dz = v.z - mu, dw = v.w - mu;
    float qv = dx * dx + dy * dy + dz * dz + dw * dw;
#pragma unroll
    for (int o = 16; o; o >>= 1) qv += __shfl_xor_sync(0xffffffffu, qv, o);
    float rs = rsqrtf(qv * (1.f / 128.f) + 1e-5f);
    float4 g4 = *((const float4*)g + lane);
    float4 b4 = *((const float4*)b + lane);
    float4 r;
    r.x = dx * rs * g4.x + b4.x;
    r.y = dy * rs * g4.y + b4.y;
    r.z = dz * rs * g4.z + b4.z;
    r.w = dw * rs * g4.w + b4.w;
    *((float4*)(out + (size_t)n * 128) + lane) = r;
}

// ---------------- fusion over 2 layers ----------------
__global__ void fuse_k(const float* __restrict__ s0, const float* __restrict__ s1,
                       const float* __restrict__ g0, const float* __restrict__ g1,
                       const float* __restrict__ fw, float* __restrict__ z)
{
    int idx = blockIdx.x * blockDim.x + threadIdx.x;
    if (idx >= N_ALL * 32) return;
    int n = idx >> 5, c = idx & 31;
    float w0 = fw[0], w1 = fw[1];
    float inv = 1.f / (w0 + w1);
    float4 a, b;
    if (n < N_SNP) {
        a = ((const float4*)(s0 + (size_t)n * 128))[c];
        b = ((const float4*)(s1 + (size_t)n * 128))[c];
    } else {
        int m = n - N_SNP;
        a = ((const float4*)(g0 + (size_t)m * 128))[c];
        b = ((const float4*)(g1 + (size_t)m * 128))[c];
    }
    float4 r;
    r.x = (w0 * a.x + w1 * b.x) * inv;
    r.y = (w0 * a.y + w1 * b.y) * inv;
    r.z = (w0 * a.z + w1 * b.z) * inv;
    r.w = (w0 * a.w + w1 * b.w) * inv;
    ((float4*)(z + (size_t)n * 128))[c] = r;
}

// ---------------- final 128->2 projection ----------------
__global__ void out_k(const float* __restrict__ A, const float* __restrict__ W,
                      const float* __restrict__ b, float* __restrict__ out, int M)
{
    int idx = blockIdx.x * blockDim.x + threadIdx.x;
    int n = idx >> 5, lane = idx & 31;
    if (n >= M) return;
    const float* ar = A + (size_t)n * 128;
    float a0 = 0, a1 = 0;
#pragma unroll
    for (int i = 0; i < 4; i++) {
        float v = ar[lane + 32 * i];
        a0 += v * W[(lane + 32 * i) * 2];
        a1 += v * W[(lane + 32 * i) * 2 + 1];
    }
#pragma unroll
    for (int o = 16; o; o >>= 1) {
        a0 += __shfl_xor_sync(0xffffffffu, a0, o);
        a1 += __shfl_xor_sync(0xffffffffu, a1, o);
    }
    if (lane == 0) { out[(size_t)n * 2] = a0 + b[0]; out[(size_t)n * 2 + 1] = a1 + b[1]; }
}

static inline int cdiv(long a, int b) { return (int)((a + b - 1) / b); }

extern "C" void kernel_launch(void* const* d_in, const int* in_sizes, int n_in,
                              void* d_out, int out_size)
{
    const float* x_snp  = (const float*)d_in[0];
    const float* x_gene = (const float*)d_in[1];
    const float* Wp_snp = (const float*)d_in[2];
    const float* bp_snp = (const float*)d_in[3];
    const float* Wp_gene= (const float*)d_in[4];
    const float* bp_gene= (const float*)d_in[5];
    const float* a_src  = (const float*)d_in[6];
    const float* a_dst  = (const float*)d_in[7];
    const float* Wk     = (const float*)d_in[8];
    const float* bk     = (const float*)d_in[9];
    const float* qvp    = (const float*)d_in[10];
    const float* ln_g   = (const float*)d_in[11];
    const float* ln_b   = (const float*)d_in[12];
    const float* fw     = (const float*)d_in[13];
    const float* Wfp    = (const float*)d_in[14];
    const float* bfp    = (const float*)d_in[15];
    const float* Wo1    = (const float*)d_in[16];
    const float* bo1    = (const float*)d_in[17];
    const float* Wo2    = (const float*)d_in[18];
    const float* bo2    = (const float*)d_in[19];
    const int* sg_s = (const int*)d_in[20];
    const int* sg_d = (const int*)d_in[21];
    const int* gs_s = (const int*)d_in[22];
    const int* gs_d = (const int*)d_in[23];
    const int* gg_s = (const int*)d_in[24];
    const int* gg_d = (const int*)d_in[25];
    const int E_sg = in_sizes[20], E_gs = in_sizes[22], E_gg = in_sizes[24];

    float *hs, *hg, *ssrc_sg, *sdst_gs, *sdst_sg, *ssrc_gs, *ssrc_gg, *sdst_gg;
    float *o_sg, *o_gs, *o_gg;
    float *out_s0, *out_s1, *out_g0, *out_g1, *sem, *attn, *buf1, *buf2;
    unsigned char* wimg;
    int *rp_sg, *rp_gs, *rp_gg, *deg, *cur, *bsum, *ss_sg, *ss_gs, *ss_gg;
    cudaGetSymbolAddress((void**)&hs, g_hs);
    cudaGetSymbolAddress((void**)&hg, g_hg);
    cudaGetSymbolAddress((void**)&ssrc_sg, g_ssrc_sg);
    cudaGetSymbolAddress((void**)&sdst_gs, g_sdst_gs);
    cudaGetSymbolAddress((void**)&sdst_sg, g_sdst_sg);
    cudaGetSymbolAddress((void**)&ssrc_gs, g_ssrc_gs);
    cudaGetSymbolAddress((void**)&ssrc_gg, g_ssrc_gg);
    cudaGetSymbolAddress((void**)&sdst_gg, g_sdst_gg);
    cudaGetSymbolAddress((void**)&o_sg, g_o_sg);
    cudaGetSymbolAddress((void**)&o_gs, g_o_gs);
    cudaGetSymbolAddress((void**)&o_gg, g_o_gg);
    cudaGetSymbolAddress((void**)&out_s0, g_out_s0);
    cudaGetSymbolAddress((void**)&out_s1, g_out_s1);
    cudaGetSymbolAddress((void**)&out_g0, g_out_g0);
    cudaGetSymbolAddress((void**)&out_g1, g_out_g1);
    cudaGetSymbolAddress((void**)&sem, g_sem);
    cudaGetSymbolAddress((void**)&attn, g_attn);
    cudaGetSymbolAddress((void**)&buf1, g_buf1);
    cudaGetSymbolAddress((void**)&buf2, g_buf2);
    cudaGetSymbolAddress((void**)&wimg, g_wimg);
    cudaGetSymbolAddress((void**)&rp_sg, g_rp_sg);
    cudaGetSymbolAddress((void**)&rp_gs, g_rp_gs);
    cudaGetSymbolAddress((void**)&rp_gg, g_rp_gg);
    cudaGetSymbolAddress((void**)&deg, g_deg);
    cudaGetSymbolAddress((void**)&cur, g_cur);
    cudaGetSymbolAddress((void**)&bsum, g_bsum);
    cudaGetSymbolAddress((void**)&ss_sg, g_ss_sg);
    cudaGetSymbolAddress((void**)&ss_gs, g_ss_gs);
    cudaGetSymbolAddress((void**)&ss_gg, g_ss_gg);

    cudaFuncSetAttribute(tgemm, cudaFuncAttributeMaxDynamicSharedMemorySize, TG_SMEM_TOTAL);

    // weight images: 0,1: Wp_snp l0/l1; 2,3: Wp_gene; 4,5: Wk; 6: Wfp; 7: Wo1
    wprep<<<64, 256>>>(Wp_snp,          wimg + 0 * WIMGSZ);
    wprep<<<64, 256>>>(Wp_snp + 16384,  wimg + 1 * WIMGSZ);
    wprep<<<64, 256>>>(Wp_gene,         wimg + 2 * WIMGSZ);
    wprep<<<64, 256>>>(Wp_gene + 16384, wimg + 3 * WIMGSZ);
    wprep<<<64, 256>>>(Wk,              wimg + 4 * WIMGSZ);
    wprep<<<64, 256>>>(Wk + 16384,      wimg + 5 * WIMGSZ);
    wprep<<<64, 256>>>(Wfp,             wimg + 6 * WIMGSZ);
    wprep<<<64, 256>>>(Wo1,             wimg + 7 * WIMGSZ);

    // ---- build CSR (once; reused by both layers) ----
    struct { const int *src, *dst; int E, Nd; int *rp, *ss; } et[3] = {
        { sg_s, sg_d, E_sg, N_GENE, rp_sg, ss_sg },
        { gs_s, gs_d, E_gs, N_SNP,  rp_gs, ss_gs },
        { gg_s, gg_d, E_gg, N_GENE, rp_gg, ss_gg },
    };
    for (int t = 0; t < 3; t++) {
        int Nd = et[t].Nd, E = et[t].E;
        int nb = cdiv(Nd, 1024);
        zero_i<<<cdiv(Nd, 256), 256>>>(deg, Nd);
        hist_k<<<cdiv(E, 256), 256>>>(et[t].dst, E, deg);
        bsum_k<<<nb, 1024>>>(deg, Nd, bsum);
        bscan_k<<<1, 32>>>(bsum, nb);
        scan_k<<<nb, 1024>>>(deg, bsum, Nd, et[t].rp);
        zero_i<<<cdiv(Nd, 256), 256>>>(cur, Nd);
        scatter_k<<<cdiv(E, 256), 256>>>(et[t].src, et[t].dst, E, et[t].rp, cur, et[t].ss);
    }

    const int TS = cdiv(N_SNP, 128), TG = cdiv(N_GENE, 128), TA = cdiv(N_ALL, 128);

    for (int l = 0; l < 2; ++l) {
        const float* ins = l ? out_s0 : x_snp;
        const float* ing = l ? out_g0 : x_gene;

        tgemm<<<TS, 256, TG_SMEM_TOTAL>>>(ins, wimg + (0 + l) * WIMGSZ, bp_snp + l * 128,
                                          hs, nullptr, N_SNP, ACT_NONE);
        tgemm<<<TG, 256, TG_SMEM_TOTAL>>>(ing, wimg + (2 + l) * WIMGSZ, bp_gene + l * 128,
                                          hg, nullptr, N_GENE, ACT_NONE);

        scores2<<<cdiv((long)N_SNP * 8, 256), 256>>>(hs, N_SNP,
            a_src + (l * 3 + 0) * 128, a_dst + (l * 3 + 1) * 128, ssrc_sg, sdst_gs);
        scores4<<<cdiv((long)N_GENE * 8, 256), 256>>>(hg, N_GENE,
            a_dst + (l * 3 + 0) * 128, a_src + (l * 3 + 1) * 128,
            a_src + (l * 3 + 2) * 128, a_dst + (l * 3 + 2) * 128,
            sdst_sg, ssrc_gs, ssrc_gg, sdst_gg);

        agg_k<<<cdiv(N_GENE, 8), 256>>>(hs, ssrc_sg, sdst_sg, rp_sg, ss_sg, o_sg, N_GENE);
        agg_k<<<cdiv(N_SNP, 8), 256>>>(hg, ssrc_gs, sdst_gs, rp_gs, ss_gs, o_gs, N_SNP);
        agg_k<<<cdiv(N_GENE, 8), 256>>>(hg, ssrc_gg, sdst_gg, rp_gg, ss_gg, o_gg, N_GENE);

        fill_f4<<<1, 64>>>((float4*)sem, 0.f, 64);
        tgemm<<<TG, 256, TG_SMEM_TOTAL>>>(o_sg, wimg + (4 + l) * WIMGSZ, bk + l * 128,
                                          nullptr, sem, N_GENE, ACT_TANHSUM);
        tgemm<<<TG, 256, TG_SMEM_TOTAL>>>(o_gg, wimg + (4 + l) * WIMGSZ, bk + l * 128,
                                          nullptr, sem + 128, N_GENE, ACT_TANHSUM);
        sem_softmax<<<1, 64>>>(qvp + l * 128, sem, attn);

        float* og = l ? out_g1 : out_g0;
        float* os = l ? out_s1 : out_s0;
        combine_ln<<<cdiv((long)N_GENE * 32, 256), 256>>>(o_sg, o_gg, attn,
            ln_g + l * 128, ln_b + l * 128, og, N_GENE);
        combine_ln<<<cdiv((long)N_SNP * 32, 256), 256>>>(o_gs, nullptr, nullptr,
            ln_g + l * 128, ln_b + l * 128, os, N_SNP);
    }

    fuse_k<<<cdiv((long)N_ALL * 32, 256), 256>>>(out_s0, out_s1, out_g0, out_g1, fw, buf1);
    tgemm<<<TA, 256, TG_SMEM_TOTAL>>>(buf1, wimg + 6 * WIMGSZ, bfp, buf2, nullptr, N_ALL, ACT_RELU);
    tgemm<<<TA, 256, TG_SMEM_TOTAL>>>(buf2, wimg + 7 * WIMGSZ, bo1, buf1, nullptr, N_ALL, ACT_RELU);
    out_k<<<cdiv((long)N_ALL * 32, 256), 256>>>(buf1, Wo2, bo2, (float*)d_out, N_ALL);
}

// round 6
// speedup vs baseline: 1.9460x; 1.0487x over previous
#include <cuda_runtime.h>
#include <cuda_bf16.h>
#include <cstdint>

#define N_SNP  100000
#define N_GENE 20000
#define N_ALL  120000
#define HID    128
#define NEG    0.2f

#define ACT_NONE    0
#define ACT_RELU    1
#define ACT_TANHSUM 2

#define E_SG_MAX 500000
#define E_GS_MAX 500000
#define E_GG_MAX 150000

// weight image geometry: [n][k] row-major bf16, padded row stride 272B,
// hi image at 0, lo image at 34816; total 69632 bytes per weight.
#define WROW   272
#define WLO    34816
#define WIMGSZ 69632

// ---------------- device scratch (static, allocation-free) ----------------
__device__ float    g_hs[N_SNP * HID];
__device__ float    g_hg[N_GENE * HID];
__device__ float    g_ssrc_sg[N_SNP * 8];
__device__ float    g_sdst_gs[N_SNP * 8];
__device__ float    g_sdst_sg[N_GENE * 8];
__device__ float    g_ssrc_gs[N_GENE * 8];
__device__ float    g_ssrc_gg[N_GENE * 8];
__device__ float    g_sdst_gg[N_GENE * 8];
__device__ float    g_o_sg[N_GENE * HID];
__device__ float    g_o_gs[N_SNP * HID];
__device__ float    g_o_gg[N_GENE * HID];
__device__ float    g_out_s0[N_SNP * HID];
__device__ float    g_out_g0[N_GENE * HID];
__device__ float    g_sem[2 * HID];
__device__ float    g_attn[2];
__device__ float    g_buf1[N_ALL * HID];
__device__ float    g_buf2[N_ALL * HID];
__device__ __align__(16) unsigned char g_wimg[8 * WIMGSZ];
// CSR build scratch
__device__ int g_rp_sg[N_GENE + 1];
__device__ int g_rp_gs[N_SNP + 1];
__device__ int g_rp_gg[N_GENE + 1];
__device__ int g_deg[N_SNP];
__device__ int g_cur[N_SNP];
__device__ int g_bsum[128];
__device__ int g_ss_sg[E_SG_MAX];
__device__ int g_ss_gs[E_GS_MAX];
__device__ int g_ss_gg[E_GG_MAX];

__device__ __forceinline__ uint32_t pack_bf(float x, float y) {
    __nv_bfloat162 t = __floats2bfloat162_rn(x, y);
    return *(uint32_t*)&t;
}
__device__ __forceinline__ void mma_bf16(float4& c, uint32_t a0, uint32_t a1,
                                         uint32_t a2, uint32_t a3,
                                         uint32_t b0, uint32_t b1) {
    asm volatile("mma.sync.aligned.m16n8k16.row.col.f32.bf16.bf16.f32 "
                 "{%0,%1,%2,%3}, {%4,%5,%6,%7}, {%8,%9}, {%0,%1,%2,%3};"
                 : "+f"(c.x), "+f"(c.y), "+f"(c.z), "+f"(c.w)
                 : "r"(a0), "r"(a1), "r"(a2), "r"(a3), "r"(b0), "r"(b1));
}

// ---------------- CSR build ----------------
__global__ void zero_i(int* p, int n) {
    int i = blockIdx.x * blockDim.x + threadIdx.x;
    if (i < n) p[i] = 0;
}
__global__ void hist_k(const int* __restrict__ dst, int E, int* __restrict__ deg) {
    int i = blockIdx.x * blockDim.x + threadIdx.x;
    if (i < E) atomicAdd(deg + dst[i], 1);
}
__global__ void bsum_k(const int* __restrict__ deg, int n, int* __restrict__ bsum) {
    __shared__ int sw[32];
    int i = blockIdx.x * 1024 + threadIdx.x;
    int v = (i < n) ? deg[i] : 0;
#pragma unroll
    for (int o = 16; o; o >>= 1) v += __shfl_xor_sync(0xffffffffu, v, o);
    if ((threadIdx.x & 31) == 0) sw[threadIdx.x >> 5] = v;
    __syncthreads();
    if (threadIdx.x < 32) {
        int t = sw[threadIdx.x];
#pragma unroll
        for (int o = 16; o; o >>= 1) t += __shfl_xor_sync(0xffffffffu, t, o);
        if (threadIdx.x == 0) bsum[blockIdx.x] = t;
    }
}
__global__ void bscan_k(int* bsum, int nb) {
    if (threadIdx.x == 0) {
        int c = 0;
        for (int i = 0; i < nb; i++) { int v = bsum[i]; bsum[i] = c; c += v; }
    }
}
__global__ void scan_k(const int* __restrict__ deg, const int* __restrict__ bsum,
                       int n, int* __restrict__ rp) {
    __shared__ int sm[1024];
    int tid = threadIdx.x;
    int i = blockIdx.x * 1024 + tid;
    int v = (i < n) ? deg[i] : 0;
    sm[tid] = v;
    __syncthreads();
#pragma unroll
    for (int off = 1; off < 1024; off <<= 1) {
        int t = (tid >= off) ? sm[tid - off] : 0;
        __syncthreads();
        sm[tid] += t;
        __syncthreads();
    }
    int incl = sm[tid];
    int base = bsum[blockIdx.x];
    if (i < n) rp[i] = base + incl - v;
    if (i == n - 1) rp[n] = base + incl;
}
__global__ void scatter_k(const int* __restrict__ src, const int* __restrict__ dst, int E,
                          const int* __restrict__ rp, int* __restrict__ cur,
                          int* __restrict__ out) {
    int e = blockIdx.x * blockDim.x + threadIdx.x;
    if (e >= E) return;
    int d = dst[e];
    int pos = rp[d] + atomicAdd(cur + d, 1);
    out[pos] = src[e];
}

// ---------------- weight prep: all 8 matrices in one launch ----------------
__global__ void wprep8(const float* __restrict__ W0, const float* __restrict__ W1,
                       const float* __restrict__ W2, const float* __restrict__ W3,
                       const float* __restrict__ W4, const float* __restrict__ W5,
                       const float* __restrict__ W6, const float* __restrict__ W7,
                       unsigned char* __restrict__ imgbase) {
    int b = blockIdx.x >> 6;                        // 0..7
    const float* W;
    if      (b == 0) W = W0; else if (b == 1) W = W1;
    else if (b == 2) W = W2; else if (b == 3) W = W3;
    else if (b == 4) W = W4; else if (b == 5) W = W5;
    else if (b == 6) W = W6; else              W = W7;
    unsigned char* img = imgbase + (size_t)b * WIMGSZ;
    int i = (blockIdx.x & 63) * 256 + threadIdx.x;  // 0..16383
    int n = i >> 7, k = i & 127;                    // Bimg[n][k] = W[k][n]
    float w = W[k * 128 + n];
    __nv_bfloat16 h = __float2bfloat16(w);
    __nv_bfloat16 l = __float2bfloat16(w - __bfloat162float(h));
    *(uint16_t*)(img + n * WROW + k * 2) = __bfloat16_as_ushort(h);
    *(uint16_t*)(img + WLO + n * WROW + k * 2) = __bfloat16_as_ushort(l);
}

// ---------------- tensor-core GEMM (mma.sync bf16 split) ----------------
#define TG_SMEM_TOTAL (WIMGSZ + 512)

__global__ void __launch_bounds__(256) tgemm(
    const float* __restrict__ A, const unsigned char* __restrict__ Bimg,
    const float* __restrict__ bias, float* __restrict__ C,
    float* __restrict__ colsum, int M, int act)
{
    extern __shared__ unsigned char smem[];
    float* scs = (float*)(smem + WIMGSZ);
    const int tid = threadIdx.x, wid = tid >> 5, lane = tid & 31;
    const int g = lane >> 2, tig = lane & 3;

    {
        const uint4* src = (const uint4*)Bimg;
        uint4* dst = (uint4*)smem;
#pragma unroll
        for (int i = 0; i < 17; i++) {
            int idx = tid + 256 * i;
            if (idx < WIMGSZ / 16) dst[idx] = src[idx];
        }
    }
    if (act == ACT_TANHSUM && tid < 128) scs[tid] = 0.f;
    __syncthreads();

    const int rowA = blockIdx.x * 128 + wid * 16 + g;
    const int rowB = rowA + 8;
    const bool vA = rowA < M, vB = rowB < M;

    float4 acc[16];
#pragma unroll
    for (int nt = 0; nt < 16; nt++) acc[nt] = make_float4(0.f, 0.f, 0.f, 0.f);

    const float* ArA = A + (size_t)rowA * 128;
    const float* ArB = A + (size_t)rowB * 128;

#pragma unroll
    for (int ks = 0; ks < 8; ks++) {
        const int k0 = ks * 16;
        float2 p00 = make_float2(0.f, 0.f), p01 = p00, p10 = p00, p11 = p00;
        if (vA) {
            p00 = *(const float2*)(ArA + k0 + 2 * tig);
            p01 = *(const float2*)(ArA + k0 + 2 * tig + 8);
        }
        if (vB) {
            p10 = *(const float2*)(ArB + k0 + 2 * tig);
            p11 = *(const float2*)(ArB + k0 + 2 * tig + 8);
        }
        uint32_t ah0 = pack_bf(p00.x, p00.y), ah1 = pack_bf(p10.x, p10.y);
        uint32_t ah2 = pack_bf(p01.x, p01.y), ah3 = pack_bf(p11.x, p11.y);
        __nv_bfloat162 h00 = *(__nv_bfloat162*)&ah0, h10 = *(__nv_bfloat162*)&ah1;
        __nv_bfloat162 h01 = *(__nv_bfloat162*)&ah2, h11 = *(__nv_bfloat162*)&ah3;
        uint32_t al0 = pack_bf(p00.x - __bfloat162float(h00.x), p00.y - __bfloat162float(h00.y));
        uint32_t al1 = pack_bf(p10.x - __bfloat162float(h10.x), p10.y - __bfloat162float(h10.y));
        uint32_t al2 = pack_bf(p01.x - __bfloat162float(h01.x), p01.y - __bfloat162float(h01.y));
        uint32_t al3 = pack_bf(p11.x - __bfloat162float(h11.x), p11.y - __bfloat162float(h11.y));

        const unsigned char* bh = smem + (size_t)g * WROW + (k0 + 2 * tig) * 2;
#pragma unroll
        for (int nt = 0; nt < 16; nt++) {
            uint32_t bh0 = *(const uint32_t*)(bh + nt * 8 * WROW);
            uint32_t bh1 = *(const uint32_t*)(bh + nt * 8 * WROW + 16);
            mma_bf16(acc[nt], ah0, ah1, ah2, ah3, bh0, bh1);
            mma_bf16(acc[nt], al0, al1, al2, al3, bh0, bh1);
            uint32_t bl0 = *(const uint32_t*)(bh + WLO + nt * 8 * WROW);
            uint32_t bl1 = *(const uint32_t*)(bh + WLO + nt * 8 * WROW + 16);
            mma_bf16(acc[nt], ah0, ah1, ah2, ah3, bl0, bl1);
        }
    }

    if (act == ACT_TANHSUM) {
#pragma unroll
        for (int nt = 0; nt < 16; nt++) {
            int col = nt * 8 + 2 * tig;
            float b0 = bias[col], b1 = bias[col + 1];
            float s0 = 0.f, s1 = 0.f;
            if (vA) { s0 += tanhf(acc[nt].x + b0); s1 += tanhf(acc[nt].y + b1); }
            if (vB) { s0 += tanhf(acc[nt].z + b0); s1 += tanhf(acc[nt].w + b1); }
            atomicAdd(scs + col, s0);
            atomicAdd(scs + col + 1, s1);
        }
        __syncthreads();
        if (tid < 128) atomicAdd(colsum + tid, scs[tid]);
    } else {
#pragma unroll
        for (int nt = 0; nt < 16; nt++) {
            int col = nt * 8 + 2 * tig;
            float b0 = bias[col], b1 = bias[col + 1];
            float2 oA = make_float2(acc[nt].x + b0, acc[nt].y + b1);
            float2 oB = make_float2(acc[nt].z + b0, acc[nt].w + b1);
            if (act == ACT_RELU) {
                oA.x = fmaxf(oA.x, 0.f); oA.y = fmaxf(oA.y, 0.f);
                oB.x = fmaxf(oB.x, 0.f); oB.y = fmaxf(oB.y, 0.f);
            }
            if (vA) *(float2*)(C + (size_t)rowA * 128 + col) = oA;
            if (vB) *(float2*)(C + (size_t)rowB * 128 + col) = oB;
        }
    }
}

// ---------------- fills ----------------
__global__ void fill_f4(float4* p, float v, int n4) {
    int i = blockIdx.x * blockDim.x + threadIdx.x;
    if (i < n4) p[i] = make_float4(v, v, v, v);
}

// ---------------- per-node attention score dots ----------------
__global__ void scores2(const float* __restrict__ h, int N,
                        const float* __restrict__ a0, const float* __restrict__ a1,
                        float* __restrict__ s0, float* __restrict__ s1)
{
    int idx = blockIdx.x * blockDim.x + threadIdx.x;
    if (idx >= N * 8) return;
    int n = idx >> 3, hd = idx & 7;
    const float4* hp = (const float4*)(h + (size_t)n * 128 + hd * 16);
    const float4* p0 = (const float4*)(a0 + hd * 16);
    const float4* p1 = (const float4*)(a1 + hd * 16);
    float d0 = 0, d1 = 0;
#pragma unroll
    for (int i = 0; i < 4; i++) {
        float4 hv = hp[i];
        float4 av = p0[i];
        d0 += hv.x * av.x + hv.y * av.y + hv.z * av.z + hv.w * av.w;
        av = p1[i];
        d1 += hv.x * av.x + hv.y * av.y + hv.z * av.z + hv.w * av.w;
    }
    s0[idx] = d0; s1[idx] = d1;
}

__global__ void scores4(const float* __restrict__ h, int N,
                        const float* __restrict__ a0, const float* __restrict__ a1,
                        const float* __restrict__ a2, const float* __restrict__ a3,
                        float* __restrict__ s0, float* __restrict__ s1,
                        float* __restrict__ s2, float* __restrict__ s3)
{
    int idx = blockIdx.x * blockDim.x + threadIdx.x;
    if (idx >= N * 8) return;
    int n = idx >> 3, hd = idx & 7;
    const float4* hp = (const float4*)(h + (size_t)n * 128 + hd * 16);
    const float4* p0 = (const float4*)(a0 + hd * 16);
    const float4* p1 = (const float4*)(a1 + hd * 16);
    const float4* p2 = (const float4*)(a2 + hd * 16);
    const float4* p3 = (const float4*)(a3 + hd * 16);
    float d0 = 0, d1 = 0, d2 = 0, d3 = 0;
#pragma unroll
    for (int i = 0; i < 4; i++) {
        float4 hv = hp[i];
        float4 av = p0[i];
        d0 += hv.x * av.x + hv.y * av.y + hv.z * av.z + hv.w * av.w;
        av = p1[i];
        d1 += hv.x * av.x + hv.y * av.y + hv.z * av.z + hv.w * av.w;
        av = p2[i];
        d2 += hv.x * av.x + hv.y * av.y + hv.z * av.z + hv.w * av.w;
        av = p3[i];
        d3 += hv.x * av.x + hv.y * av.y + hv.z * av.z + hv.w * av.w;
    }
    s0[idx] = d0; s1[idx] = d1; s2[idx] = d2; s3[idx] = d3;
}

// ---------------- CSR aggregation: warp per destination, 2-edge unroll ----------------
// out[d] = relu( (sum_e exp(a_e) * h_src[e]) / (sum_e exp(a_e) + 1e-16) )
__global__ void __launch_bounds__(256) agg_k(
    const float* __restrict__ hsrc, const float* __restrict__ ssrc,
    const float* __restrict__ sdst, const int* __restrict__ rp,
    const int* __restrict__ srcs, float* __restrict__ out, int Ndst)
{
    int d = blockIdx.x * 8 + (threadIdx.x >> 5);
    if (d >= Ndst) return;
    int lane = threadIdx.x & 31, hd = lane >> 2;
    float sdh = __ldg(sdst + d * 8 + hd);
    int beg = __ldg(rp + d), end = __ldg(rp + d + 1);

    float4 acc0 = make_float4(0.f, 0.f, 0.f, 0.f);
    float4 acc1 = make_float4(0.f, 0.f, 0.f, 0.f);
    float se0 = 0.f, se1 = 0.f;

    int i = beg;
    for (; i + 2 <= end; i += 2) {
        int s0 = __ldg(srcs + i), s1 = __ldg(srcs + i + 1);
        float a0 = __ldg(ssrc + s0 * 8 + hd) + sdh;
        float a1 = __ldg(ssrc + s1 * 8 + hd) + sdh;
        float4 h0 = *((const float4*)(hsrc + (size_t)s0 * 128) + lane);
        float4 h1 = *((const float4*)(hsrc + (size_t)s1 * 128) + lane);
        a0 = a0 > 0.f ? a0 : NEG * a0;
        a1 = a1 > 0.f ? a1 : NEG * a1;
        float e0 = __expf(a0), e1 = __expf(a1);
        acc0.x = fmaf(e0, h0.x, acc0.x); acc0.y = fmaf(e0, h0.y, acc0.y);
        acc0.z = fmaf(e0, h0.z, acc0.z); acc0.w = fmaf(e0, h0.w, acc0.w);
        acc1.x = fmaf(e1, h1.x, acc1.x); acc1.y = fmaf(e1, h1.y, acc1.y);
        acc1.z = fmaf(e1, h1.z, acc1.z); acc1.w = fmaf(e1, h1.w, acc1.w);
        se0 += e0; se1 += e1;
    }
    if (i < end) {
        int s0 = __ldg(srcs + i);
        float a0 = __ldg(ssrc + s0 * 8 + hd) + sdh;
        float4 h0 = *((const float4*)(hsrc + (size_t)s0 * 128) + lane);
        a0 = a0 > 0.f ? a0 : NEG * a0;
        float e0 = __expf(a0);
        acc0.x = fmaf(e0, h0.x, acc0.x); acc0.y = fmaf(e0, h0.y, acc0.y);
        acc0.z = fmaf(e0, h0.z, acc0.z); acc0.w = fmaf(e0, h0.w, acc0.w);
        se0 += e0;
    }
    float se = se0 + se1;
    float inv = 1.f / (se + 1e-16f);
    float4 r;
    r.x = fmaxf((acc0.x + acc1.x) * inv, 0.f);
    r.y = fmaxf((acc0.y + acc1.y) * inv, 0.f);
    r.z = fmaxf((acc0.z + acc1.z) * inv, 0.f);
    r.w = fmaxf((acc0.w + acc1.w) * inv, 0.f);
    *((float4*)(out + (size_t)d * 128) + lane) = r;
}

// ---------------- semantic softmax (2 metapaths) ----------------
__global__ void sem_softmax(const float* __restrict__ q, const float* __restrict__ cs,
                            float* __restrict__ attn)
{
    __shared__ float sc[2];
    int m = threadIdx.x >> 5, lane = threadIdx.x & 31;
    float s = 0;
#pragma unroll
    for (int i = 0; i < 4; i++) s += q[lane + 32 * i] * cs[m * 128 + lane + 32 * i];
#pragma unroll
    for (int o = 16; o; o >>= 1) s += __shfl_xor_sync(0xffffffffu, s, o);
    if (lane == 0) sc[m] = s / 20000.f;
    __syncthreads();
    if (threadIdx.x == 0) {
        float mx = fmaxf(sc[0], sc[1]);
        float e0 = __expf(sc[0] - mx), e1 = __expf(sc[1] - mx);
        float inv = 1.f / (e0 + e1);
        attn[0] = e0 * inv; attn[1] = e1 * inv;
    }
}

// ---------------- (semantic combine) + LayerNorm + optional layer fusion ----------
// If prev != null: writes (fw0*prev + fw1*LN(x)) / (fw0+fw1)  [layer-1 path]
__global__ void combine_ln(const float* __restrict__ o1, const float* __restrict__ o2,
                           const float* __restrict__ attn,
                           const float* __restrict__ g, const float* __restrict__ b,
                           const float* __restrict__ prev, const float* __restrict__ fw,
                           float* __restrict__ out, int N)
{
    int idx = blockIdx.x * blockDim.x + threadIdx.x;
    int n = idx >> 5, lane = idx & 31;
    if (n >= N) return;
    float4 v = *((const float4*)(o1 + (size_t)n * 128) + lane);
    if (o2) {
        float a0 = attn[0], a1 = attn[1];
        float4 u = *((const float4*)(o2 + (size_t)n * 128) + lane);
        v.x = a0 * v.x + a1 * u.x;
        v.y = a0 * v.y + a1 * u.y;
        v.z = a0 * v.z + a1 * u.z;
        v.w = a0 * v.w + a1 * u.w;
    }
    float s = v.x + v.y + v.z + v.w;
#pragma unroll
    for (int o = 16; o; o >>= 1) s += __shfl_xor_sync(0xffffffffu, s, o);
    float mu = s * (1.f / 128.f);
    float dx = v.x - mu, dy = v.y - mu, dz = v.z - mu, dw = v.w - mu;
    float qv = dx * dx + dy * dy + dz * dz + dw * dw;
#pragma unroll
    for (int o = 16; o; o >>= 1) qv += __shfl_xor_sync(0xffffffffu, qv, o);
    float rs = rsqrtf(qv * (1.f / 128.f) + 1e-5f);
    float4 g4 = *((const float4*)g + lane);
    float4 b4 = *((const float4*)b + lane);
    float4 r;
    r.x = dx * rs * g4.x + b4.x;
    r.y = dy * rs * g4.y + b4.y;
    r.z = dz * rs * g4.z + b4.z;
    r.w = dw * rs * g4.w + b4.w;
    if (prev) {
        float w0 = fw[0], w1 = fw[1];
        float inv = 1.f / (w0 + w1);
        float4 p = *((const float4*)(prev + (size_t)n * 128) + lane);
        r.x = (w0 * p.x + w1 * r.x) * inv;
        r.y = (w0 * p.y + w1 * r.y) * inv;
        r.z = (w0 * p.z + w1 * r.z) * inv;
        r.w = (w0 * p.w + w1 * r.w) * inv;
    }
    *((float4*)(out + (size_t)n * 128) + lane) = r;
}

// ---------------- final 128->2 projection ----------------
__global__ void out_k(const float* __restrict__ A, const float* __restrict__ W,
                      const float* __restrict__ b, float* __restrict__ out, int M)
{
    int idx = blockIdx.x * blockDim.x + threadIdx.x;
    int n = idx >> 5, lane = idx & 31;
    if (n >= M) return;
    const float* ar = A + (size_t)n * 128;
    float a0 = 0, a1 = 0;
#pragma unroll
    for (int i = 0; i < 4; i++) {
        float v = ar[lane + 32 * i];
        a0 += v * W[(lane + 32 * i) * 2];
        a1 += v * W[(lane + 32 * i) * 2 + 1];
    }
#pragma unroll
    for (int o = 16; o; o >>= 1) {
        a0 += __shfl_xor_sync(0xffffffffu, a0, o);
        a1 += __shfl_xor_sync(0xffffffffu, a1, o);
    }
    if (lane == 0) { out[(size_t)n * 2] = a0 + b[0]; out[(size_t)n * 2 + 1] = a1 + b[1]; }
}

static inline int cdiv(long a, int b) { return (int)((a + b - 1) / b); }

extern "C" void kernel_launch(void* const* d_in, const int* in_sizes, int n_in,
                              void* d_out, int out_size)
{
    const float* x_snp  = (const float*)d_in[0];
    const float* x_gene = (const float*)d_in[1];
    const float* Wp_snp = (const float*)d_in[2];
    const float* bp_snp = (const float*)d_in[3];
    const float* Wp_gene= (const float*)d_in[4];
    const float* bp_gene= (const float*)d_in[5];
    const float* a_src  = (const float*)d_in[6];
    const float* a_dst  = (const float*)d_in[7];
    const float* Wk     = (const float*)d_in[8];
    const float* bk     = (const float*)d_in[9];
    const float* qvp    = (const float*)d_in[10];
    const float* ln_g   = (const float*)d_in[11];
    const float* ln_b   = (const float*)d_in[12];
    const float* fw     = (const float*)d_in[13];
    const float* Wfp    = (const float*)d_in[14];
    const float* bfp    = (const float*)d_in[15];
    const float* Wo1    = (const float*)d_in[16];
    const float* bo1    = (const float*)d_in[17];
    const float* Wo2    = (const float*)d_in[18];
    const float* bo2    = (const float*)d_in[19];
    const int* sg_s = (const int*)d_in[20];
    const int* sg_d = (const int*)d_in[21];
    const int* gs_s = (const int*)d_in[22];
    const int* gs_d = (const int*)d_in[23];
    const int* gg_s = (const int*)d_in[24];
    const int* gg_d = (const int*)d_in[25];
    const int E_sg = in_sizes[20], E_gs = in_sizes[22], E_gg = in_sizes[24];

    float *hs, *hg, *ssrc_sg, *sdst_gs, *sdst_sg, *ssrc_gs, *ssrc_gg, *sdst_gg;
    float *o_sg, *o_gs, *o_gg;
    float *out_s0, *out_g0, *sem, *attn, *buf1, *buf2;
    unsigned char* wimg;
    int *rp_sg, *rp_gs, *rp_gg, *deg, *cur, *bsum, *ss_sg, *ss_gs, *ss_gg;
    cudaGetSymbolAddress((void**)&hs, g_hs);
    cudaGetSymbolAddress((void**)&hg, g_hg);
    cudaGetSymbolAddress((void**)&ssrc_sg, g_ssrc_sg);
    cudaGetSymbolAddress((void**)&sdst_gs, g_sdst_gs);
    cudaGetSymbolAddress((void**)&sdst_sg, g_sdst_sg);
    cudaGetSymbolAddress((void**)&ssrc_gs, g_ssrc_gs);
    cudaGetSymbolAddress((void**)&ssrc_gg, g_ssrc_gg);
    cudaGetSymbolAddress((void**)&sdst_gg, g_sdst_gg);
    cudaGetSymbolAddress((void**)&o_sg, g_o_sg);
    cudaGetSymbolAddress((void**)&o_gs, g_o_gs);
    cudaGetSymbolAddress((void**)&o_gg, g_o_gg);
    cudaGetSymbolAddress((void**)&out_s0, g_out_s0);
    cudaGetSymbolAddress((void**)&out_g0, g_out_g0);
    cudaGetSymbolAddress((void**)&sem, g_sem);
    cudaGetSymbolAddress((void**)&attn, g_attn);
    cudaGetSymbolAddress((void**)&buf1, g_buf1);
    cudaGetSymbolAddress((void**)&buf2, g_buf2);
    cudaGetSymbolAddress((void**)&wimg, g_wimg);
    cudaGetSymbolAddress((void**)&rp_sg, g_rp_sg);
    cudaGetSymbolAddress((void**)&rp_gs, g_rp_gs);
    cudaGetSymbolAddress((void**)&rp_gg, g_rp_gg);
    cudaGetSymbolAddress((void**)&deg, g_deg);
    cudaGetSymbolAddress((void**)&cur, g_cur);
    cudaGetSymbolAddress((void**)&bsum, g_bsum);
    cudaGetSymbolAddress((void**)&ss_sg, g_ss_sg);
    cudaGetSymbolAddress((void**)&ss_gs, g_ss_gs);
    cudaGetSymbolAddress((void**)&ss_gg, g_ss_gg);

    cudaFuncSetAttribute(tgemm, cudaFuncAttributeMaxDynamicSharedMemorySize, TG_SMEM_TOTAL);

    // weight images in ONE launch: 0,1: Wp_snp l0/l1; 2,3: Wp_gene; 4,5: Wk; 6: Wfp; 7: Wo1
    wprep8<<<512, 256>>>(Wp_snp, Wp_snp + 16384, Wp_gene, Wp_gene + 16384,
                         Wk, Wk + 16384, Wfp, Wo1, wimg);

    // ---- build CSR (once; reused by both layers) ----
    struct { const int *src, *dst; int E, Nd; int *rp, *ss; } et[3] = {
        { sg_s, sg_d, E_sg, N_GENE, rp_sg, ss_sg },
        { gs_s, gs_d, E_gs, N_SNP,  rp_gs, ss_gs },
        { gg_s, gg_d, E_gg, N_GENE, rp_gg, ss_gg },
    };
    for (int t = 0; t < 3; t++) {
        int Nd = et[t].Nd, E = et[t].E;
        int nb = cdiv(Nd, 1024);
        zero_i<<<cdiv(Nd, 256), 256>>>(deg, Nd);
        hist_k<<<cdiv(E, 256), 256>>>(et[t].dst, E, deg);
        bsum_k<<<nb, 1024>>>(deg, Nd, bsum);
        bscan_k<<<1, 32>>>(bsum, nb);
        scan_k<<<nb, 1024>>>(deg, bsum, Nd, et[t].rp);
        zero_i<<<cdiv(Nd, 256), 256>>>(cur, Nd);
        scatter_k<<<cdiv(E, 256), 256>>>(et[t].src, et[t].dst, E, et[t].rp, cur, et[t].ss);
    }

    const int TS = cdiv(N_SNP, 128), TG = cdiv(N_GENE, 128), TA = cdiv(N_ALL, 128);

    for (int l = 0; l < 2; ++l) {
        const float* ins = l ? out_s0 : x_snp;
        const float* ing = l ? out_g0 : x_gene;

        tgemm<<<TS, 256, TG_SMEM_TOTAL>>>(ins, wimg + (0 + l) * WIMGSZ, bp_snp + l * 128,
                                          hs, nullptr, N_SNP, ACT_NONE);
        tgemm<<<TG, 256, TG_SMEM_TOTAL>>>(ing, wimg + (2 + l) * WIMGSZ, bp_gene + l * 128,
                                          hg, nullptr, N_GENE, ACT_NONE);

        scores2<<<cdiv((long)N_SNP * 8, 256), 256>>>(hs, N_SNP,
            a_src + (l * 3 + 0) * 128, a_dst + (l * 3 + 1) * 128, ssrc_sg, sdst_gs);
        scores4<<<cdiv((long)N_GENE * 8, 256), 256>>>(hg, N_GENE,
            a_dst + (l * 3 + 0) * 128, a_src + (l * 3 + 1) * 128,
            a_src + (l * 3 + 2) * 128, a_dst + (l * 3 + 2) * 128,
            sdst_sg, ssrc_gs, ssrc_gg, sdst_gg);

        agg_k<<<cdiv(N_GENE, 8), 256>>>(hs, ssrc_sg, sdst_sg, rp_sg, ss_sg, o_sg, N_GENE);
        agg_k<<<cdiv(N_SNP, 8), 256>>>(hg, ssrc_gs, sdst_gs, rp_gs, ss_gs, o_gs, N_SNP);
        agg_k<<<cdiv(N_GENE, 8), 256>>>(hg, ssrc_gg, sdst_gg, rp_gg, ss_gg, o_gg, N_GENE);

        fill_f4<<<1, 64>>>((float4*)sem, 0.f, 64);
        tgemm<<<TG, 256, TG_SMEM_TOTAL>>>(o_sg, wimg + (4 + l) * WIMGSZ, bk + l * 128,
                                          nullptr, sem, N_GENE, ACT_TANHSUM);
        tgemm<<<TG, 256, TG_SMEM_TOTAL>>>(o_gg, wimg + (4 + l) * WIMGSZ, bk + l * 128,
                                          nullptr, sem + 128, N_GENE, ACT_TANHSUM);
        sem_softmax<<<1, 64>>>(qvp + l * 128, sem, attn);

        if (l == 0) {
            combine_ln<<<cdiv((long)N_GENE * 32, 256), 256>>>(o_sg, o_gg, attn,
                ln_g, ln_b, nullptr, nullptr, out_g0, N_GENE);
            combine_ln<<<cdiv((long)N_SNP * 32, 256), 256>>>(o_gs, nullptr, nullptr,
                ln_g, ln_b, nullptr, nullptr, out_s0, N_SNP);
        } else {
            // fuse with layer-0 output directly into buf1
            combine_ln<<<cdiv((long)N_GENE * 32, 256), 256>>>(o_sg, o_gg, attn,
                ln_g + 128, ln_b + 128, out_g0, fw, buf1 + (size_t)N_SNP * 128, N_GENE);
            combine_ln<<<cdiv((long)N_SNP * 32, 256), 256>>>(o_gs, nullptr, nullptr,
                ln_g + 128, ln_b + 128, out_s0, fw, buf1, N_SNP);
        }
    }

    tgemm<<<TA, 256, TG_SMEM_TOTAL>>>(buf1, wimg + 6 * WIMGSZ, bfp, buf2, nullptr, N_ALL, ACT_RELU);
    tgemm<<<TA, 256, TG_SMEM_TOTAL>>>(buf2, wimg + 7 * WIMGSZ, bo1, buf1, nullptr, N_ALL, ACT_RELU);
    out_k<<<cdiv((long)N_ALL * 32, 256), 256>>>(buf1, Wo2, bo2, (float*)d_out, N_ALL);
}

// round 7
// speedup vs baseline: 2.0113x; 1.0335x over previous
#include <cuda_runtime.h>
#include <cuda_bf16.h>
#include <cstdint>

#define N_SNP  100000
#define N_GENE 20000
#define N_ALL  120000
#define HID    128
#define NEG    0.2f

#define ACT_NONE    0
#define ACT_RELU    1
#define ACT_TANHSUM 2

#define E_SG_MAX 500000
#define E_GS_MAX 500000
#define E_GG_MAX 150000

// CSR segment layout in g_dc: deg at [0,140000), cur at [140000,280000)
// seg bases: sg 0, gs 20000, gg 120000
#define SEG_GS 20000
#define SEG_GG 120000
#define NSEG_TOT 140000
// bsum blocks: sg 20, gs 98, gg 20 (block 1024)
#define NB_SG 20
#define NB_GS 98
#define NB_GG 20
#define NB_TOT 138

// semantic partials: TG blocks of 128 cols per metapath
#define TG_BLKS 157

// weight image geometry
#define WROW   272
#define WLO    34816
#define WIMGSZ 69632

// ---------------- device scratch ----------------
__device__ float    g_hs[N_SNP * HID];
__device__ float    g_hg[N_GENE * HID];
__device__ float    g_ssrc_sg[N_SNP * 8];
__device__ float    g_sdst_gs[N_SNP * 8];
__device__ float    g_sdst_sg[N_GENE * 8];
__device__ float    g_ssrc_gs[N_GENE * 8];
__device__ float    g_ssrc_gg[N_GENE * 8];
__device__ float    g_sdst_gg[N_GENE * 8];
__device__ float    g_o_sg[N_GENE * HID];
__device__ float    g_o_gs[N_SNP * HID];
__device__ float    g_o_gg[N_GENE * HID];
__device__ float    g_out_s0[N_SNP * HID];
__device__ float    g_out_g0[N_GENE * HID];
__device__ float    g_sempart[2 * TG_BLKS * HID];
__device__ float    g_attn[2];
__device__ float    g_buf1[N_ALL * HID];
__device__ float    g_buf2[N_ALL * HID];
__device__ __align__(16) unsigned char g_wimg[8 * WIMGSZ];
__device__ int g_rp_sg[N_GENE + 1];
__device__ int g_rp_gs[N_SNP + 1];
__device__ int g_rp_gg[N_GENE + 1];
__device__ int g_dc[2 * NSEG_TOT];
__device__ int g_bsum[NB_TOT + 4];
__device__ int g_ss_sg[E_SG_MAX];
__device__ int g_ss_gs[E_GS_MAX];
__device__ int g_ss_gg[E_GG_MAX];

__device__ __forceinline__ uint32_t pack_bf(float x, float y) {
    __nv_bfloat162 t = __floats2bfloat162_rn(x, y);
    return *(uint32_t*)&t;
}
__device__ __forceinline__ void mma_bf16(float4& c, uint32_t a0, uint32_t a1,
                                         uint32_t a2, uint32_t a3,
                                         uint32_t b0, uint32_t b1) {
    asm volatile("mma.sync.aligned.m16n8k16.row.col.f32.bf16.bf16.f32 "
                 "{%0,%1,%2,%3}, {%4,%5,%6,%7}, {%8,%9}, {%0,%1,%2,%3};"
                 : "+f"(c.x), "+f"(c.y), "+f"(c.z), "+f"(c.w)
                 : "r"(a0), "r"(a1), "r"(a2), "r"(a3), "r"(b0), "r"(b1));
}

// ---------------- CSR build (batched over 3 edge types) ----------------
__global__ void zero_all() {
    int i = blockIdx.x * 256 + threadIdx.x;
    if (i < 2 * NSEG_TOT) g_dc[i] = 0;
}
__global__ void hist3(const int* __restrict__ d1, const int* __restrict__ d2,
                      const int* __restrict__ d3, int E1, int E2, int E3) {
    int i = blockIdx.x * 256 + threadIdx.x;
    if (i < E1) atomicAdd(g_dc + d1[i], 1);
    else if (i < E1 + E2) atomicAdd(g_dc + SEG_GS + d2[i - E1], 1);
    else if (i < E1 + E2 + E3) atomicAdd(g_dc + SEG_GG + d3[i - E1 - E2], 1);
}
__device__ __forceinline__ void seg_map(int b, int& degoff, int& nd, int& boff, int& lb) {
    if (b < NB_SG)            { degoff = 0;      nd = N_GENE; boff = 0;             lb = b; }
    else if (b < NB_SG+NB_GS) { degoff = SEG_GS; nd = N_SNP;  boff = NB_SG;         lb = b - NB_SG; }
    else                      { degoff = SEG_GG; nd = N_GENE; boff = NB_SG + NB_GS; lb = b - NB_SG - NB_GS; }
}
__global__ void bsum3() {
    __shared__ int sw[32];
    int degoff, nd, boff, lb;
    seg_map(blockIdx.x, degoff, nd, boff, lb);
    int i = lb * 1024 + threadIdx.x;
    int v = (i < nd) ? g_dc[degoff + i] : 0;
#pragma unroll
    for (int o = 16; o; o >>= 1) v += __shfl_xor_sync(0xffffffffu, v, o);
    if ((threadIdx.x & 31) == 0) sw[threadIdx.x >> 5] = v;
    __syncthreads();
    if (threadIdx.x < 32) {
        int t = sw[threadIdx.x];
#pragma unroll
        for (int o = 16; o; o >>= 1) t += __shfl_xor_sync(0xffffffffu, t, o);
        if (threadIdx.x == 0) g_bsum[boff + lb] = t;
    }
}
__global__ void bscan3() {
    if (threadIdx.x == 0) {
        const int off[3] = {0, NB_SG, NB_SG + NB_GS};
        const int nb[3] = {NB_SG, NB_GS, NB_GG};
        for (int s = 0; s < 3; s++) {
            int c = 0;
            for (int i = 0; i < nb[s]; i++) {
                int v = g_bsum[off[s] + i];
                g_bsum[off[s] + i] = c;
                c += v;
            }
        }
    }
}
__global__ void scan3() {
    __shared__ int sm[1024];
    int degoff, nd, boff, lb;
    seg_map(blockIdx.x, degoff, nd, boff, lb);
    int* rp = (blockIdx.x < NB_SG) ? g_rp_sg
            : (blockIdx.x < NB_SG + NB_GS) ? g_rp_gs : g_rp_gg;
    int tid = threadIdx.x;
    int i = lb * 1024 + tid;
    int v = (i < nd) ? g_dc[degoff + i] : 0;
    sm[tid] = v;
    __syncthreads();
#pragma unroll
    for (int off = 1; off < 1024; off <<= 1) {
        int t = (tid >= off) ? sm[tid - off] : 0;
        __syncthreads();
        sm[tid] += t;
        __syncthreads();
    }
    int incl = sm[tid];
    int base = g_bsum[boff + lb];
    if (i < nd) rp[i] = base + incl - v;
    if (i == nd - 1) rp[nd] = base + incl;
}
__global__ void scatter3(const int* __restrict__ s1, const int* __restrict__ d1,
                         const int* __restrict__ s2, const int* __restrict__ d2,
                         const int* __restrict__ s3, const int* __restrict__ d3,
                         int E1, int E2, int E3) {
    int i = blockIdx.x * 256 + threadIdx.x;
    if (i < E1) {
        int d = d1[i];
        g_ss_sg[g_rp_sg[d] + atomicAdd(g_dc + NSEG_TOT + d, 1)] = s1[i];
    } else if (i < E1 + E2) {
        int e = i - E1, d = d2[e];
        g_ss_gs[g_rp_gs[d] + atomicAdd(g_dc + NSEG_TOT + SEG_GS + d, 1)] = s2[e];
    } else if (i < E1 + E2 + E3) {
        int e = i - E1 - E2, d = d3[e];
        g_ss_gg[g_rp_gg[d] + atomicAdd(g_dc + NSEG_TOT + SEG_GG + d, 1)] = s3[e];
    }
}

// ---------------- weight prep: all 8 matrices in one launch ----------------
__global__ void wprep8(const float* __restrict__ W0, const float* __restrict__ W1,
                       const float* __restrict__ W2, const float* __restrict__ W3,
                       const float* __restrict__ W4, const float* __restrict__ W5,
                       const float* __restrict__ W6, const float* __restrict__ W7,
                       unsigned char* __restrict__ imgbase) {
    int b = blockIdx.x >> 6;
    const float* W;
    if      (b == 0) W = W0; else if (b == 1) W = W1;
    else if (b == 2) W = W2; else if (b == 3) W = W3;
    else if (b == 4) W = W4; else if (b == 5) W = W5;
    else if (b == 6) W = W6; else              W = W7;
    unsigned char* img = imgbase + (size_t)b * WIMGSZ;
    int i = (blockIdx.x & 63) * 256 + threadIdx.x;
    int n = i >> 7, k = i & 127;
    float w = W[k * 128 + n];
    __nv_bfloat16 h = __float2bfloat16(w);
    __nv_bfloat16 l = __float2bfloat16(w - __bfloat162float(h));
    *(uint16_t*)(img + n * WROW + k * 2) = __bfloat16_as_ushort(h);
    *(uint16_t*)(img + WLO + n * WROW + k * 2) = __bfloat16_as_ushort(l);
}

// ---------------- tensor-core GEMM (mma.sync bf16 split) ----------------
#define TG_SMEM_TOTAL (WIMGSZ + 512)

__global__ void __launch_bounds__(256) tgemm(
    const float* __restrict__ A, const unsigned char* __restrict__ Bimg,
    const float* __restrict__ bias, float* __restrict__ C,
    float* __restrict__ colsum, int M, int act)
{
    extern __shared__ unsigned char smem[];
    float* scs = (float*)(smem + WIMGSZ);
    const int tid = threadIdx.x, wid = tid >> 5, lane = tid & 31;
    const int g = lane >> 2, tig = lane & 3;

    {
        const uint4* src = (const uint4*)Bimg;
        uint4* dst = (uint4*)smem;
#pragma unroll
        for (int i = 0; i < 17; i++) {
            int idx = tid + 256 * i;
            if (idx < WIMGSZ / 16) dst[idx] = src[idx];
        }
    }
    if (act == ACT_TANHSUM && tid < 128) scs[tid] = 0.f;
    __syncthreads();

    const int rowA = blockIdx.x * 128 + wid * 16 + g;
    const int rowB = rowA + 8;
    const bool vA = rowA < M, vB = rowB < M;

    float4 acc[16];
#pragma unroll
    for (int nt = 0; nt < 16; nt++) acc[nt] = make_float4(0.f, 0.f, 0.f, 0.f);

    const float* ArA = A + (size_t)rowA * 128;
    const float* ArB = A + (size_t)rowB * 128;

#pragma unroll
    for (int ks = 0; ks < 8; ks++) {
        const int k0 = ks * 16;
        float2 p00 = make_float2(0.f, 0.f), p01 = p00, p10 = p00, p11 = p00;
        if (vA) {
            p00 = *(const float2*)(ArA + k0 + 2 * tig);
            p01 = *(const float2*)(ArA + k0 + 2 * tig + 8);
        }
        if (vB) {
            p10 = *(const float2*)(ArB + k0 + 2 * tig);
            p11 = *(const float2*)(ArB + k0 + 2 * tig + 8);
        }
        uint32_t ah0 = pack_bf(p00.x, p00.y), ah1 = pack_bf(p10.x, p10.y);
        uint32_t ah2 = pack_bf(p01.x, p01.y), ah3 = pack_bf(p11.x, p11.y);
        __nv_bfloat162 h00 = *(__nv_bfloat162*)&ah0, h10 = *(__nv_bfloat162*)&ah1;
        __nv_bfloat162 h01 = *(__nv_bfloat162*)&ah2, h11 = *(__nv_bfloat162*)&ah3;
        uint32_t al0 = pack_bf(p00.x - __bfloat162float(h00.x), p00.y - __bfloat162float(h00.y));
        uint32_t al1 = pack_bf(p10.x - __bfloat162float(h10.x), p10.y - __bfloat162float(h10.y));
        uint32_t al2 = pack_bf(p01.x - __bfloat162float(h01.x), p01.y - __bfloat162float(h01.y));
        uint32_t al3 = pack_bf(p11.x - __bfloat162float(h11.x), p11.y - __bfloat162float(h11.y));

        const unsigned char* bh = smem + (size_t)g * WROW + (k0 + 2 * tig) * 2;
#pragma unroll
        for (int nt = 0; nt < 16; nt++) {
            uint32_t bh0 = *(const uint32_t*)(bh + nt * 8 * WROW);
            uint32_t bh1 = *(const uint32_t*)(bh + nt * 8 * WROW + 16);
            mma_bf16(acc[nt], ah0, ah1, ah2, ah3, bh0, bh1);
            mma_bf16(acc[nt], al0, al1, al2, al3, bh0, bh1);
            uint32_t bl0 = *(const uint32_t*)(bh + WLO + nt * 8 * WROW);
            uint32_t bl1 = *(const uint32_t*)(bh + WLO + nt * 8 * WROW + 16);
            mma_bf16(acc[nt], ah0, ah1, ah2, ah3, bl0, bl1);
        }
    }

    if (act == ACT_TANHSUM) {
#pragma unroll
        for (int nt = 0; nt < 16; nt++) {
            int col = nt * 8 + 2 * tig;
            float b0 = bias[col], b1 = bias[col + 1];
            float s0 = 0.f, s1 = 0.f;
            if (vA) { s0 += tanhf(acc[nt].x + b0); s1 += tanhf(acc[nt].y + b1); }
            if (vB) { s0 += tanhf(acc[nt].z + b0); s1 += tanhf(acc[nt].w + b1); }
            atomicAdd(scs + col, s0);
            atomicAdd(scs + col + 1, s1);
        }
        __syncthreads();
        if (tid < 128) colsum[blockIdx.x * 128 + tid] = scs[tid];  // per-block partial
    } else {
#pragma unroll
        for (int nt = 0; nt < 16; nt++) {
            int col = nt * 8 + 2 * tig;
            float b0 = bias[col], b1 = bias[col + 1];
            float2 oA = make_float2(acc[nt].x + b0, acc[nt].y + b1);
            float2 oB = make_float2(acc[nt].z + b0, acc[nt].w + b1);
            if (act == ACT_RELU) {
                oA.x = fmaxf(oA.x, 0.f); oA.y = fmaxf(oA.y, 0.f);
                oB.x = fmaxf(oB.x, 0.f); oB.y = fmaxf(oB.y, 0.f);
            }
            if (vA) *(float2*)(C + (size_t)rowA * 128 + col) = oA;
            if (vB) *(float2*)(C + (size_t)rowB * 128 + col) = oB;
        }
    }
}

// ---------------- per-node attention score dots (snp + gene fused) ----------------
__device__ __forceinline__ float dot128(const float4* hp, const float* a, int hd) {
    const float4* p = (const float4*)(a + hd * 16);
    float d = 0;
#pragma unroll
    for (int i = 0; i < 4; i++) {
        float4 hv = hp[i], av = p[i];
        d += hv.x * av.x + hv.y * av.y + hv.z * av.z + hv.w * av.w;
    }
    return d;
}
__global__ void scores_all(int l, const float* __restrict__ a_src,
                           const float* __restrict__ a_dst)
{
    int idx = blockIdx.x * blockDim.x + threadIdx.x;
    const int SN = N_SNP * 8;
    if (idx < SN) {
        int n = idx >> 3, hd = idx & 7;
        const float4* hp = (const float4*)(g_hs + (size_t)n * 128 + hd * 16);
        g_ssrc_sg[idx] = dot128(hp, a_src + (l * 3 + 0) * 128, hd);
        g_sdst_gs[idx] = dot128(hp, a_dst + (l * 3 + 1) * 128, hd);
    } else if (idx < SN + N_GENE * 8) {
        int j = idx - SN;
        int n = j >> 3, hd = j & 7;
        const float4* hp = (const float4*)(g_hg + (size_t)n * 128 + hd * 16);
        g_sdst_sg[j] = dot128(hp, a_dst + (l * 3 + 0) * 128, hd);
        g_ssrc_gs[j] = dot128(hp, a_src + (l * 3 + 1) * 128, hd);
        g_ssrc_gg[j] = dot128(hp, a_src + (l * 3 + 2) * 128, hd);
        g_sdst_gg[j] = dot128(hp, a_dst + (l * 3 + 2) * 128, hd);
    }
}

// ---------------- CSR aggregation: all 3 edge types, warp per dst, 4-edge unroll ----
__global__ void __launch_bounds__(256) agg3()
{
    int w = blockIdx.x * 8 + (threadIdx.x >> 5);
    const float *hsrc, *ssrc, *sdst;
    const int *rp, *ss;
    float* out;
    int d;
    if (w < N_GENE) {
        d = w; hsrc = g_hs; ssrc = g_ssrc_sg; sdst = g_sdst_sg;
        rp = g_rp_sg; ss = g_ss_sg; out = g_o_sg;
    } else if (w < N_GENE + N_SNP) {
        d = w - N_GENE; hsrc = g_hg; ssrc = g_ssrc_gs; sdst = g_sdst_gs;
        rp = g_rp_gs; ss = g_ss_gs; out = g_o_gs;
    } else if (w < 2 * N_GENE + N_SNP) {
        d = w - (N_GENE + N_SNP); hsrc = g_hg; ssrc = g_ssrc_gg; sdst = g_sdst_gg;
        rp = g_rp_gg; ss = g_ss_gg; out = g_o_gg;
    } else return;

    int lane = threadIdx.x & 31, hd = lane >> 2;
    float sdh = __ldg(sdst + d * 8 + hd);
    int beg = __ldg(rp + d), end = __ldg(rp + d + 1);

    float4 acc0 = make_float4(0.f, 0.f, 0.f, 0.f);
    float4 acc1 = make_float4(0.f, 0.f, 0.f, 0.f);
    float se0 = 0.f, se1 = 0.f;

    int i = beg;
    for (; i + 4 <= end; i += 4) {
        int s0 = __ldg(ss + i), s1 = __ldg(ss + i + 1);
        int s2 = __ldg(ss + i + 2), s3 = __ldg(ss + i + 3);
        float a0 = __ldg(ssrc + s0 * 8 + hd) + sdh;
        float a1 = __ldg(ssrc + s1 * 8 + hd) + sdh;
        float a2 = __ldg(ssrc + s2 * 8 + hd) + sdh;
        float a3 = __ldg(ssrc + s3 * 8 + hd) + sdh;
        float4 h0 = *((const float4*)(hsrc + (size_t)s0 * 128) + lane);
        float4 h1 = *((const float4*)(hsrc + (size_t)s1 * 128) + lane);
        float4 h2 = *((const float4*)(hsrc + (size_t)s2 * 128) + lane);
        float4 h3 = *((const float4*)(hsrc + (size_t)s3 * 128) + lane);
        a0 = a0 > 0.f ? a0 : NEG * a0;
        a1 = a1 > 0.f ? a1 : NEG * a1;
        a2 = a2 > 0.f ? a2 : NEG * a2;
        a3 = a3 > 0.f ? a3 : NEG * a3;
        float e0 = __expf(a0), e1 = __expf(a1), e2 = __expf(a2), e3 = __expf(a3);
        acc0.x = fmaf(e0, h0.x, acc0.x); acc0.y = fmaf(e0, h0.y, acc0.y);
        acc0.z = fmaf(e0, h0.z, acc0.z); acc0.w = fmaf(e0, h0.w, acc0.w);
        acc1.x = fmaf(e1, h1.x, acc1.x); acc1.y = fmaf(e1, h1.y, acc1.y);
        acc1.z = fmaf(e1, h1.z, acc1.z); acc1.w = fmaf(e1, h1.w, acc1.w);
        acc0.x = fmaf(e2, h2.x, acc0.x); acc0.y = fmaf(e2, h2.y, acc0.y);
        acc0.z = fmaf(e2, h2.z, acc0.z); acc0.w = fmaf(e2, h2.w, acc0.w);
        acc1.x = fmaf(e3, h3.x, acc1.x); acc1.y = fmaf(e3, h3.y, acc1.y);
        acc1.z = fmaf(e3, h3.z, acc1.z); acc1.w = fmaf(e3, h3.w, acc1.w);
        se0 += e0 + e2; se1 += e1 + e3;
    }
    for (; i < end; i++) {
        int s0 = __ldg(ss + i);
        float a0 = __ldg(ssrc + s0 * 8 + hd) + sdh;
        float4 h0 = *((const float4*)(hsrc + (size_t)s0 * 128) + lane);
        a0 = a0 > 0.f ? a0 : NEG * a0;
        float e0 = __expf(a0);
        acc0.x = fmaf(e0, h0.x, acc0.x); acc0.y = fmaf(e0, h0.y, acc0.y);
        acc0.z = fmaf(e0, h0.z, acc0.z); acc0.w = fmaf(e0, h0.w, acc0.w);
        se0 += e0;
    }
    float inv = 1.f / (se0 + se1 + 1e-16f);
    float4 r;
    r.x = fmaxf((acc0.x + acc1.x) * inv, 0.f);
    r.y = fmaxf((acc0.y + acc1.y) * inv, 0.f);
    r.z = fmaxf((acc0.z + acc1.z) * inv, 0.f);
    r.w = fmaxf((acc0.w + acc1.w) * inv, 0.f);
    *((float4*)(out + (size_t)d * 128) + lane) = r;
}

// ---------------- semantic softmax: reduce per-block partials + softmax ----------------
__global__ void sem_softmax2(const float* __restrict__ q)
{
    // 256 threads: t = m*128 + col
    __shared__ float sw[8];
    int m = threadIdx.x >> 7, col = threadIdx.x & 127;
    float s = 0.f;
    const float* part = g_sempart + (size_t)m * TG_BLKS * 128 + col;
    for (int b = 0; b < TG_BLKS; b++) s += part[b * 128];
    float v = q[col] * (s / 20000.f);
    int lane = threadIdx.x & 31;
#pragma unroll
    for (int o = 16; o; o >>= 1) v += __shfl_xor_sync(0xffffffffu, v, o);
    if (lane == 0) sw[threadIdx.x >> 5] = v;
    __syncthreads();
    if (threadIdx.x == 0) {
        float s0 = sw[0] + sw[1] + sw[2] + sw[3];
        float s1 = sw[4] + sw[5] + sw[6] + sw[7];
        float mx = fmaxf(s0, s1);
        float e0 = __expf(s0 - mx), e1 = __expf(s1 - mx);
        float inv = 1.f / (e0 + e1);
        g_attn[0] = e0 * inv; g_attn[1] = e1 * inv;
    }
}

// ---------------- combine + LayerNorm (+ layer fusion), gene + snp fused ----------------
__global__ void __launch_bounds__(256) combine_all(
    const float* __restrict__ ln_gp, const float* __restrict__ ln_bp,
    const float* __restrict__ fw, int layer1)
{
    int idx = blockIdx.x * blockDim.x + threadIdx.x;
    int w = idx >> 5, lane = idx & 31;
    if (w >= N_GENE + N_SNP) return;
    const float *o1, *o2, *prev;
    float* out;
    int n;
    if (w < N_GENE) {
        n = w; o1 = g_o_sg; o2 = g_o_gg;
        prev = layer1 ? g_out_g0 : nullptr;
        out = layer1 ? (g_buf1 + (size_t)N_SNP * 128) : g_out_g0;
    } else {
        n = w - N_GENE; o1 = g_o_gs; o2 = nullptr;
        prev = layer1 ? g_out_s0 : nullptr;
        out = layer1 ? g_buf1 : g_out_s0;
    }
    float4 v = *((const float4*)(o1 + (size_t)n * 128) + lane);
    if (o2) {
        float a0 = g_attn[0], a1 = g_attn[1];
        float4 u = *((const float4*)(o2 + (size_t)n * 128) + lane);
        v.x = a0 * v.x + a1 * u.x;
        v.y = a0 * v.y + a1 * u.y;
        v.z = a0 * v.z + a1 * u.z;
        v.w = a0 * v.w + a1 * u.w;
    }
    float s = v.x + v.y + v.z + v.w;
#pragma unroll
    for (int o = 16; o; o >>= 1) s += __shfl_xor_sync(0xffffffffu, s, o);
    float mu = s * (1.f / 128.f);
    float dx = v.x - mu, dy = v.y - mu, dz = v.z - mu, dw = v.w - mu;
    float qv = dx * dx + dy * dy + dz * dz + dw * dw;
#pragma unroll
    for (int o = 16; o; o >>= 1) qv += __shfl_xor_sync(0xffffffffu, qv, o);
    float rs = rsqrtf(qv * (1.f / 128.f) + 1e-5f);
    float4 g4 = *((const float4*)ln_gp + lane);
    float4 b4 = *((const float4*)ln_bp + lane);
    float4 r;
    r.x = dx * rs * g4.x + b4.x;
    r.y = dy * rs * g4.y + b4.y;
    r.z = dz * rs * g4.z + b4.z;
    r.w = dw * rs * g4.w + b4.w;
    if (prev) {
        float w0 = fw[0], w1 = fw[1];
        float inv = 1.f / (w0 + w1);
        float4 p = *((const float4*)(prev + (size_t)n * 128) + lane);
        r.x = (w0 * p.x + w1 * r.x) * inv;
        r.y = (w0 * p.y + w1 * r.y) * inv;
        r.z = (w0 * p.z + w1 * r.z) * inv;
        r.w = (w0 * p.w + w1 * r.w) * inv;
    }
    *((float4*)(out + (size_t)n * 128) + lane) = r;
}

// ---------------- final 128->2 projection ----------------
__global__ void out_k(const float* __restrict__ A, const float* __restrict__ W,
                      const float* __restrict__ b, float* __restrict__ out, int M)
{
    int idx = blockIdx.x * blockDim.x + threadIdx.x;
    int n = idx >> 5, lane = idx & 31;
    if (n >= M) return;
    const float* ar = A + (size_t)n * 128;
    float a0 = 0, a1 = 0;
#pragma unroll
    for (int i = 0; i < 4; i++) {
        float v = ar[lane + 32 * i];
        a0 += v * W[(lane + 32 * i) * 2];
        a1 += v * W[(lane + 32 * i) * 2 + 1];
    }
#pragma unroll
    for (int o = 16; o; o >>= 1) {
        a0 += __shfl_xor_sync(0xffffffffu, a0, o);
        a1 += __shfl_xor_sync(0xffffffffu, a1, o);
    }
    if (lane == 0) { out[(size_t)n * 2] = a0 + b[0]; out[(size_t)n * 2 + 1] = a1 + b[1]; }
}

static inline int cdiv(long a, int b) { return (int)((a + b - 1) / b); }

extern "C" void kernel_launch(void* const* d_in, const int* in_sizes, int n_in,
                              void* d_out, int out_size)
{
    const float* x_snp  = (const float*)d_in[0];
    const float* x_gene = (const float*)d_in[1];
    const float* Wp_snp = (const float*)d_in[2];
    const float* bp_snp = (const float*)d_in[3];
    const float* Wp_gene= (const float*)d_in[4];
    const float* bp_gene= (const float*)d_in[5];
    const float* a_src  = (const float*)d_in[6];
    const float* a_dst  = (const float*)d_in[7];
    const float* Wk     = (const float*)d_in[8];
    const float* bk     = (const float*)d_in[9];
    const float* qvp    = (const float*)d_in[10];
    const float* ln_g   = (const float*)d_in[11];
    const float* ln_b   = (const float*)d_in[12];
    const float* fw     = (const float*)d_in[13];
    const float* Wfp    = (const float*)d_in[14];
    const float* bfp    = (const float*)d_in[15];
    const float* Wo1    = (const float*)d_in[16];
    const float* bo1    = (const float*)d_in[17];
    const float* Wo2    = (const float*)d_in[18];
    const float* bo2    = (const float*)d_in[19];
    const int* sg_s = (const int*)d_in[20];
    const int* sg_d = (const int*)d_in[21];
    const int* gs_s = (const int*)d_in[22];
    const int* gs_d = (const int*)d_in[23];
    const int* gg_s = (const int*)d_in[24];
    const int* gg_d = (const int*)d_in[25];
    const int E_sg = in_sizes[20], E_gs = in_sizes[22], E_gg = in_sizes[24];

    float *hs, *hg, *o_sg, *o_gg, *out_s0, *out_g0, *sempart, *buf1, *buf2;
    unsigned char* wimg;
    cudaGetSymbolAddress((void**)&hs, g_hs);
    cudaGetSymbolAddress((void**)&hg, g_hg);
    cudaGetSymbolAddress((void**)&o_sg, g_o_sg);
    cudaGetSymbolAddress((void**)&o_gg, g_o_gg);
    cudaGetSymbolAddress((void**)&out_s0, g_out_s0);
    cudaGetSymbolAddress((void**)&out_g0, g_out_g0);
    cudaGetSymbolAddress((void**)&sempart, g_sempart);
    cudaGetSymbolAddress((void**)&buf1, g_buf1);
    cudaGetSymbolAddress((void**)&buf2, g_buf2);
    cudaGetSymbolAddress((void**)&wimg, g_wimg);

    cudaFuncSetAttribute(tgemm, cudaFuncAttributeMaxDynamicSharedMemorySize, TG_SMEM_TOTAL);

    // weight images: 0,1: Wp_snp l0/l1; 2,3: Wp_gene; 4,5: Wk; 6: Wfp; 7: Wo1
    wprep8<<<512, 256>>>(Wp_snp, Wp_snp + 16384, Wp_gene, Wp_gene + 16384,
                         Wk, Wk + 16384, Wfp, Wo1, wimg);

    // ---- CSR build (6 launches, all 3 edge types batched) ----
    const int E_tot = E_sg + E_gs + E_gg;
    zero_all<<<cdiv(2 * NSEG_TOT, 256), 256>>>();
    hist3<<<cdiv(E_tot, 256), 256>>>(sg_d, gs_d, gg_d, E_sg, E_gs, E_gg);
    bsum3<<<NB_TOT, 1024>>>();
    bscan3<<<1, 32>>>();
    scan3<<<NB_TOT, 1024>>>();
    scatter3<<<cdiv(E_tot, 256), 256>>>(sg_s, sg_d, gs_s, gs_d, gg_s, gg_d,
                                        E_sg, E_gs, E_gg);

    const int TS = cdiv(N_SNP, 128), TG = cdiv(N_GENE, 128), TA = cdiv(N_ALL, 128);

    for (int l = 0; l < 2; ++l) {
        const float* ins = l ? out_s0 : x_snp;
        const float* ing = l ? out_g0 : x_gene;

        tgemm<<<TS, 256, TG_SMEM_TOTAL>>>(ins, wimg + (0 + l) * WIMGSZ, bp_snp + l * 128,
                                          hs, nullptr, N_SNP, ACT_NONE);
        tgemm<<<TG, 256, TG_SMEM_TOTAL>>>(ing, wimg + (2 + l) * WIMGSZ, bp_gene + l * 128,
                                          hg, nullptr, N_GENE, ACT_NONE);

        scores_all<<<cdiv((long)(N_SNP + N_GENE) * 8, 256), 256>>>(l, a_src, a_dst);

        agg3<<<cdiv(2 * N_GENE + N_SNP, 8), 256>>>();

        tgemm<<<TG, 256, TG_SMEM_TOTAL>>>(o_sg, wimg + (4 + l) * WIMGSZ, bk + l * 128,
                                          nullptr, sempart, N_GENE, ACT_TANHSUM);
        tgemm<<<TG, 256, TG_SMEM_TOTAL>>>(o_gg, wimg + (4 + l) * WIMGSZ, bk + l * 128,
                                          nullptr, sempart + TG_BLKS * 128, N_GENE, ACT_TANHSUM);
        sem_softmax2<<<1, 256>>>(qvp + l * 128);

        combine_all<<<cdiv((long)(N_GENE + N_SNP) * 32, 256), 256>>>(
            ln_g + l * 128, ln_b + l * 128, fw, l);
    }

    tgemm<<<TA, 256, TG_SMEM_TOTAL>>>(buf1, wimg + 6 * WIMGSZ, bfp, buf2, nullptr, N_ALL, ACT_RELU);
    tgemm<<<TA, 256, TG_SMEM_TOTAL>>>(buf2, wimg + 7 * WIMGSZ, bo1, buf1, nullptr, N_ALL, ACT_RELU);
    out_k<<<cdiv((long)N_ALL * 32, 256), 256>>>(buf1, Wo2, bo2, (float*)d_out, N_ALL);
}

// round 8
// speedup vs baseline: 2.2593x; 1.1233x over previous
#include <cuda_runtime.h>
#include <cuda_bf16.h>
#include <cuda_fp16.h>
#include <cstdint>

#define N_SNP  100000
#define N_GENE 20000
#define N_ALL  120000
#define HID    128
#define NEG    0.2f

#define ACT_RELU    1
#define ACT_TANHSUM 2
#define ACT_H       3
#define ACT_OUT     4

#define E_SG_MAX 500000
#define E_GS_MAX 500000
#define E_GG_MAX 150000

// CSR segment layout in g_dc: deg at [0,140000), cur at [140000,280000)
#define SEG_GS 20000
#define SEG_GG 120000
#define NSEG_TOT 140000
#define NB_SG 20
#define NB_GS 98
#define NB_GG 20
#define NB_TOT 138

#define TG_BLKS 157

// weight image geometry
#define WROW   272
#define WLO    34816
#define WIMGSZ 69632

// ---------------- device scratch ----------------
__device__ __half   g_hsh[N_SNP * HID];
__device__ __half   g_hgh[N_GENE * HID];
__device__ float    g_ssrc_sg[N_SNP * 8];
__device__ float    g_sdst_gs[N_SNP * 8];
__device__ float    g_sdst_sg[N_GENE * 8];
__device__ float    g_ssrc_gs[N_GENE * 8];
__device__ float    g_ssrc_gg[N_GENE * 8];
__device__ float    g_sdst_gg[N_GENE * 8];
__device__ float    g_o_sg[N_GENE * HID];
__device__ float    g_o_gs[N_SNP * HID];
__device__ float    g_o_gg[N_GENE * HID];
__device__ float    g_out_s0[N_SNP * HID];
__device__ float    g_out_g0[N_GENE * HID];
__device__ float    g_sempart[2 * TG_BLKS * HID];
__device__ float    g_attn[2];
__device__ float    g_buf1[N_ALL * HID];
__device__ float    g_buf2[N_ALL * HID];
__device__ __align__(16) unsigned char g_wimg[8 * WIMGSZ];
__device__ int g_rp_sg[N_GENE + 1];
__device__ int g_rp_gs[N_SNP + 1];
__device__ int g_rp_gg[N_GENE + 1];
__device__ int g_dc[2 * NSEG_TOT];
__device__ int g_bsum[NB_TOT + 4];
__device__ int g_ss_sg[E_SG_MAX];
__device__ int g_ss_gs[E_GS_MAX];
__device__ int g_ss_gg[E_GG_MAX];

__device__ __forceinline__ uint32_t pack_bf(float x, float y) {
    __nv_bfloat162 t = __floats2bfloat162_rn(x, y);
    return *(uint32_t*)&t;
}
__device__ __forceinline__ void mma_bf16(float4& c, uint32_t a0, uint32_t a1,
                                         uint32_t a2, uint32_t a3,
                                         uint32_t b0, uint32_t b1) {
    asm volatile("mma.sync.aligned.m16n8k16.row.col.f32.bf16.bf16.f32 "
                 "{%0,%1,%2,%3}, {%4,%5,%6,%7}, {%8,%9}, {%0,%1,%2,%3};"
                 : "+f"(c.x), "+f"(c.y), "+f"(c.z), "+f"(c.w)
                 : "r"(a0), "r"(a1), "r"(a2), "r"(a3), "r"(b0), "r"(b1));
}

// ---------------- CSR build (batched over 3 edge types) ----------------
__global__ void zero_all() {
    int i = blockIdx.x * 256 + threadIdx.x;
    if (i < 2 * NSEG_TOT) g_dc[i] = 0;
}
__global__ void hist3(const int* __restrict__ d1, const int* __restrict__ d2,
                      const int* __restrict__ d3, int E1, int E2, int E3) {
    int i = blockIdx.x * 256 + threadIdx.x;
    if (i < E1) atomicAdd(g_dc + d1[i], 1);
    else if (i < E1 + E2) atomicAdd(g_dc + SEG_GS + d2[i - E1], 1);
    else if (i < E1 + E2 + E3) atomicAdd(g_dc + SEG_GG + d3[i - E1 - E2], 1);
}
__device__ __forceinline__ void seg_map(int b, int& degoff, int& nd, int& boff, int& lb) {
    if (b < NB_SG)            { degoff = 0;      nd = N_GENE; boff = 0;             lb = b; }
    else if (b < NB_SG+NB_GS) { degoff = SEG_GS; nd = N_SNP;  boff = NB_SG;         lb = b - NB_SG; }
    else                      { degoff = SEG_GG; nd = N_GENE; boff = NB_SG + NB_GS; lb = b - NB_SG - NB_GG - NB_GS + NB_GG; }
}
__global__ void bsum3() {
    __shared__ int sw[32];
    int degoff, nd, boff, lb;
    seg_map(blockIdx.x, degoff, nd, boff, lb);
    int i = lb * 1024 + threadIdx.x;
    int v = (i < nd) ? g_dc[degoff + i] : 0;
#pragma unroll
    for (int o = 16; o; o >>= 1) v += __shfl_xor_sync(0xffffffffu, v, o);
    if ((threadIdx.x & 31) == 0) sw[threadIdx.x >> 5] = v;
    __syncthreads();
    if (threadIdx.x < 32) {
        int t = sw[threadIdx.x];
#pragma unroll
        for (int o = 16; o; o >>= 1) t += __shfl_xor_sync(0xffffffffu, t, o);
        if (threadIdx.x == 0) g_bsum[boff + lb] = t;
    }
}
__global__ void bscan3() {
    if (threadIdx.x == 0) {
        const int off[3] = {0, NB_SG, NB_SG + NB_GS};
        const int nb[3] = {NB_SG, NB_GS, NB_GG};
        for (int s = 0; s < 3; s++) {
            int c = 0;
            for (int i = 0; i < nb[s]; i++) {
                int v = g_bsum[off[s] + i];
                g_bsum[off[s] + i] = c;
                c += v;
            }
        }
    }
}
__global__ void scan3() {
    __shared__ int sm[1024];
    int degoff, nd, boff, lb;
    seg_map(blockIdx.x, degoff, nd, boff, lb);
    int* rp = (blockIdx.x < NB_SG) ? g_rp_sg
            : (blockIdx.x < NB_SG + NB_GS) ? g_rp_gs : g_rp_gg;
    int tid = threadIdx.x;
    int i = lb * 1024 + tid;
    int v = (i < nd) ? g_dc[degoff + i] : 0;
    sm[tid] = v;
    __syncthreads();
#pragma unroll
    for (int off = 1; off < 1024; off <<= 1) {
        int t = (tid >= off) ? sm[tid - off] : 0;
        __syncthreads();
        sm[tid] += t;
        __syncthreads();
    }
    int incl = sm[tid];
    int base = g_bsum[boff + lb];
    if (i < nd) rp[i] = base + incl - v;
    if (i == nd - 1) rp[nd] = base + incl;
}
__global__ void scatter3(const int* __restrict__ s1, const int* __restrict__ d1,
                         const int* __restrict__ s2, const int* __restrict__ d2,
                         const int* __restrict__ s3, const int* __restrict__ d3,
                         int E1, int E2, int E3) {
    int i = blockIdx.x * 256 + threadIdx.x;
    if (i < E1) {
        int d = d1[i];
        g_ss_sg[g_rp_sg[d] + atomicAdd(g_dc + NSEG_TOT + d, 1)] = s1[i];
    } else if (i < E1 + E2) {
        int e = i - E1, d = d2[e];
        g_ss_gs[g_rp_gs[d] + atomicAdd(g_dc + NSEG_TOT + SEG_GS + d, 1)] = s2[e];
    } else if (i < E1 + E2 + E3) {
        int e = i - E1 - E2, d = d3[e];
        g_ss_gg[g_rp_gg[d] + atomicAdd(g_dc + NSEG_TOT + SEG_GG + d, 1)] = s3[e];
    }
}

// ---------------- weight prep: all 8 matrices in one launch ----------------
__global__ void wprep8(const float* __restrict__ W0, const float* __restrict__ W1,
                       const float* __restrict__ W2, const float* __restrict__ W3,
                       const float* __restrict__ W4, const float* __restrict__ W5,
                       const float* __restrict__ W6, const float* __restrict__ W7,
                       unsigned char* __restrict__ imgbase) {
    int b = blockIdx.x >> 6;
    const float* W;
    if      (b == 0) W = W0; else if (b == 1) W = W1;
    else if (b == 2) W = W2; else if (b == 3) W = W3;
    else if (b == 4) W = W4; else if (b == 5) W = W5;
    else if (b == 6) W = W6; else              W = W7;
    unsigned char* img = imgbase + (size_t)b * WIMGSZ;
    int i = (blockIdx.x & 63) * 256 + threadIdx.x;
    int n = i >> 7, k = i & 127;
    float w = W[k * 128 + n];
    __nv_bfloat16 h = __float2bfloat16(w);
    __nv_bfloat16 l = __float2bfloat16(w - __bfloat162float(h));
    *(uint16_t*)(img + n * WROW + k * 2) = __bfloat16_as_ushort(h);
    *(uint16_t*)(img + WLO + n * WROW + k * 2) = __bfloat16_as_ushort(l);
}

// ---------------- tensor-core GEMM (mma.sync bf16 split) ----------------
// act modes:
//  ACT_RELU    : C = relu(A@W+b)
//  ACT_TANHSUM : per-block colsum partials of tanh(A@W+b); A2 = second input
//                (blocks >= nhalf use A2), colsum index = blockIdx.x
//  ACT_H       : Ch = fp16(A@W+b); scores vs up to 4 attention vectors -> sb0..3
//  ACT_OUT     : d_out[row,0:2] = relu(A@W+b) @ W2 + b2
#define TG_SMEM_TOTAL (WIMGSZ + 512)

__global__ void __launch_bounds__(256) tgemm(
    const float* __restrict__ A, const float* __restrict__ A2,
    const unsigned char* __restrict__ Bimg,
    const float* __restrict__ bias, float* __restrict__ C,
    __half* __restrict__ Ch,
    const float* __restrict__ v0, const float* __restrict__ v1,
    const float* __restrict__ v2, const float* __restrict__ v3,
    float* __restrict__ sb0, float* __restrict__ sb1,
    float* __restrict__ sb2, float* __restrict__ sb3,
    const float* __restrict__ W2, const float* __restrict__ b2,
    float* __restrict__ outp,
    int M, int nhalf, int act)
{
    extern __shared__ unsigned char smem[];
    float* scs = (float*)(smem + WIMGSZ);
    const int tid = threadIdx.x, wid = tid >> 5, lane = tid & 31;
    const int g = lane >> 2, tig = lane & 3;

    int blk = blockIdx.x;
    if (act == ACT_TANHSUM && blk >= nhalf) { A = A2; blk -= nhalf; }

    {
        const uint4* src = (const uint4*)Bimg;
        uint4* dst = (uint4*)smem;
#pragma unroll
        for (int i = 0; i < 17; i++) {
            int idx = tid + 256 * i;
            if (idx < WIMGSZ / 16) dst[idx] = src[idx];
        }
    }
    if (act == ACT_TANHSUM && tid < 128) scs[tid] = 0.f;
    __syncthreads();

    const int rowA = blk * 128 + wid * 16 + g;
    const int rowB = rowA + 8;
    const bool vA = rowA < M, vB = rowB < M;

    float4 acc[16];
#pragma unroll
    for (int nt = 0; nt < 16; nt++) acc[nt] = make_float4(0.f, 0.f, 0.f, 0.f);

    const float* ArA = A + (size_t)rowA * 128;
    const float* ArB = A + (size_t)rowB * 128;

#pragma unroll
    for (int ks = 0; ks < 8; ks++) {
        const int k0 = ks * 16;
        float2 p00 = make_float2(0.f, 0.f), p01 = p00, p10 = p00, p11 = p00;
        if (vA) {
            p00 = *(const float2*)(ArA + k0 + 2 * tig);
            p01 = *(const float2*)(ArA + k0 + 2 * tig + 8);
        }
        if (vB) {
            p10 = *(const float2*)(ArB + k0 + 2 * tig);
            p11 = *(const float2*)(ArB + k0 + 2 * tig + 8);
        }
        uint32_t ah0 = pack_bf(p00.x, p00.y), ah1 = pack_bf(p10.x, p10.y);
        uint32_t ah2 = pack_bf(p01.x, p01.y), ah3 = pack_bf(p11.x, p11.y);
        __nv_bfloat162 h00 = *(__nv_bfloat162*)&ah0, h10 = *(__nv_bfloat162*)&ah1;
        __nv_bfloat162 h01 = *(__nv_bfloat162*)&ah2, h11 = *(__nv_bfloat162*)&ah3;
        uint32_t al0 = pack_bf(p00.x - __bfloat162float(h00.x), p00.y - __bfloat162float(h00.y));
        uint32_t al1 = pack_bf(p10.x - __bfloat162float(h10.x), p10.y - __bfloat162float(h10.y));
        uint32_t al2 = pack_bf(p01.x - __bfloat162float(h01.x), p01.y - __bfloat162float(h01.y));
        uint32_t al3 = pack_bf(p11.x - __bfloat162float(h11.x), p11.y - __bfloat162float(h11.y));

        const unsigned char* bh = smem + (size_t)g * WROW + (k0 + 2 * tig) * 2;
#pragma unroll
        for (int nt = 0; nt < 16; nt++) {
            uint32_t bh0 = *(const uint32_t*)(bh + nt * 8 * WROW);
            uint32_t bh1 = *(const uint32_t*)(bh + nt * 8 * WROW + 16);
            mma_bf16(acc[nt], ah0, ah1, ah2, ah3, bh0, bh1);
            mma_bf16(acc[nt], al0, al1, al2, al3, bh0, bh1);
            uint32_t bl0 = *(const uint32_t*)(bh + WLO + nt * 8 * WROW);
            uint32_t bl1 = *(const uint32_t*)(bh + WLO + nt * 8 * WROW + 16);
            mma_bf16(acc[nt], ah0, ah1, ah2, ah3, bl0, bl1);
        }
    }

    // add bias
#pragma unroll
    for (int nt = 0; nt < 16; nt++) {
        int col = nt * 8 + 2 * tig;
        float b0 = bias[col], b1 = bias[col + 1];
        acc[nt].x += b0; acc[nt].y += b1;
        acc[nt].z += b0; acc[nt].w += b1;
    }

    if (act == ACT_TANHSUM) {
#pragma unroll
        for (int nt = 0; nt < 16; nt++) {
            int col = nt * 8 + 2 * tig;
            float s0 = 0.f, s1 = 0.f;
            if (vA) { s0 += tanhf(acc[nt].x); s1 += tanhf(acc[nt].y); }
            if (vB) { s0 += tanhf(acc[nt].z); s1 += tanhf(acc[nt].w); }
            atomicAdd(scs + col, s0);
            atomicAdd(scs + col + 1, s1);
        }
        __syncthreads();
        if (tid < 128) C[blockIdx.x * 128 + tid] = scs[tid];
    } else if (act == ACT_H) {
        // fp16 h rows
#pragma unroll
        for (int nt = 0; nt < 16; nt++) {
            int col = nt * 8 + 2 * tig;
            if (vA) *((__half2*)(Ch + (size_t)rowA * 128 + col)) = __floats2half2_rn(acc[nt].x, acc[nt].y);
            if (vB) *((__half2*)(Ch + (size_t)rowB * 128 + col)) = __floats2half2_rn(acc[nt].z, acc[nt].w);
        }
        // scores against up to 4 vectors (exact fp32)
        const float* vv[4] = {v0, v1, v2, v3};
        float* sb[4] = {sb0, sb1, sb2, sb3};
#pragma unroll
        for (int v = 0; v < 4; v++) {
            if (vv[v]) {
#pragma unroll
                for (int hd = 0; hd < 8; hd++) {
                    float a0 = __ldg(vv[v] + 16 * hd + 2 * tig);
                    float a1 = __ldg(vv[v] + 16 * hd + 2 * tig + 1);
                    float a2 = __ldg(vv[v] + 16 * hd + 8 + 2 * tig);
                    float a3 = __ldg(vv[v] + 16 * hd + 8 + 2 * tig + 1);
                    float pA = acc[2*hd].x * a0 + acc[2*hd].y * a1
                             + acc[2*hd+1].x * a2 + acc[2*hd+1].y * a3;
                    float pB = acc[2*hd].z * a0 + acc[2*hd].w * a1
                             + acc[2*hd+1].z * a2 + acc[2*hd+1].w * a3;
                    pA += __shfl_xor_sync(0xffffffffu, pA, 1);
                    pA += __shfl_xor_sync(0xffffffffu, pA, 2);
                    pB += __shfl_xor_sync(0xffffffffu, pB, 1);
                    pB += __shfl_xor_sync(0xffffffffu, pB, 2);
                    if (tig == 0) {
                        if (vA) sb[v][rowA * 8 + hd] = pA;
                        if (vB) sb[v][rowB * 8 + hd] = pB;
                    }
                }
            }
        }
    } else if (act == ACT_OUT) {
        float pA0 = 0.f, pA1 = 0.f, pB0 = 0.f, pB1 = 0.f;
#pragma unroll
        for (int nt = 0; nt < 16; nt++) {
            int col = nt * 8 + 2 * tig;
            float rx = fmaxf(acc[nt].x, 0.f), ry = fmaxf(acc[nt].y, 0.f);
            float rz = fmaxf(acc[nt].z, 0.f), rw = fmaxf(acc[nt].w, 0.f);
            float w00 = __ldg(W2 + col * 2), w01 = __ldg(W2 + col * 2 + 1);
            float w10 = __ldg(W2 + (col + 1) * 2), w11 = __ldg(W2 + (col + 1) * 2 + 1);
            pA0 += rx * w00 + ry * w10; pA1 += rx * w01 + ry * w11;
            pB0 += rz * w00 + rw * w10; pB1 += rz * w01 + rw * w11;
        }
        pA0 += __shfl_xor_sync(0xffffffffu, pA0, 1); pA0 += __shfl_xor_sync(0xffffffffu, pA0, 2);
        pA1 += __shfl_xor_sync(0xffffffffu, pA1, 1); pA1 += __shfl_xor_sync(0xffffffffu, pA1, 2);
        pB0 += __shfl_xor_sync(0xffffffffu, pB0, 1); pB0 += __shfl_xor_sync(0xffffffffu, pB0, 2);
        pB1 += __shfl_xor_sync(0xffffffffu, pB1, 1); pB1 += __shfl_xor_sync(0xffffffffu, pB1, 2);
        if (tig == 0) {
            if (vA) { outp[(size_t)rowA * 2] = pA0 + b2[0]; outp[(size_t)rowA * 2 + 1] = pA1 + b2[1]; }
            if (vB) { outp[(size_t)rowB * 2] = pB0 + b2[0]; outp[(size_t)rowB * 2 + 1] = pB1 + b2[1]; }
        }
    } else { // ACT_RELU
#pragma unroll
        for (int nt = 0; nt < 16; nt++) {
            int col = nt * 8 + 2 * tig;
            float2 oA = make_float2(fmaxf(acc[nt].x, 0.f), fmaxf(acc[nt].y, 0.f));
            float2 oB = make_float2(fmaxf(acc[nt].z, 0.f), fmaxf(acc[nt].w, 0.f));
            if (vA) *(float2*)(C + (size_t)rowA * 128 + col) = oA;
            if (vB) *(float2*)(C + (size_t)rowB * 128 + col) = oB;
        }
    }
}

// ---------------- CSR aggregation: fp16 payload, warp per dst, 4-edge unroll ----
__global__ void __launch_bounds__(256) agg3()
{
    int w = blockIdx.x * 8 + (threadIdx.x >> 5);
    const __half* hsrc;
    const float *ssrc, *sdst;
    const int *rp, *ss;
    float* out;
    int d;
    if (w < N_GENE) {
        d = w; hsrc = g_hsh; ssrc = g_ssrc_sg; sdst = g_sdst_sg;
        rp = g_rp_sg; ss = g_ss_sg; out = g_o_sg;
    } else if (w < N_GENE + N_SNP) {
        d = w - N_GENE; hsrc = g_hgh; ssrc = g_ssrc_gs; sdst = g_sdst_gs;
        rp = g_rp_gs; ss = g_ss_gs; out = g_o_gs;
    } else if (w < 2 * N_GENE + N_SNP) {
        d = w - (N_GENE + N_SNP); hsrc = g_hgh; ssrc = g_ssrc_gg; sdst = g_sdst_gg;
        rp = g_rp_gg; ss = g_ss_gg; out = g_o_gg;
    } else return;

    int lane = threadIdx.x & 31, hd = lane >> 2;
    float sdh = __ldg(sdst + d * 8 + hd);
    int beg = __ldg(rp + d), end = __ldg(rp + d + 1);

    float4 acc0 = make_float4(0.f, 0.f, 0.f, 0.f);
    float4 acc1 = make_float4(0.f, 0.f, 0.f, 0.f);
    float se0 = 0.f, se1 = 0.f;

    int i = beg;
    for (; i + 4 <= end; i += 4) {
        int s0 = __ldg(ss + i), s1 = __ldg(ss + i + 1);
        int s2 = __ldg(ss + i + 2), s3 = __ldg(ss + i + 3);
        float a0 = __ldg(ssrc + s0 * 8 + hd) + sdh;
        float a1 = __ldg(ssrc + s1 * 8 + hd) + sdh;
        float a2 = __ldg(ssrc + s2 * 8 + hd) + sdh;
        float a3 = __ldg(ssrc + s3 * 8 + hd) + sdh;
        uint2 u0 = *((const uint2*)(hsrc + (size_t)s0 * 128) + lane);
        uint2 u1 = *((const uint2*)(hsrc + (size_t)s1 * 128) + lane);
        uint2 u2 = *((const uint2*)(hsrc + (size_t)s2 * 128) + lane);
        uint2 u3 = *((const uint2*)(hsrc + (size_t)s3 * 128) + lane);
        a0 = a0 > 0.f ? a0 : NEG * a0;
        a1 = a1 > 0.f ? a1 : NEG * a1;
        a2 = a2 > 0.f ? a2 : NEG * a2;
        a3 = a3 > 0.f ? a3 : NEG * a3;
        float e0 = __expf(a0), e1 = __expf(a1), e2 = __expf(a2), e3 = __expf(a3);
        float2 f0a = __half22float2(*(__half2*)&u0.x), f0b = __half22float2(*(__half2*)&u0.y);
        float2 f1a = __half22float2(*(__half2*)&u1.x), f1b = __half22float2(*(__half2*)&u1.y);
        float2 f2a = __half22float2(*(__half2*)&u2.x), f2b = __half22float2(*(__half2*)&u2.y);
        float2 f3a = __half22float2(*(__half2*)&u3.x), f3b = __half22float2(*(__half2*)&u3.y);
        acc0.x = fmaf(e0, f0a.x, acc0.x); acc0.y = fmaf(e0, f0a.y, acc0.y);
        acc0.z = fmaf(e0, f0b.x, acc0.z); acc0.w = fmaf(e0, f0b.y, acc0.w);
        acc1.x = fmaf(e1, f1a.x, acc1.x); acc1.y = fmaf(e1, f1a.y, acc1.y);
        acc1.z = fmaf(e1, f1b.x, acc1.z); acc1.w = fmaf(e1, f1b.y, acc1.w);
        acc0.x = fmaf(e2, f2a.x, acc0.x); acc0.y = fmaf(e2, f2a.y, acc0.y);
        acc0.z = fmaf(e2, f2b.x, acc0.z); acc0.w = fmaf(e2, f2b.y, acc0.w);
        acc1.x = fmaf(e3, f3a.x, acc1.x); acc1.y = fmaf(e3, f3a.y, acc1.y);
        acc1.z = fmaf(e3, f3b.x, acc1.z); acc1.w = fmaf(e3, f3b.y, acc1.w);
        se0 += e0 + e2; se1 += e1 + e3;
    }
    for (; i < end; i++) {
        int s0 = __ldg(ss + i);
        float a0 = __ldg(ssrc + s0 * 8 + hd) + sdh;
        uint2 u0 = *((const uint2*)(hsrc + (size_t)s0 * 128) + lane);
        a0 = a0 > 0.f ? a0 : NEG * a0;
        float e0 = __expf(a0);
        float2 f0a = __half22float2(*(__half2*)&u0.x), f0b = __half22float2(*(__half2*)&u0.y);
        acc0.x = fmaf(e0, f0a.x, acc0.x); acc0.y = fmaf(e0, f0a.y, acc0.y);
        acc0.z = fmaf(e0, f0b.x, acc0.z); acc0.w = fmaf(e0, f0b.y, acc0.w);
        se0 += e0;
    }
    float inv = 1.f / (se0 + se1 + 1e-16f);
    float4 r;
    r.x = fmaxf((acc0.x + acc1.x) * inv, 0.f);
    r.y = fmaxf((acc0.y + acc1.y) * inv, 0.f);
    r.z = fmaxf((acc0.z + acc1.z) * inv, 0.f);
    r.w = fmaxf((acc0.w + acc1.w) * inv, 0.f);
    *((float4*)(out + (size_t)d * 128) + lane) = r;
}

// ---------------- semantic softmax: reduce per-block partials + softmax ----------------
__global__ void sem_softmax2(const float* __restrict__ q)
{
    __shared__ float sw[8];
    int m = threadIdx.x >> 7, col = threadIdx.x & 127;
    float s = 0.f;
    const float* part = g_sempart + (size_t)m * TG_BLKS * 128 + col;
    for (int b = 0; b < TG_BLKS; b++) s += part[b * 128];
    float v = q[col] * (s / 20000.f);
    int lane = threadIdx.x & 31;
#pragma unroll
    for (int o = 16; o; o >>= 1) v += __shfl_xor_sync(0xffffffffu, v, o);
    if (lane == 0) sw[threadIdx.x >> 5] = v;
    __syncthreads();
    if (threadIdx.x == 0) {
        float s0 = sw[0] + sw[1] + sw[2] + sw[3];
        float s1 = sw[4] + sw[5] + sw[6] + sw[7];
        float mx = fmaxf(s0, s1);
        float e0 = __expf(s0 - mx), e1 = __expf(s1 - mx);
        float inv = 1.f / (e0 + e1);
        g_attn[0] = e0 * inv; g_attn[1] = e1 * inv;
    }
}

// ---------------- combine + LayerNorm (+ layer fusion), gene + snp fused ----------------
__global__ void __launch_bounds__(256) combine_all(
    const float* __restrict__ ln_gp, const float* __restrict__ ln_bp,
    const float* __restrict__ fw, int layer1)
{
    int idx = blockIdx.x * blockDim.x + threadIdx.x;
    int w = idx >> 5, lane = idx & 31;
    if (w >= N_GENE + N_SNP) return;
    const float *o1, *o2, *prev;
    float* out;
    int n;
    if (w < N_GENE) {
        n = w; o1 = g_o_sg; o2 = g_o_gg;
        prev = layer1 ? g_out_g0 : nullptr;
        out = layer1 ? (g_buf1 + (size_t)N_SNP * 128) : g_out_g0;
    } else {
        n = w - N_GENE; o1 = g_o_gs; o2 = nullptr;
        prev = layer1 ? g_out_s0 : nullptr;
        out = layer1 ? g_buf1 : g_out_s0;
    }
    float4 v = *((const float4*)(o1 + (size_t)n * 128) + lane);
    if (o2) {
        float a0 = g_attn[0], a1 = g_attn[1];
        float4 u = *((const float4*)(o2 + (size_t)n * 128) + lane);
        v.x = a0 * v.x + a1 * u.x;
        v.y = a0 * v.y + a1 * u.y;
        v.z = a0 * v.z + a1 * u.z;
        v.w = a0 * v.w + a1 * u.w;
    }
    float s = v.x + v.y + v.z + v.w;
#pragma unroll
    for (int o = 16; o; o >>= 1) s += __shfl_xor_sync(0xffffffffu, s, o);
    float mu = s * (1.f / 128.f);
    float dx = v.x - mu, dy = v.y - mu, dz = v.z - mu, dw = v.w - mu;
    float qv = dx * dx + dy * dy + dz * dz + dw * dw;
#pragma unroll
    for (int o = 16; o; o >>= 1) qv += __shfl_xor_sync(0xffffffffu, qv, o);
    float rs = rsqrtf(qv * (1.f / 128.f) + 1e-5f);
    float4 g4 = *((const float4*)ln_gp + lane);
    float4 b4 = *((const float4*)ln_bp + lane);
    float4 r;
    r.x = dx * rs * g4.x + b4.x;
    r.y = dy * rs * g4.y + b4.y;
    r.z = dz * rs * g4.z + b4.z;
    r.w = dw * rs * g4.w + b4.w;
    if (prev) {
        float w0 = fw[0], w1 = fw[1];
        float inv = 1.f / (w0 + w1);
        float4 p = *((const float4*)(prev + (size_t)n * 128) + lane);
        r.x = (w0 * p.x + w1 * r.x) * inv;
        r.y = (w0 * p.y + w1 * r.y) * inv;
        r.z = (w0 * p.z + w1 * r.z) * inv;
        r.w = (w0 * p.w + w1 * r.w) * inv;
    }
    *((float4*)(out + (size_t)n * 128) + lane) = r;
}

static inline int cdiv(long a, int b) { return (int)((a + b - 1) / b); }

extern "C" void kernel_launch(void* const* d_in, const int* in_sizes, int n_in,
                              void* d_out, int out_size)
{
    const float* x_snp  = (const float*)d_in[0];
    const float* x_gene = (const float*)d_in[1];
    const float* Wp_snp = (const float*)d_in[2];
    const float* bp_snp = (const float*)d_in[3];
    const float* Wp_gene= (const float*)d_in[4];
    const float* bp_gene= (const float*)d_in[5];
    const float* a_src  = (const float*)d_in[6];
    const float* a_dst  = (const float*)d_in[7];
    const float* Wk     = (const float*)d_in[8];
    const float* bk     = (const float*)d_in[9];
    const float* qvp    = (const float*)d_in[10];
    const float* ln_g   = (const float*)d_in[11];
    const float* ln_b   = (const float*)d_in[12];
    const float* fw     = (const float*)d_in[13];
    const float* Wfp    = (const float*)d_in[14];
    const float* bfp    = (const float*)d_in[15];
    const float* Wo1    = (const float*)d_in[16];
    const float* bo1    = (const float*)d_in[17];
    const float* Wo2    = (const float*)d_in[18];
    const float* bo2    = (const float*)d_in[19];
    const int* sg_s = (const int*)d_in[20];
    const int* sg_d = (const int*)d_in[21];
    const int* gs_s = (const int*)d_in[22];
    const int* gs_d = (const int*)d_in[23];
    const int* gg_s = (const int*)d_in[24];
    const int* gg_d = (const int*)d_in[25];
    const int E_sg = in_sizes[20], E_gs = in_sizes[22], E_gg = in_sizes[24];

    __half *hsh, *hgh;
    float *o_sg, *o_gg, *out_s0, *out_g0, *sempart, *buf1, *buf2;
    float *ssrc_sg, *sdst_gs, *sdst_sg, *ssrc_gs, *ssrc_gg, *sdst_gg;
    unsigned char* wimg;
    cudaGetSymbolAddress((void**)&hsh, g_hsh);
    cudaGetSymbolAddress((void**)&hgh, g_hgh);
    cudaGetSymbolAddress((void**)&o_sg, g_o_sg);
    cudaGetSymbolAddress((void**)&o_gg, g_o_gg);
    cudaGetSymbolAddress((void**)&out_s0, g_out_s0);
    cudaGetSymbolAddress((void**)&out_g0, g_out_g0);
    cudaGetSymbolAddress((void**)&sempart, g_sempart);
    cudaGetSymbolAddress((void**)&buf1, g_buf1);
    cudaGetSymbolAddress((void**)&buf2, g_buf2);
    cudaGetSymbolAddress((void**)&wimg, g_wimg);
    cudaGetSymbolAddress((void**)&ssrc_sg, g_ssrc_sg);
    cudaGetSymbolAddress((void**)&sdst_gs, g_sdst_gs);
    cudaGetSymbolAddress((void**)&sdst_sg, g_sdst_sg);
    cudaGetSymbolAddress((void**)&ssrc_gs, g_ssrc_gs);
    cudaGetSymbolAddress((void**)&ssrc_gg, g_ssrc_gg);
    cudaGetSymbolAddress((void**)&sdst_gg, g_sdst_gg);

    cudaFuncSetAttribute(tgemm, cudaFuncAttributeMaxDynamicSharedMemorySize, TG_SMEM_TOTAL);

    wprep8<<<512, 256>>>(Wp_snp, Wp_snp + 16384, Wp_gene, Wp_gene + 16384,
                         Wk, Wk + 16384, Wfp, Wo1, wimg);

    const int E_tot = E_sg + E_gs + E_gg;
    zero_all<<<cdiv(2 * NSEG_TOT, 256), 256>>>();
    hist3<<<cdiv(E_tot, 256), 256>>>(sg_d, gs_d, gg_d, E_sg, E_gs, E_gg);
    bsum3<<<NB_TOT, 1024>>>();
    bscan3<<<1, 32>>>();
    scan3<<<NB_TOT, 1024>>>();
    scatter3<<<cdiv(E_tot, 256), 256>>>(sg_s, sg_d, gs_s, gs_d, gg_s, gg_d,
                                        E_sg, E_gs, E_gg);

    const int TS = cdiv(N_SNP, 128), TG = cdiv(N_GENE, 128), TA = cdiv(N_ALL, 128);

    for (int l = 0; l < 2; ++l) {
        const float* ins = l ? out_s0 : x_snp;
        const float* ing = l ? out_g0 : x_gene;

        // snp projection + fp16 h + scores (src of sg, dst of gs)
        tgemm<<<TS, 256, TG_SMEM_TOTAL>>>(ins, nullptr, wimg + (0 + l) * WIMGSZ,
            bp_snp + l * 128, nullptr, hsh,
            a_src + (l * 3 + 0) * 128, a_dst + (l * 3 + 1) * 128, nullptr, nullptr,
            ssrc_sg, sdst_gs, nullptr, nullptr,
            nullptr, nullptr, nullptr, N_SNP, 0, ACT_H);
        // gene projection + fp16 h + scores (dst sg, src gs, src gg, dst gg)
        tgemm<<<TG, 256, TG_SMEM_TOTAL>>>(ing, nullptr, wimg + (2 + l) * WIMGSZ,
            bp_gene + l * 128, nullptr, hgh,
            a_dst + (l * 3 + 0) * 128, a_src + (l * 3 + 1) * 128,
            a_src + (l * 3 + 2) * 128, a_dst + (l * 3 + 2) * 128,
            sdst_sg, ssrc_gs, ssrc_gg, sdst_gg,
            nullptr, nullptr, nullptr, N_GENE, 0, ACT_H);

        agg3<<<cdiv(2 * N_GENE + N_SNP, 8), 256>>>();

        // merged semantic GEMMs: blocks [0,TG)->o_sg, [TG,2TG)->o_gg
        tgemm<<<2 * TG, 256, TG_SMEM_TOTAL>>>(o_sg, o_gg, wimg + (4 + l) * WIMGSZ,
            bk + l * 128, sempart, nullptr,
            nullptr, nullptr, nullptr, nullptr,
            nullptr, nullptr, nullptr, nullptr,
            nullptr, nullptr, nullptr, N_GENE, TG, ACT_TANHSUM);
        sem_softmax2<<<1, 256>>>(qvp + l * 128);

        combine_all<<<cdiv((long)(N_GENE + N_SNP) * 32, 256), 256>>>(
            ln_g + l * 128, ln_b + l * 128, fw, l);
    }

    tgemm<<<TA, 256, TG_SMEM_TOTAL>>>(buf1, nullptr, wimg + 6 * WIMGSZ,
        bfp, buf2, nullptr,
        nullptr, nullptr, nullptr, nullptr,
        nullptr, nullptr, nullptr, nullptr,
        nullptr, nullptr, nullptr, N_ALL, 0, ACT_RELU);
    tgemm<<<TA, 256, TG_SMEM_TOTAL>>>(buf2, nullptr, wimg + 7 * WIMGSZ,
        bo1, nullptr, nullptr,
        nullptr, nullptr, nullptr, nullptr,
        nullptr, nullptr, nullptr, nullptr,
        Wo2, bo2, (float*)d_out, N_ALL, 0, ACT_OUT);
}

// round 9
// speedup vs baseline: 2.3244x; 1.0288x over previous
#include <cuda_runtime.h>
#include <cuda_bf16.h>
#include <cuda_fp16.h>
#include <cstdint>

#define N_SNP  100000
#define N_GENE 20000
#define N_ALL  120000
#define HID    128
#define NEG    0.2f

#define ACT_RELU    1
#define ACT_TANHSUM 2
#define ACT_H       3
#define ACT_OUT     4

#define E_SG_MAX 500000
#define E_GS_MAX 500000
#define E_GG_MAX 150000

#define SEG_GS 20000
#define SEG_GG 120000
#define NSEG_TOT 140000
#define NB_SG 20
#define NB_GS 98
#define NB_GG 20
#define NB_TOT 138

#define TG_BLKS 157

#define WROW   272
#define WLO    34816
#define WIMGSZ 69632

// ---------------- device scratch ----------------
__device__ __half   g_hsh[N_SNP * HID];
__device__ __half   g_hgh[N_GENE * HID];
__device__ float    g_ssrc_sg[N_SNP * 8];
__device__ float    g_sdst_gs[N_SNP * 8];
__device__ float    g_sdst_sg[N_GENE * 8];
__device__ float    g_ssrc_gs[N_GENE * 8];
__device__ float    g_ssrc_gg[N_GENE * 8];
__device__ float    g_sdst_gg[N_GENE * 8];
__device__ float    g_o_sg[N_GENE * HID];
__device__ float    g_o_gg[N_GENE * HID];
__device__ float    g_out_s0[N_SNP * HID];
__device__ float    g_out_g0[N_GENE * HID];
__device__ float    g_sempart[2 * TG_BLKS * HID];
__device__ float    g_attn[2];
__device__ float    g_buf1[N_ALL * HID];
__device__ float    g_buf2[N_ALL * HID];
__device__ __align__(16) unsigned char g_wimg[8 * WIMGSZ];
__device__ int g_rp_sg[N_GENE + 1];
__device__ int g_rp_gs[N_SNP + 1];
__device__ int g_rp_gg[N_GENE + 1];
__device__ int g_dc[2 * NSEG_TOT];
__device__ int g_bsum[NB_TOT + 4];
__device__ int g_ss_sg[E_SG_MAX];
__device__ int g_ss_gs[E_GS_MAX];
__device__ int g_ss_gg[E_GG_MAX];

__device__ __forceinline__ uint32_t pack_bf(float x, float y) {
    __nv_bfloat162 t = __floats2bfloat162_rn(x, y);
    return *(uint32_t*)&t;
}
__device__ __forceinline__ void mma_bf16(float4& c, uint32_t a0, uint32_t a1,
                                         uint32_t a2, uint32_t a3,
                                         uint32_t b0, uint32_t b1) {
    asm volatile("mma.sync.aligned.m16n8k16.row.col.f32.bf16.bf16.f32 "
                 "{%0,%1,%2,%3}, {%4,%5,%6,%7}, {%8,%9}, {%0,%1,%2,%3};"
                 : "+f"(c.x), "+f"(c.y), "+f"(c.z), "+f"(c.w)
                 : "r"(a0), "r"(a1), "r"(a2), "r"(a3), "r"(b0), "r"(b1));
}

// ---------------- CSR build (batched over 3 edge types) ----------------
__global__ void zero_all() {
    int i = blockIdx.x * 256 + threadIdx.x;
    if (i < 2 * NSEG_TOT) g_dc[i] = 0;
}
__global__ void hist3(const int* __restrict__ d1, const int* __restrict__ d2,
                      const int* __restrict__ d3, int E1, int E2, int E3) {
    int i = blockIdx.x * 256 + threadIdx.x;
    if (i < E1) atomicAdd(g_dc + d1[i], 1);
    else if (i < E1 + E2) atomicAdd(g_dc + SEG_GS + d2[i - E1], 1);
    else if (i < E1 + E2 + E3) atomicAdd(g_dc + SEG_GG + d3[i - E1 - E2], 1);
}
__device__ __forceinline__ void seg_map(int b, int& degoff, int& nd, int& boff, int& lb) {
    if (b < NB_SG)            { degoff = 0;      nd = N_GENE; boff = 0;             lb = b; }
    else if (b < NB_SG+NB_GS) { degoff = SEG_GS; nd = N_SNP;  boff = NB_SG;         lb = b - NB_SG; }
    else                      { degoff = SEG_GG; nd = N_GENE; boff = NB_SG + NB_GS; lb = b - NB_SG - NB_GS; }
}
__global__ void bsum3() {
    __shared__ int sw[32];
    int degoff, nd, boff, lb;
    seg_map(blockIdx.x, degoff, nd, boff, lb);
    int i = lb * 1024 + threadIdx.x;
    int v = (i < nd) ? g_dc[degoff + i] : 0;
#pragma unroll
    for (int o = 16; o; o >>= 1) v += __shfl_xor_sync(0xffffffffu, v, o);
    if ((threadIdx.x & 31) == 0) sw[threadIdx.x >> 5] = v;
    __syncthreads();
    if (threadIdx.x < 32) {
        int t = sw[threadIdx.x];
#pragma unroll
        for (int o = 16; o; o >>= 1) t += __shfl_xor_sync(0xffffffffu, t, o);
        if (threadIdx.x == 0) g_bsum[boff + lb] = t;
    }
}
__global__ void bscan3() {
    if (threadIdx.x == 0) {
        const int off[3] = {0, NB_SG, NB_SG + NB_GS};
        const int nb[3] = {NB_SG, NB_GS, NB_GG};
        for (int s = 0; s < 3; s++) {
            int c = 0;
            for (int i = 0; i < nb[s]; i++) {
                int v = g_bsum[off[s] + i];
                g_bsum[off[s] + i] = c;
                c += v;
            }
        }
    }
}
__global__ void scan3() {
    __shared__ int sm[1024];
    int degoff, nd, boff, lb;
    seg_map(blockIdx.x, degoff, nd, boff, lb);
    int* rp = (blockIdx.x < NB_SG) ? g_rp_sg
            : (blockIdx.x < NB_SG + NB_GS) ? g_rp_gs : g_rp_gg;
    int tid = threadIdx.x;
    int i = lb * 1024 + tid;
    int v = (i < nd) ? g_dc[degoff + i] : 0;
    sm[tid] = v;
    __syncthreads();
#pragma unroll
    for (int off = 1; off < 1024; off <<= 1) {
        int t = (tid >= off) ? sm[tid - off] : 0;
        __syncthreads();
        sm[tid] += t;
        __syncthreads();
    }
    int incl = sm[tid];
    int base = g_bsum[boff + lb];
    if (i < nd) rp[i] = base + incl - v;
    if (i == nd - 1) rp[nd] = base + incl;
}
__global__ void scatter3(const int* __restrict__ s1, const int* __restrict__ d1,
                         const int* __restrict__ s2, const int* __restrict__ d2,
                         const int* __restrict__ s3, const int* __restrict__ d3,
                         int E1, int E2, int E3) {
    int i = blockIdx.x * 256 + threadIdx.x;
    if (i < E1) {
        int d = d1[i];
        g_ss_sg[g_rp_sg[d] + atomicAdd(g_dc + NSEG_TOT + d, 1)] = s1[i];
    } else if (i < E1 + E2) {
        int e = i - E1, d = d2[e];
        g_ss_gs[g_rp_gs[d] + atomicAdd(g_dc + NSEG_TOT + SEG_GS + d, 1)] = s2[e];
    } else if (i < E1 + E2 + E3) {
        int e = i - E1 - E2, d = d3[e];
        g_ss_gg[g_rp_gg[d] + atomicAdd(g_dc + NSEG_TOT + SEG_GG + d, 1)] = s3[e];
    }
}

// ---------------- weight prep: all 8 matrices in one launch ----------------
__global__ void wprep8(const float* __restrict__ W0, const float* __restrict__ W1,
                       const float* __restrict__ W2, const float* __restrict__ W3,
                       const float* __restrict__ W4, const float* __restrict__ W5,
                       const float* __restrict__ W6, const float* __restrict__ W7,
                       unsigned char* __restrict__ imgbase) {
    int b = blockIdx.x >> 6;
    const float* W;
    if      (b == 0) W = W0; else if (b == 1) W = W1;
    else if (b == 2) W = W2; else if (b == 3) W = W3;
    else if (b == 4) W = W4; else if (b == 5) W = W5;
    else if (b == 6) W = W6; else              W = W7;
    unsigned char* img = imgbase + (size_t)b * WIMGSZ;
    int i = (blockIdx.x & 63) * 256 + threadIdx.x;
    int n = i >> 7, k = i & 127;
    float w = W[k * 128 + n];
    __nv_bfloat16 h = __float2bfloat16(w);
    __nv_bfloat16 l = __float2bfloat16(w - __bfloat162float(h));
    *(uint16_t*)(img + n * WROW + k * 2) = __bfloat16_as_ushort(h);
    *(uint16_t*)(img + WLO + n * WROW + k * 2) = __bfloat16_as_ushort(l);
}

// ---------------- tensor-core GEMM (mma.sync bf16 split) ----------------
#define TG_SMEM_TOTAL (WIMGSZ + 512)

__global__ void __launch_bounds__(256) tgemm(
    const float* __restrict__ A, const float* __restrict__ A2,
    const unsigned char* __restrict__ Bimg,
    const float* __restrict__ bias, float* __restrict__ C,
    __half* __restrict__ Ch,
    const float* __restrict__ v0, const float* __restrict__ v1,
    const float* __restrict__ v2, const float* __restrict__ v3,
    float* __restrict__ sb0, float* __restrict__ sb1,
    float* __restrict__ sb2, float* __restrict__ sb3,
    const float* __restrict__ W2, const float* __restrict__ b2,
    float* __restrict__ outp,
    int M, int nhalf, int act)
{
    extern __shared__ unsigned char smem[];
    float* scs = (float*)(smem + WIMGSZ);
    const int tid = threadIdx.x, wid = tid >> 5, lane = tid & 31;
    const int g = lane >> 2, tig = lane & 3;

    int blk = blockIdx.x;
    if (act == ACT_TANHSUM && blk >= nhalf) { A = A2; blk -= nhalf; }

    {
        const uint4* src = (const uint4*)Bimg;
        uint4* dst = (uint4*)smem;
#pragma unroll
        for (int i = 0; i < 17; i++) {
            int idx = tid + 256 * i;
            if (idx < WIMGSZ / 16) dst[idx] = src[idx];
        }
    }
    if (act == ACT_TANHSUM && tid < 128) scs[tid] = 0.f;
    __syncthreads();

    const int rowA = blk * 128 + wid * 16 + g;
    const int rowB = rowA + 8;
    const bool vA = rowA < M, vB = rowB < M;

    float4 acc[16];
#pragma unroll
    for (int nt = 0; nt < 16; nt++) acc[nt] = make_float4(0.f, 0.f, 0.f, 0.f);

    const float* ArA = A + (size_t)rowA * 128;
    const float* ArB = A + (size_t)rowB * 128;

#pragma unroll
    for (int ks = 0; ks < 8; ks++) {
        const int k0 = ks * 16;
        float2 p00 = make_float2(0.f, 0.f), p01 = p00, p10 = p00, p11 = p00;
        if (vA) {
            p00 = *(const float2*)(ArA + k0 + 2 * tig);
            p01 = *(const float2*)(ArA + k0 + 2 * tig + 8);
        }
        if (vB) {
            p10 = *(const float2*)(ArB + k0 + 2 * tig);
            p11 = *(const float2*)(ArB + k0 + 2 * tig + 8);
        }
        uint32_t ah0 = pack_bf(p00.x, p00.y), ah1 = pack_bf(p10.x, p10.y);
        uint32_t ah2 = pack_bf(p01.x, p01.y), ah3 = pack_bf(p11.x, p11.y);
        __nv_bfloat162 h00 = *(__nv_bfloat162*)&ah0, h10 = *(__nv_bfloat162*)&ah1;
        __nv_bfloat162 h01 = *(__nv_bfloat162*)&ah2, h11 = *(__nv_bfloat162*)&ah3;
        uint32_t al0 = pack_bf(p00.x - __bfloat162float(h00.x), p00.y - __bfloat162float(h00.y));
        uint32_t al1 = pack_bf(p10.x - __bfloat162float(h10.x), p10.y - __bfloat162float(h10.y));
        uint32_t al2 = pack_bf(p01.x - __bfloat162float(h01.x), p01.y - __bfloat162float(h01.y));
        uint32_t al3 = pack_bf(p11.x - __bfloat162float(h11.x), p11.y - __bfloat162float(h11.y));

        const unsigned char* bh = smem + (size_t)g * WROW + (k0 + 2 * tig) * 2;
#pragma unroll
        for (int nt = 0; nt < 16; nt++) {
            uint32_t bh0 = *(const uint32_t*)(bh + nt * 8 * WROW);
            uint32_t bh1 = *(const uint32_t*)(bh + nt * 8 * WROW + 16);
            mma_bf16(acc[nt], ah0, ah1, ah2, ah3, bh0, bh1);
            mma_bf16(acc[nt], al0, al1, al2, al3, bh0, bh1);
            uint32_t bl0 = *(const uint32_t*)(bh + WLO + nt * 8 * WROW);
            uint32_t bl1 = *(const uint32_t*)(bh + WLO + nt * 8 * WROW + 16);
            mma_bf16(acc[nt], ah0, ah1, ah2, ah3, bl0, bl1);
        }
    }

#pragma unroll
    for (int nt = 0; nt < 16; nt++) {
        int col = nt * 8 + 2 * tig;
        float b0 = bias[col], b1 = bias[col + 1];
        acc[nt].x += b0; acc[nt].y += b1;
        acc[nt].z += b0; acc[nt].w += b1;
    }

    if (act == ACT_TANHSUM) {
#pragma unroll
        for (int nt = 0; nt < 16; nt++) {
            int col = nt * 8 + 2 * tig;
            float s0 = 0.f, s1 = 0.f;
            if (vA) { s0 += tanhf(acc[nt].x); s1 += tanhf(acc[nt].y); }
            if (vB) { s0 += tanhf(acc[nt].z); s1 += tanhf(acc[nt].w); }
            atomicAdd(scs + col, s0);
            atomicAdd(scs + col + 1, s1);
        }
        __syncthreads();
        if (tid < 128) C[blockIdx.x * 128 + tid] = scs[tid];
    } else if (act == ACT_H) {
#pragma unroll
        for (int nt = 0; nt < 16; nt++) {
            int col = nt * 8 + 2 * tig;
            if (vA) *((__half2*)(Ch + (size_t)rowA * 128 + col)) = __floats2half2_rn(acc[nt].x, acc[nt].y);
            if (vB) *((__half2*)(Ch + (size_t)rowB * 128 + col)) = __floats2half2_rn(acc[nt].z, acc[nt].w);
        }
        const float* vv[4] = {v0, v1, v2, v3};
        float* sb[4] = {sb0, sb1, sb2, sb3};
#pragma unroll
        for (int v = 0; v < 4; v++) {
            if (vv[v]) {
#pragma unroll
                for (int hd = 0; hd < 8; hd++) {
                    float a0 = __ldg(vv[v] + 16 * hd + 2 * tig);
                    float a1 = __ldg(vv[v] + 16 * hd + 2 * tig + 1);
                    float a2 = __ldg(vv[v] + 16 * hd + 8 + 2 * tig);
                    float a3 = __ldg(vv[v] + 16 * hd + 8 + 2 * tig + 1);
                    float pA = acc[2*hd].x * a0 + acc[2*hd].y * a1
                             + acc[2*hd+1].x * a2 + acc[2*hd+1].y * a3;
                    float pB = acc[2*hd].z * a0 + acc[2*hd].w * a1
                             + acc[2*hd+1].z * a2 + acc[2*hd+1].w * a3;
                    pA += __shfl_xor_sync(0xffffffffu, pA, 1);
                    pA += __shfl_xor_sync(0xffffffffu, pA, 2);
                    pB += __shfl_xor_sync(0xffffffffu, pB, 1);
                    pB += __shfl_xor_sync(0xffffffffu, pB, 2);
                    if (tig == 0) {
                        if (vA) sb[v][rowA * 8 + hd] = pA;
                        if (vB) sb[v][rowB * 8 + hd] = pB;
                    }
                }
            }
        }
    } else if (act == ACT_OUT) {
        float pA0 = 0.f, pA1 = 0.f, pB0 = 0.f, pB1 = 0.f;
#pragma unroll
        for (int nt = 0; nt < 16; nt++) {
            int col = nt * 8 + 2 * tig;
            float rx = fmaxf(acc[nt].x, 0.f), ry = fmaxf(acc[nt].y, 0.f);
            float rz = fmaxf(acc[nt].z, 0.f), rw = fmaxf(acc[nt].w, 0.f);
            float w00 = __ldg(W2 + col * 2), w01 = __ldg(W2 + col * 2 + 1);
            float w10 = __ldg(W2 + (col + 1) * 2), w11 = __ldg(W2 + (col + 1) * 2 + 1);
            pA0 += rx * w00 + ry * w10; pA1 += rx * w01 + ry * w11;
            pB0 += rz * w00 + rw * w10; pB1 += rz * w01 + rw * w11;
        }
        pA0 += __shfl_xor_sync(0xffffffffu, pA0, 1); pA0 += __shfl_xor_sync(0xffffffffu, pA0, 2);
        pA1 += __shfl_xor_sync(0xffffffffu, pA1, 1); pA1 += __shfl_xor_sync(0xffffffffu, pA1, 2);
        pB0 += __shfl_xor_sync(0xffffffffu, pB0, 1); pB0 += __shfl_xor_sync(0xffffffffu, pB0, 2);
        pB1 += __shfl_xor_sync(0xffffffffu, pB1, 1); pB1 += __shfl_xor_sync(0xffffffffu, pB1, 2);
        if (tig == 0) {
            if (vA) { outp[(size_t)rowA * 2] = pA0 + b2[0]; outp[(size_t)rowA * 2 + 1] = pA1 + b2[1]; }
            if (vB) { outp[(size_t)rowB * 2] = pB0 + b2[0]; outp[(size_t)rowB * 2 + 1] = pB1 + b2[1]; }
        }
    } else { // ACT_RELU
#pragma unroll
        for (int nt = 0; nt < 16; nt++) {
            int col = nt * 8 + 2 * tig;
            float2 oA = make_float2(fmaxf(acc[nt].x, 0.f), fmaxf(acc[nt].y, 0.f));
            float2 oB = make_float2(fmaxf(acc[nt].z, 0.f), fmaxf(acc[nt].w, 0.f));
            if (vA) *(float2*)(C + (size_t)rowA * 128 + col) = oA;
            if (vB) *(float2*)(C + (size_t)rowB * 128 + col) = oB;
        }
    }
}

// ---------------- CSR aggregation: half-warp per edge, fused snp LN ----------------
// warp = one destination. lanes 0-15 process even edges, 16-31 odd edges (16B h chunks).
// gene paths write o_sg/o_gg; snp path applies LN (+layer fusion) inline.
__global__ void __launch_bounds__(256) agg3(
    const float* __restrict__ ln_gp, const float* __restrict__ ln_bp,
    const float* __restrict__ fw, int layer1)
{
    int w = blockIdx.x * 8 + (threadIdx.x >> 5);
    const __half* hsrc;
    const float *ssrc, *sdst;
    const int *rp, *ss;
    float* out;
    const float* prev = nullptr;
    int d;
    bool fuse = false;
    if (w < N_GENE) {
        d = w; hsrc = g_hsh; ssrc = g_ssrc_sg; sdst = g_sdst_sg;
        rp = g_rp_sg; ss = g_ss_sg; out = g_o_sg;
    } else if (w < N_GENE + N_SNP) {
        d = w - N_GENE; hsrc = g_hgh; ssrc = g_ssrc_gs; sdst = g_sdst_gs;
        rp = g_rp_gs; ss = g_ss_gs;
        fuse = true;
        prev = layer1 ? g_out_s0 : nullptr;
        out = layer1 ? g_buf1 : g_out_s0;
    } else if (w < 2 * N_GENE + N_SNP) {
        d = w - (N_GENE + N_SNP); hsrc = g_hgh; ssrc = g_ssrc_gg; sdst = g_sdst_gg;
        rp = g_rp_gg; ss = g_ss_gg; out = g_o_gg;
    } else return;

    const int lane = threadIdx.x & 31, hw = lane >> 4, l16 = lane & 15, hd = l16 >> 1;
    float sdh = __ldg(sdst + d * 8 + hd);
    int beg = __ldg(rp + d), end = __ldg(rp + d + 1);

    float acc[8];
#pragma unroll
    for (int j = 0; j < 8; j++) acc[j] = 0.f;
    float se = 0.f;

#pragma unroll 2
    for (int i = beg; i < end; i += 2) {
        int ii = i + hw;
        if (ii < end) {
            int s = __ldg(ss + ii);
            float a = __ldg(ssrc + s * 8 + hd) + sdh;
            uint4 u = *((const uint4*)(hsrc + (size_t)s * 128) + l16);
            a = a > 0.f ? a : NEG * a;
            float e = __expf(a);
            float2 f0 = __half22float2(*(__half2*)&u.x);
            float2 f1 = __half22float2(*(__half2*)&u.y);
            float2 f2 = __half22float2(*(__half2*)&u.z);
            float2 f3 = __half22float2(*(__half2*)&u.w);
            acc[0] = fmaf(e, f0.x, acc[0]); acc[1] = fmaf(e, f0.y, acc[1]);
            acc[2] = fmaf(e, f1.x, acc[2]); acc[3] = fmaf(e, f1.y, acc[3]);
            acc[4] = fmaf(e, f2.x, acc[4]); acc[5] = fmaf(e, f2.y, acc[5]);
            acc[6] = fmaf(e, f3.x, acc[6]); acc[7] = fmaf(e, f3.y, acc[7]);
            se += e;
        }
    }
    // combine half-warps (both halves end up with totals)
    se += __shfl_xor_sync(0xffffffffu, se, 16);
#pragma unroll
    for (int j = 0; j < 8; j++) acc[j] += __shfl_xor_sync(0xffffffffu, acc[j], 16);
    float inv = 1.f / (se + 1e-16f);
    float r[8];
#pragma unroll
    for (int j = 0; j < 8; j++) r[j] = fmaxf(acc[j] * inv, 0.f);

    if (!fuse) {
        if (hw == 0) {
            float4* op = (float4*)(out + (size_t)d * 128 + l16 * 8);
            op[0] = make_float4(r[0], r[1], r[2], r[3]);
            op[1] = make_float4(r[4], r[5], r[6], r[7]);
        }
        return;
    }

    // fused LayerNorm (+ layer fusion) for the snp path
    float ps = r[0] + r[1] + r[2] + r[3] + r[4] + r[5] + r[6] + r[7];
#pragma unroll
    for (int o = 8; o; o >>= 1) ps += __shfl_xor_sync(0xffffffffu, ps, o);
    float mu = ps * (1.f / 128.f);
    float pv = 0.f;
#pragma unroll
    for (int j = 0; j < 8; j++) { float dl = r[j] - mu; pv += dl * dl; }
#pragma unroll
    for (int o = 8; o; o >>= 1) pv += __shfl_xor_sync(0xffffffffu, pv, o);
    float rs = rsqrtf(pv * (1.f / 128.f) + 1e-5f);
    if (hw == 0) {
        float4 g0 = __ldg((const float4*)ln_gp + l16 * 2);
        float4 g1 = __ldg((const float4*)ln_gp + l16 * 2 + 1);
        float4 b0 = __ldg((const float4*)ln_bp + l16 * 2);
        float4 b1 = __ldg((const float4*)ln_bp + l16 * 2 + 1);
        float4 o0, o1;
        o0.x = (r[0] - mu) * rs * g0.x + b0.x;
        o0.y = (r[1] - mu) * rs * g0.y + b0.y;
        o0.z = (r[2] - mu) * rs * g0.z + b0.z;
        o0.w = (r[3] - mu) * rs * g0.w + b0.w;
        o1.x = (r[4] - mu) * rs * g1.x + b1.x;
        o1.y = (r[5] - mu) * rs * g1.y + b1.y;
        o1.z = (r[6] - mu) * rs * g1.z + b1.z;
        o1.w = (r[7] - mu) * rs * g1.w + b1.w;
        if (prev) {
            float w0 = fw[0], w1 = fw[1];
            float iw = 1.f / (w0 + w1);
            float4 p0 = *((const float4*)(prev + (size_t)d * 128 + l16 * 8));
            float4 p1 = *((const float4*)(prev + (size_t)d * 128 + l16 * 8) + 1);
            o0.x = (w0 * p0.x + w1 * o0.x) * iw;
            o0.y = (w0 * p0.y + w1 * o0.y) * iw;
            o0.z = (w0 * p0.z + w1 * o0.z) * iw;
            o0.w = (w0 * p0.w + w1 * o0.w) * iw;
            o1.x = (w0 * p1.x + w1 * o1.x) * iw;
            o1.y = (w0 * p1.y + w1 * o1.y) * iw;
            o1.z = (w0 * p1.z + w1 * o1.z) * iw;
            o1.w = (w0 * p1.w + w1 * o1.w) * iw;
        }
        float4* op = (float4*)(out + (size_t)d * 128 + l16 * 8);
        op[0] = o0; op[1] = o1;
    }
}

// ---------------- semantic softmax: reduce per-block partials + softmax ----------------
__global__ void sem_softmax2(const float* __restrict__ q)
{
    __shared__ float sw[8];
    int m = threadIdx.x >> 7, col = threadIdx.x & 127;
    float s = 0.f;
    const float* part = g_sempart + (size_t)m * TG_BLKS * 128 + col;
    for (int b = 0; b < TG_BLKS; b++) s += part[b * 128];
    float v = q[col] * (s / 20000.f);
    int lane = threadIdx.x & 31;
#pragma unroll
    for (int o = 16; o; o >>= 1) v += __shfl_xor_sync(0xffffffffu, v, o);
    if (lane == 0) sw[threadIdx.x >> 5] = v;
    __syncthreads();
    if (threadIdx.x == 0) {
        float s0 = sw[0] + sw[1] + sw[2] + sw[3];
        float s1 = sw[4] + sw[5] + sw[6] + sw[7];
        float mx = fmaxf(s0, s1);
        float e0 = __expf(s0 - mx), e1 = __expf(s1 - mx);
        float inv = 1.f / (e0 + e1);
        g_attn[0] = e0 * inv; g_attn[1] = e1 * inv;
    }
}

// ---------------- gene combine + LayerNorm (+ layer fusion) ----------------
__global__ void __launch_bounds__(256) combine_all(
    const float* __restrict__ ln_gp, const float* __restrict__ ln_bp,
    const float* __restrict__ fw, int layer1)
{
    int idx = blockIdx.x * blockDim.x + threadIdx.x;
    int n = idx >> 5, lane = idx & 31;
    if (n >= N_GENE) return;
    const float* prev = layer1 ? g_out_g0 : nullptr;
    float* out = layer1 ? (g_buf1 + (size_t)N_SNP * 128) : g_out_g0;
    float4 v = *((const float4*)(g_o_sg + (size_t)n * 128) + lane);
    {
        float a0 = g_attn[0], a1 = g_attn[1];
        float4 u = *((const float4*)(g_o_gg + (size_t)n * 128) + lane);
        v.x = a0 * v.x + a1 * u.x;
        v.y = a0 * v.y + a1 * u.y;
        v.z = a0 * v.z + a1 * u.z;
        v.w = a0 * v.w + a1 * u.w;
    }
    float s = v.x + v.y + v.z + v.w;
#pragma unroll
    for (int o = 16; o; o >>= 1) s += __shfl_xor_sync(0xffffffffu, s, o);
    float mu = s * (1.f / 128.f);
    float dx = v.x - mu, dy = v.y - mu, dz = v.z - mu, dw = v.w - mu;
    float qv = dx * dx + dy * dy + dz * dz + dw * dw;
#pragma unroll
    for (int o = 16; o; o >>= 1) qv += __shfl_xor_sync(0xffffffffu, qv, o);
    float rs = rsqrtf(qv * (1.f / 128.f) + 1e-5f);
    float4 g4 = *((const float4*)ln_gp + lane);
    float4 b4 = *((const float4*)ln_bp + lane);
    float4 r;
    r.x = dx * rs * g4.x + b4.x;
    r.y = dy * rs * g4.y + b4.y;
    r.z = dz * rs * g4.z + b4.z;
    r.w = dw * rs * g4.w + b4.w;
    if (prev) {
        float w0 = fw[0], w1 = fw[1];
        float inv = 1.f / (w0 + w1);
        float4 p = *((const float4*)(prev + (size_t)n * 128) + lane);
        r.x = (w0 * p.x + w1 * r.x) * inv;
        r.y = (w0 * p.y + w1 * r.y) * inv;
        r.z = (w0 * p.z + w1 * r.z) * inv;
        r.w = (w0 * p.w + w1 * r.w) * inv;
    }
    *((float4*)(out + (size_t)n * 128) + lane) = r;
}

static inline int cdiv(long a, int b) { return (int)((a + b - 1) / b); }

extern "C" void kernel_launch(void* const* d_in, const int* in_sizes, int n_in,
                              void* d_out, int out_size)
{
    const float* x_snp  = (const float*)d_in[0];
    const float* x_gene = (const float*)d_in[1];
    const float* Wp_snp = (const float*)d_in[2];
    const float* bp_snp = (const float*)d_in[3];
    const float* Wp_gene= (const float*)d_in[4];
    const float* bp_gene= (const float*)d_in[5];
    const float* a_src  = (const float*)d_in[6];
    const float* a_dst  = (const float*)d_in[7];
    const float* Wk     = (const float*)d_in[8];
    const float* bk     = (const float*)d_in[9];
    const float* qvp    = (const float*)d_in[10];
    const float* ln_g   = (const float*)d_in[11];
    const float* ln_b   = (const float*)d_in[12];
    const float* fw     = (const float*)d_in[13];
    const float* Wfp    = (const float*)d_in[14];
    const float* bfp    = (const float*)d_in[15];
    const float* Wo1    = (const float*)d_in[16];
    const float* bo1    = (const float*)d_in[17];
    const float* Wo2    = (const float*)d_in[18];
    const float* bo2    = (const float*)d_in[19];
    const int* sg_s = (const int*)d_in[20];
    const int* sg_d = (const int*)d_in[21];
    const int* gs_s = (const int*)d_in[22];
    const int* gs_d = (const int*)d_in[23];
    const int* gg_s = (const int*)d_in[24];
    const int* gg_d = (const int*)d_in[25];
    const int E_sg = in_sizes[20], E_gs = in_sizes[22], E_gg = in_sizes[24];

    __half *hsh, *hgh;
    float *o_sg, *o_gg, *out_s0, *out_g0, *sempart, *buf1, *buf2;
    float *ssrc_sg, *sdst_gs, *sdst_sg, *ssrc_gs, *ssrc_gg, *sdst_gg;
    unsigned char* wimg;
    cudaGetSymbolAddress((void**)&hsh, g_hsh);
    cudaGetSymbolAddress((void**)&hgh, g_hgh);
    cudaGetSymbolAddress((void**)&o_sg, g_o_sg);
    cudaGetSymbolAddress((void**)&o_gg, g_o_gg);
    cudaGetSymbolAddress((void**)&out_s0, g_out_s0);
    cudaGetSymbolAddress((void**)&out_g0, g_out_g0);
    cudaGetSymbolAddress((void**)&sempart, g_sempart);
    cudaGetSymbolAddress((void**)&buf1, g_buf1);
    cudaGetSymbolAddress((void**)&buf2, g_buf2);
    cudaGetSymbolAddress((void**)&wimg, g_wimg);
    cudaGetSymbolAddress((void**)&ssrc_sg, g_ssrc_sg);
    cudaGetSymbolAddress((void**)&sdst_gs, g_sdst_gs);
    cudaGetSymbolAddress((void**)&sdst_sg, g_sdst_sg);
    cudaGetSymbolAddress((void**)&ssrc_gs, g_ssrc_gs);
    cudaGetSymbolAddress((void**)&ssrc_gg, g_ssrc_gg);
    cudaGetSymbolAddress((void**)&sdst_gg, g_sdst_gg);

    cudaFuncSetAttribute(tgemm, cudaFuncAttributeMaxDynamicSharedMemorySize, TG_SMEM_TOTAL);

    wprep8<<<512, 256>>>(Wp_snp, Wp_snp + 16384, Wp_gene, Wp_gene + 16384,
                         Wk, Wk + 16384, Wfp, Wo1, wimg);

    const int E_tot = E_sg + E_gs + E_gg;
    zero_all<<<cdiv(2 * NSEG_TOT, 256), 256>>>();
    hist3<<<cdiv(E_tot, 256), 256>>>(sg_d, gs_d, gg_d, E_sg, E_gs, E_gg);
    bsum3<<<NB_TOT, 1024>>>();
    bscan3<<<1, 32>>>();
    scan3<<<NB_TOT, 1024>>>();
    scatter3<<<cdiv(E_tot, 256), 256>>>(sg_s, sg_d, gs_s, gs_d, gg_s, gg_d,
                                        E_sg, E_gs, E_gg);

    const int TS = cdiv(N_SNP, 128), TG = cdiv(N_GENE, 128), TA = cdiv(N_ALL, 128);

    for (int l = 0; l < 2; ++l) {
        const float* ins = l ? out_s0 : x_snp;
        const float* ing = l ? out_g0 : x_gene;

        tgemm<<<TS, 256, TG_SMEM_TOTAL>>>(ins, nullptr, wimg + (0 + l) * WIMGSZ,
            bp_snp + l * 128, nullptr, hsh,
            a_src + (l * 3 + 0) * 128, a_dst + (l * 3 + 1) * 128, nullptr, nullptr,
            ssrc_sg, sdst_gs, nullptr, nullptr,
            nullptr, nullptr, nullptr, N_SNP, 0, ACT_H);
        tgemm<<<TG, 256, TG_SMEM_TOTAL>>>(ing, nullptr, wimg + (2 + l) * WIMGSZ,
            bp_gene + l * 128, nullptr, hgh,
            a_dst + (l * 3 + 0) * 128, a_src + (l * 3 + 1) * 128,
            a_src + (l * 3 + 2) * 128, a_dst + (l * 3 + 2) * 128,
            sdst_sg, ssrc_gs, ssrc_gg, sdst_gg,
            nullptr, nullptr, nullptr, N_GENE, 0, ACT_H);

        agg3<<<cdiv(2 * N_GENE + N_SNP, 8), 256>>>(ln_g + l * 128, ln_b + l * 128, fw, l);

        tgemm<<<2 * TG, 256, TG_SMEM_TOTAL>>>(o_sg, o_gg, wimg + (4 + l) * WIMGSZ,
            bk + l * 128, sempart, nullptr,
            nullptr, nullptr, nullptr, nullptr,
            nullptr, nullptr, nullptr, nullptr,
            nullptr, nullptr, nullptr, N_GENE, TG, ACT_TANHSUM);
        sem_softmax2<<<1, 256>>>(qvp + l * 128);

        combine_all<<<cdiv((long)N_GENE * 32, 256), 256>>>(
            ln_g + l * 128, ln_b + l * 128, fw, l);
    }

    tgemm<<<TA, 256, TG_SMEM_TOTAL>>>(buf1, nullptr, wimg + 6 * WIMGSZ,
        bfp, buf2, nullptr,
        nullptr, nullptr, nullptr, nullptr,
        nullptr, nullptr, nullptr, nullptr,
        nullptr, nullptr, nullptr, N_ALL, 0, ACT_RELU);
    tgemm<<<TA, 256, TG_SMEM_TOTAL>>>(buf2, nullptr, wimg + 7 * WIMGSZ,
        bo1, nullptr, nullptr,
        nullptr, nullptr, nullptr, nullptr,
        nullptr, nullptr, nullptr, nullptr,
        Wo2, bo2, (float*)d_out, N_ALL, 0, ACT_OUT);
}

// round 10
// speedup vs baseline: 2.4199x; 1.0411x over previous
#include <cuda_runtime.h>
#include <cuda_bf16.h>
#include <cuda_fp16.h>
#include <cstdint>

#define N_SNP  100000
#define N_GENE 20000
#define N_ALL  120000
#define HID    128
#define NEG    0.2f

#define E_SG_MAX 500000
#define E_GS_MAX 500000
#define E_GG_MAX 150000

#define SEG_GS 20000
#define SEG_GG 120000
#define NSEG_TOT 140000
#define NB_SG 20
#define NB_GS 98
#define NB_GG 20
#define NB_TOT 138

#define TG_BLKS 157

#define WROW   272
#define WLO    34816
#define WIMGSZ 69632

// ---------------- device scratch ----------------
__device__ __half   g_hsh[N_SNP * HID];
__device__ __half   g_hgh[N_GENE * HID];
__device__ float    g_ssrc_sg[N_SNP * 8];
__device__ float    g_sdst_gs[N_SNP * 8];
__device__ float    g_sdst_sg[N_GENE * 8];
__device__ float    g_ssrc_gs[N_GENE * 8];
__device__ float    g_ssrc_gg[N_GENE * 8];
__device__ float    g_sdst_gg[N_GENE * 8];
__device__ float    g_o_sg[N_GENE * HID];
__device__ float    g_o_gg[N_GENE * HID];
__device__ float    g_out_s0[N_SNP * HID];
__device__ float    g_out_g0[N_GENE * HID];
__device__ float    g_sempart[2 * TG_BLKS * HID];
__device__ float    g_attn[2];
__device__ float    g_buf1[N_ALL * HID];
__device__ __align__(16) unsigned char g_wimg[8 * WIMGSZ];
__device__ int g_rp_sg[N_GENE + 1];
__device__ int g_rp_gs[N_SNP + 1];
__device__ int g_rp_gg[N_GENE + 1];
__device__ int g_dc[2 * NSEG_TOT];
__device__ int g_bsum[NB_TOT + 4];
__device__ int g_ss_sg[E_SG_MAX];
__device__ int g_ss_gs[E_GS_MAX];
__device__ int g_ss_gg[E_GG_MAX];

__device__ __forceinline__ uint32_t pack_bf(float x, float y) {
    __nv_bfloat162 t = __floats2bfloat162_rn(x, y);
    return *(uint32_t*)&t;
}
__device__ __forceinline__ void mma_bf16(float4& c, uint32_t a0, uint32_t a1,
                                         uint32_t a2, uint32_t a3,
                                         uint32_t b0, uint32_t b1) {
    asm volatile("mma.sync.aligned.m16n8k16.row.col.f32.bf16.bf16.f32 "
                 "{%0,%1,%2,%3}, {%4,%5,%6,%7}, {%8,%9}, {%0,%1,%2,%3};"
                 : "+f"(c.x), "+f"(c.y), "+f"(c.z), "+f"(c.w)
                 : "r"(a0), "r"(a1), "r"(a2), "r"(a3), "r"(b0), "r"(b1));
}

// Core GEMM: 16-row strip pair per warp from gmem fp32 A vs smem weight image.
__device__ __forceinline__ void gemm_core(
    const float* __restrict__ A, int rowA, int rowB, bool vA, bool vB,
    const unsigned char* sm, int lane, float4 acc[16])
{
    const int g = lane >> 2, tig = lane & 3;
    const float* ArA = A + (size_t)rowA * 128;
    const float* ArB = A + (size_t)rowB * 128;
#pragma unroll
    for (int ks = 0; ks < 8; ks++) {
        const int k0 = ks * 16;
        float2 p00 = make_float2(0.f, 0.f), p01 = p00, p10 = p00, p11 = p00;
        if (vA) {
            p00 = *(const float2*)(ArA + k0 + 2 * tig);
            p01 = *(const float2*)(ArA + k0 + 2 * tig + 8);
        }
        if (vB) {
            p10 = *(const float2*)(ArB + k0 + 2 * tig);
            p11 = *(const float2*)(ArB + k0 + 2 * tig + 8);
        }
        uint32_t ah0 = pack_bf(p00.x, p00.y), ah1 = pack_bf(p10.x, p10.y);
        uint32_t ah2 = pack_bf(p01.x, p01.y), ah3 = pack_bf(p11.x, p11.y);
        __nv_bfloat162 h00 = *(__nv_bfloat162*)&ah0, h10 = *(__nv_bfloat162*)&ah1;
        __nv_bfloat162 h01 = *(__nv_bfloat162*)&ah2, h11 = *(__nv_bfloat162*)&ah3;
        uint32_t al0 = pack_bf(p00.x - __bfloat162float(h00.x), p00.y - __bfloat162float(h00.y));
        uint32_t al1 = pack_bf(p10.x - __bfloat162float(h10.x), p10.y - __bfloat162float(h10.y));
        uint32_t al2 = pack_bf(p01.x - __bfloat162float(h01.x), p01.y - __bfloat162float(h01.y));
        uint32_t al3 = pack_bf(p11.x - __bfloat162float(h11.x), p11.y - __bfloat162float(h11.y));

        const unsigned char* bh = sm + (size_t)g * WROW + (k0 + 2 * tig) * 2;
#pragma unroll
        for (int nt = 0; nt < 16; nt++) {
            uint32_t bh0 = *(const uint32_t*)(bh + nt * 8 * WROW);
            uint32_t bh1 = *(const uint32_t*)(bh + nt * 8 * WROW + 16);
            mma_bf16(acc[nt], ah0, ah1, ah2, ah3, bh0, bh1);
            mma_bf16(acc[nt], al0, al1, al2, al3, bh0, bh1);
            uint32_t bl0 = *(const uint32_t*)(bh + WLO + nt * 8 * WROW);
            uint32_t bl1 = *(const uint32_t*)(bh + WLO + nt * 8 * WROW + 16);
            mma_bf16(acc[nt], ah0, ah1, ah2, ah3, bl0, bl1);
        }
    }
}

// Second GEMM with A operand coming from register accumulators (fragment layout match).
__device__ __forceinline__ void gemm_core_reg(
    const float4 a1[16], const unsigned char* sm, int lane, float4 acc[16])
{
    const int g = lane >> 2, tig = lane & 3;
#pragma unroll
    for (int kt = 0; kt < 8; kt++) {
        float x0 = a1[2*kt].x,   y0 = a1[2*kt].y;
        float x1 = a1[2*kt].z,   y1 = a1[2*kt].w;
        float x2 = a1[2*kt+1].x, y2 = a1[2*kt+1].y;
        float x3 = a1[2*kt+1].z, y3 = a1[2*kt+1].w;
        uint32_t ah0 = pack_bf(x0, y0), ah1 = pack_bf(x1, y1);
        uint32_t ah2 = pack_bf(x2, y2), ah3 = pack_bf(x3, y3);
        __nv_bfloat162 h0 = *(__nv_bfloat162*)&ah0, h1 = *(__nv_bfloat162*)&ah1;
        __nv_bfloat162 h2 = *(__nv_bfloat162*)&ah2, h3 = *(__nv_bfloat162*)&ah3;
        uint32_t al0 = pack_bf(x0 - __bfloat162float(h0.x), y0 - __bfloat162float(h0.y));
        uint32_t al1 = pack_bf(x1 - __bfloat162float(h1.x), y1 - __bfloat162float(h1.y));
        uint32_t al2 = pack_bf(x2 - __bfloat162float(h2.x), y2 - __bfloat162float(h2.y));
        uint32_t al3 = pack_bf(x3 - __bfloat162float(h3.x), y3 - __bfloat162float(h3.y));

        const unsigned char* bh = sm + (size_t)g * WROW + (kt * 16 + 2 * tig) * 2;
#pragma unroll
        for (int nt = 0; nt < 16; nt++) {
            uint32_t bh0 = *(const uint32_t*)(bh + nt * 8 * WROW);
            uint32_t bh1 = *(const uint32_t*)(bh + nt * 8 * WROW + 16);
            mma_bf16(acc[nt], ah0, ah1, ah2, ah3, bh0, bh1);
            mma_bf16(acc[nt], al0, al1, al2, al3, bh0, bh1);
            uint32_t bl0 = *(const uint32_t*)(bh + WLO + nt * 8 * WROW);
            uint32_t bl1 = *(const uint32_t*)(bh + WLO + nt * 8 * WROW + 16);
            mma_bf16(acc[nt], ah0, ah1, ah2, ah3, bl0, bl1);
        }
    }
}

// ---------------- CSR build (batched over 3 edge types) ----------------
__global__ void zero_all() {
    int i = blockIdx.x * 256 + threadIdx.x;
    if (i < 2 * NSEG_TOT) g_dc[i] = 0;
}
__global__ void hist3(const int* __restrict__ d1, const int* __restrict__ d2,
                      const int* __restrict__ d3, int E1, int E2, int E3) {
    int i = blockIdx.x * 256 + threadIdx.x;
    if (i < E1) atomicAdd(g_dc + d1[i], 1);
    else if (i < E1 + E2) atomicAdd(g_dc + SEG_GS + d2[i - E1], 1);
    else if (i < E1 + E2 + E3) atomicAdd(g_dc + SEG_GG + d3[i - E1 - E2], 1);
}
__device__ __forceinline__ void seg_map(int b, int& degoff, int& nd, int& boff, int& lb) {
    if (b < NB_SG)            { degoff = 0;      nd = N_GENE; boff = 0;             lb = b; }
    else if (b < NB_SG+NB_GS) { degoff = SEG_GS; nd = N_SNP;  boff = NB_SG;         lb = b - NB_SG; }
    else                      { degoff = SEG_GG; nd = N_GENE; boff = NB_SG + NB_GS; lb = b - NB_SG - NB_GS; }
}
__global__ void bsum3() {
    __shared__ int sw[32];
    int degoff, nd, boff, lb;
    seg_map(blockIdx.x, degoff, nd, boff, lb);
    int i = lb * 1024 + threadIdx.x;
    int v = (i < nd) ? g_dc[degoff + i] : 0;
#pragma unroll
    for (int o = 16; o; o >>= 1) v += __shfl_xor_sync(0xffffffffu, v, o);
    if ((threadIdx.x & 31) == 0) sw[threadIdx.x >> 5] = v;
    __syncthreads();
    if (threadIdx.x < 32) {
        int t = sw[threadIdx.x];
#pragma unroll
        for (int o = 16; o; o >>= 1) t += __shfl_xor_sync(0xffffffffu, t, o);
        if (threadIdx.x == 0) g_bsum[boff + lb] = t;
    }
}
__global__ void bscan3() {
    if (threadIdx.x == 0) {
        const int off[3] = {0, NB_SG, NB_SG + NB_GS};
        const int nb[3] = {NB_SG, NB_GS, NB_GG};
        for (int s = 0; s < 3; s++) {
            int c = 0;
            for (int i = 0; i < nb[s]; i++) {
                int v = g_bsum[off[s] + i];
                g_bsum[off[s] + i] = c;
                c += v;
            }
        }
    }
}
__global__ void scan3() {
    __shared__ int sm[1024];
    int degoff, nd, boff, lb;
    seg_map(blockIdx.x, degoff, nd, boff, lb);
    int* rp = (blockIdx.x < NB_SG) ? g_rp_sg
            : (blockIdx.x < NB_SG + NB_GS) ? g_rp_gs : g_rp_gg;
    int tid = threadIdx.x;
    int i = lb * 1024 + tid;
    int v = (i < nd) ? g_dc[degoff + i] : 0;
    sm[tid] = v;
    __syncthreads();
#pragma unroll
    for (int off = 1; off < 1024; off <<= 1) {
        int t = (tid >= off) ? sm[tid - off] : 0;
        __syncthreads();
        sm[tid] += t;
        __syncthreads();
    }
    int incl = sm[tid];
    int base = g_bsum[boff + lb];
    if (i < nd) rp[i] = base + incl - v;
    if (i == nd - 1) rp[nd] = base + incl;
}
__global__ void scatter3(const int* __restrict__ s1, const int* __restrict__ d1,
                         const int* __restrict__ s2, const int* __restrict__ d2,
                         const int* __restrict__ s3, const int* __restrict__ d3,
                         int E1, int E2, int E3) {
    int i = blockIdx.x * 256 + threadIdx.x;
    if (i < E1) {
        int d = d1[i];
        g_ss_sg[g_rp_sg[d] + atomicAdd(g_dc + NSEG_TOT + d, 1)] = s1[i];
    } else if (i < E1 + E2) {
        int e = i - E1, d = d2[e];
        g_ss_gs[g_rp_gs[d] + atomicAdd(g_dc + NSEG_TOT + SEG_GS + d, 1)] = s2[e];
    } else if (i < E1 + E2 + E3) {
        int e = i - E1 - E2, d = d3[e];
        g_ss_gg[g_rp_gg[d] + atomicAdd(g_dc + NSEG_TOT + SEG_GG + d, 1)] = s3[e];
    }
}

// ---------------- weight prep: all 8 matrices in one launch ----------------
__global__ void wprep8(const float* __restrict__ W0, const float* __restrict__ W1,
                       const float* __restrict__ W2, const float* __restrict__ W3,
                       const float* __restrict__ W4, const float* __restrict__ W5,
                       const float* __restrict__ W6, const float* __restrict__ W7,
                       unsigned char* __restrict__ imgbase) {
    int b = blockIdx.x >> 6;
    const float* W;
    if      (b == 0) W = W0; else if (b == 1) W = W1;
    else if (b == 2) W = W2; else if (b == 3) W = W3;
    else if (b == 4) W = W4; else if (b == 5) W = W5;
    else if (b == 6) W = W6; else              W = W7;
    unsigned char* img = imgbase + (size_t)b * WIMGSZ;
    int i = (blockIdx.x & 63) * 256 + threadIdx.x;
    int n = i >> 7, k = i & 127;
    float w = W[k * 128 + n];
    __nv_bfloat16 h = __float2bfloat16(w);
    __nv_bfloat16 l = __float2bfloat16(w - __bfloat162float(h));
    *(uint16_t*)(img + n * WROW + k * 2) = __bfloat16_as_ushort(h);
    *(uint16_t*)(img + WLO + n * WROW + k * 2) = __bfloat16_as_ushort(l);
}

// ---------------- merged projection GEMM: snp + gene in one launch ----------------
// blocks [0,nsblk): snp -> g_hsh + 2 score sets; blocks [nsblk,..): gene -> g_hgh + 4 sets.
#define TG_SMEM1 (WIMGSZ + 16)

__global__ void __launch_bounds__(256) proj_h(
    const float* __restrict__ As, const float* __restrict__ Ag,
    const unsigned char* __restrict__ imgS, const unsigned char* __restrict__ imgG,
    const float* __restrict__ bS, const float* __restrict__ bG,
    const float* __restrict__ a_src, const float* __restrict__ a_dst,
    int l, int nsblk)
{
    extern __shared__ unsigned char smem[];
    const int tid = threadIdx.x, wid = tid >> 5, lane = tid & 31;
    const int g = lane >> 2, tig = lane & 3;
    const bool is_snp = blockIdx.x < nsblk;
    const int blk = is_snp ? blockIdx.x : blockIdx.x - nsblk;
    const float* A = is_snp ? As : Ag;
    const unsigned char* Bimg = is_snp ? imgS : imgG;
    const float* bias = is_snp ? bS : bG;
    const int M = is_snp ? N_SNP : N_GENE;
    __half* Ch = is_snp ? g_hsh : g_hgh;

    {
        const uint4* src = (const uint4*)Bimg;
        uint4* dst = (uint4*)smem;
#pragma unroll
        for (int i = 0; i < 17; i++) {
            int idx = tid + 256 * i;
            if (idx < WIMGSZ / 16) dst[idx] = src[idx];
        }
    }
    __syncthreads();

    const int rowA = blk * 128 + wid * 16 + g;
    const int rowB = rowA + 8;
    const bool vA = rowA < M, vB = rowB < M;

    float4 acc[16];
#pragma unroll
    for (int nt = 0; nt < 16; nt++) acc[nt] = make_float4(0.f, 0.f, 0.f, 0.f);
    gemm_core(A, rowA, rowB, vA, vB, smem, lane, acc);

#pragma unroll
    for (int nt = 0; nt < 16; nt++) {
        int col = nt * 8 + 2 * tig;
        float b0 = bias[col], b1 = bias[col + 1];
        acc[nt].x += b0; acc[nt].y += b1;
        acc[nt].z += b0; acc[nt].w += b1;
    }

#pragma unroll
    for (int nt = 0; nt < 16; nt++) {
        int col = nt * 8 + 2 * tig;
        if (vA) *((__half2*)(Ch + (size_t)rowA * 128 + col)) = __floats2half2_rn(acc[nt].x, acc[nt].y);
        if (vB) *((__half2*)(Ch + (size_t)rowB * 128 + col)) = __floats2half2_rn(acc[nt].z, acc[nt].w);
    }

    const float* vv[4];
    float* sb[4];
    int nv;
    if (is_snp) {
        nv = 2;
        vv[0] = a_src + (l * 3 + 0) * 128; sb[0] = g_ssrc_sg;
        vv[1] = a_dst + (l * 3 + 1) * 128; sb[1] = g_sdst_gs;
        vv[2] = nullptr; vv[3] = nullptr;
    } else {
        nv = 4;
        vv[0] = a_dst + (l * 3 + 0) * 128; sb[0] = g_sdst_sg;
        vv[1] = a_src + (l * 3 + 1) * 128; sb[1] = g_ssrc_gs;
        vv[2] = a_src + (l * 3 + 2) * 128; sb[2] = g_ssrc_gg;
        vv[3] = a_dst + (l * 3 + 2) * 128; sb[3] = g_sdst_gg;
    }
#pragma unroll
    for (int v = 0; v < 4; v++) {
        if (v < nv) {
#pragma unroll
            for (int hd = 0; hd < 8; hd++) {
                float a0 = __ldg(vv[v] + 16 * hd + 2 * tig);
                float a1 = __ldg(vv[v] + 16 * hd + 2 * tig + 1);
                float a2 = __ldg(vv[v] + 16 * hd + 8 + 2 * tig);
                float a3 = __ldg(vv[v] + 16 * hd + 8 + 2 * tig + 1);
                float pA = acc[2*hd].x * a0 + acc[2*hd].y * a1
                         + acc[2*hd+1].x * a2 + acc[2*hd+1].y * a3;
                float pB = acc[2*hd].z * a0 + acc[2*hd].w * a1
                         + acc[2*hd+1].z * a2 + acc[2*hd+1].w * a3;
                pA += __shfl_xor_sync(0xffffffffu, pA, 1);
                pA += __shfl_xor_sync(0xffffffffu, pA, 2);
                pB += __shfl_xor_sync(0xffffffffu, pB, 1);
                pB += __shfl_xor_sync(0xffffffffu, pB, 2);
                if (tig == 0) {
                    if (vA) sb[v][rowA * 8 + hd] = pA;
                    if (vB) sb[v][rowB * 8 + hd] = pB;
                }
            }
        }
    }
}

// ---------------- semantic GEMM: tanh colsum partials (o_sg | o_gg merged) ----------
#define TG_SMEM_SEM (WIMGSZ + 512)

__global__ void __launch_bounds__(256) tgemm_sem(
    const unsigned char* __restrict__ Bimg, const float* __restrict__ bias, int nhalf)
{
    extern __shared__ unsigned char smem[];
    float* scs = (float*)(smem + WIMGSZ);
    const int tid = threadIdx.x, wid = tid >> 5, lane = tid & 31;
    const int g = lane >> 2, tig = lane & 3;
    int blk = blockIdx.x;
    const float* A = g_o_sg;
    if (blk >= nhalf) { A = g_o_gg; blk -= nhalf; }

    {
        const uint4* src = (const uint4*)Bimg;
        uint4* dst = (uint4*)smem;
#pragma unroll
        for (int i = 0; i < 17; i++) {
            int idx = tid + 256 * i;
            if (idx < WIMGSZ / 16) dst[idx] = src[idx];
        }
    }
    if (tid < 128) scs[tid] = 0.f;
    __syncthreads();

    const int rowA = blk * 128 + wid * 16 + g;
    const int rowB = rowA + 8;
    const bool vA = rowA < N_GENE, vB = rowB < N_GENE;

    float4 acc[16];
#pragma unroll
    for (int nt = 0; nt < 16; nt++) acc[nt] = make_float4(0.f, 0.f, 0.f, 0.f);
    gemm_core(A, rowA, rowB, vA, vB, smem, lane, acc);

#pragma unroll
    for (int nt = 0; nt < 16; nt++) {
        int col = nt * 8 + 2 * tig;
        float b0 = bias[col], b1 = bias[col + 1];
        float s0 = 0.f, s1 = 0.f;
        if (vA) { s0 += tanhf(acc[nt].x + b0); s1 += tanhf(acc[nt].y + b1); }
        if (vB) { s0 += tanhf(acc[nt].z + b0); s1 += tanhf(acc[nt].w + b1); }
        atomicAdd(scs + col, s0);
        atomicAdd(scs + col + 1, s1);
    }
    __syncthreads();
    if (tid < 128) g_sempart[(size_t)blockIdx.x * 128 + tid] = scs[tid];
}

// ---------------- final fused MLP: out = relu(relu(A@Wfp+bfp)@Wo1+bo1)@Wo2+bo2 ------
#define TG_SMEM_FIN (2 * WIMGSZ)

__global__ void __launch_bounds__(256) final2(
    const float* __restrict__ A,
    const unsigned char* __restrict__ img1, const unsigned char* __restrict__ img2,
    const float* __restrict__ b1, const float* __restrict__ b2v,
    const float* __restrict__ W2, const float* __restrict__ b2,
    float* __restrict__ outp, int M)
{
    extern __shared__ unsigned char smem[];
    const int tid = threadIdx.x, wid = tid >> 5, lane = tid & 31;
    const int g = lane >> 2, tig = lane & 3;

    {
        const uint4* s1 = (const uint4*)img1;
        const uint4* s2 = (const uint4*)img2;
        uint4* d1 = (uint4*)smem;
        uint4* d2 = (uint4*)(smem + WIMGSZ);
#pragma unroll
        for (int i = 0; i < 17; i++) {
            int idx = tid + 256 * i;
            if (idx < WIMGSZ / 16) { d1[idx] = s1[idx]; d2[idx] = s2[idx]; }
        }
    }
    __syncthreads();

    const int rowA = blockIdx.x * 128 + wid * 16 + g;
    const int rowB = rowA + 8;
    const bool vA = rowA < M, vB = rowB < M;

    float4 acc[16];
#pragma unroll
    for (int nt = 0; nt < 16; nt++) acc[nt] = make_float4(0.f, 0.f, 0.f, 0.f);
    gemm_core(A, rowA, rowB, vA, vB, smem, lane, acc);

    // bias + relu (hidden 1)
#pragma unroll
    for (int nt = 0; nt < 16; nt++) {
        int col = nt * 8 + 2 * tig;
        float c0 = b1[col], c1 = b1[col + 1];
        acc[nt].x = fmaxf(acc[nt].x + c0, 0.f);
        acc[nt].y = fmaxf(acc[nt].y + c1, 0.f);
        acc[nt].z = fmaxf(acc[nt].z + c0, 0.f);
        acc[nt].w = fmaxf(acc[nt].w + c1, 0.f);
    }

    // second GEMM from registers
    float4 acc2[16];
#pragma unroll
    for (int nt = 0; nt < 16; nt++) acc2[nt] = make_float4(0.f, 0.f, 0.f, 0.f);
    gemm_core_reg(acc, smem + WIMGSZ, lane, acc2);

    // bias + relu (hidden 2), then 128->2 projection
    float pA0 = 0.f, pA1 = 0.f, pB0 = 0.f, pB1 = 0.f;
#pragma unroll
    for (int nt = 0; nt < 16; nt++) {
        int col = nt * 8 + 2 * tig;
        float c0 = b2v[col], c1 = b2v[col + 1];
        float rx = fmaxf(acc2[nt].x + c0, 0.f), ry = fmaxf(acc2[nt].y + c1, 0.f);
        float rz = fmaxf(acc2[nt].z + c0, 0.f), rw = fmaxf(acc2[nt].w + c1, 0.f);
        float w00 = __ldg(W2 + col * 2), w01 = __ldg(W2 + col * 2 + 1);
        float w10 = __ldg(W2 + (col + 1) * 2), w11 = __ldg(W2 + (col + 1) * 2 + 1);
        pA0 += rx * w00 + ry * w10; pA1 += rx * w01 + ry * w11;
        pB0 += rz * w00 + rw * w10; pB1 += rz * w01 + rw * w11;
    }
    pA0 += __shfl_xor_sync(0xffffffffu, pA0, 1); pA0 += __shfl_xor_sync(0xffffffffu, pA0, 2);
    pA1 += __shfl_xor_sync(0xffffffffu, pA1, 1); pA1 += __shfl_xor_sync(0xffffffffu, pA1, 2);
    pB0 += __shfl_xor_sync(0xffffffffu, pB0, 1); pB0 += __shfl_xor_sync(0xffffffffu, pB0, 2);
    pB1 += __shfl_xor_sync(0xffffffffu, pB1, 1); pB1 += __shfl_xor_sync(0xffffffffu, pB1, 2);
    if (tig == 0) {
        if (vA) { outp[(size_t)rowA * 2] = pA0 + b2[0]; outp[(size_t)rowA * 2 + 1] = pA1 + b2[1]; }
        if (vB) { outp[(size_t)rowB * 2] = pB0 + b2[0]; outp[(size_t)rowB * 2 + 1] = pB1 + b2[1]; }
    }
}

// ---------------- CSR aggregation: half-warp per edge, fused snp LN ----------------
__global__ void __launch_bounds__(256) agg3(
    const float* __restrict__ ln_gp, const float* __restrict__ ln_bp,
    const float* __restrict__ fw, int layer1)
{
    int w = blockIdx.x * 8 + (threadIdx.x >> 5);
    const __half* hsrc;
    const float *ssrc, *sdst;
    const int *rp, *ss;
    float* out;
    const float* prev = nullptr;
    int d;
    bool fuse = false;
    if (w < N_GENE) {
        d = w; hsrc = g_hsh; ssrc = g_ssrc_sg; sdst = g_sdst_sg;
        rp = g_rp_sg; ss = g_ss_sg; out = g_o_sg;
    } else if (w < N_GENE + N_SNP) {
        d = w - N_GENE; hsrc = g_hgh; ssrc = g_ssrc_gs; sdst = g_sdst_gs;
        rp = g_rp_gs; ss = g_ss_gs;
        fuse = true;
        prev = layer1 ? g_out_s0 : nullptr;
        out = layer1 ? g_buf1 : g_out_s0;
    } else if (w < 2 * N_GENE + N_SNP) {
        d = w - (N_GENE + N_SNP); hsrc = g_hgh; ssrc = g_ssrc_gg; sdst = g_sdst_gg;
        rp = g_rp_gg; ss = g_ss_gg; out = g_o_gg;
    } else return;

    const int lane = threadIdx.x & 31, hw = lane >> 4, l16 = lane & 15, hd = l16 >> 1;
    float sdh = __ldg(sdst + d * 8 + hd);
    int beg = __ldg(rp + d), end = __ldg(rp + d + 1);

    float acc[8];
#pragma unroll
    for (int j = 0; j < 8; j++) acc[j] = 0.f;
    float se = 0.f;

#pragma unroll 2
    for (int i = beg; i < end; i += 2) {
        int ii = i + hw;
        if (ii < end) {
            int s = __ldg(ss + ii);
            float a = __ldg(ssrc + s * 8 + hd) + sdh;
            uint4 u = *((const uint4*)(hsrc + (size_t)s * 128) + l16);
            a = a > 0.f ? a : NEG * a;
            float e = __expf(a);
            float2 f0 = __half22float2(*(__half2*)&u.x);
            float2 f1 = __half22float2(*(__half2*)&u.y);
            float2 f2 = __half22float2(*(__half2*)&u.z);
            float2 f3 = __half22float2(*(__half2*)&u.w);
            acc[0] = fmaf(e, f0.x, acc[0]); acc[1] = fmaf(e, f0.y, acc[1]);
            acc[2] = fmaf(e, f1.x, acc[2]); acc[3] = fmaf(e, f1.y, acc[3]);
            acc[4] = fmaf(e, f2.x, acc[4]); acc[5] = fmaf(e, f2.y, acc[5]);
            acc[6] = fmaf(e, f3.x, acc[6]); acc[7] = fmaf(e, f3.y, acc[7]);
            se += e;
        }
    }
    se += __shfl_xor_sync(0xffffffffu, se, 16);
#pragma unroll
    for (int j = 0; j < 8; j++) acc[j] += __shfl_xor_sync(0xffffffffu, acc[j], 16);
    float inv = 1.f / (se + 1e-16f);
    float r[8];
#pragma unroll
    for (int j = 0; j < 8; j++) r[j] = fmaxf(acc[j] * inv, 0.f);

    if (!fuse) {
        if (hw == 0) {
            float4* op = (float4*)(out + (size_t)d * 128 + l16 * 8);
            op[0] = make_float4(r[0], r[1], r[2], r[3]);
            op[1] = make_float4(r[4], r[5], r[6], r[7]);
        }
        return;
    }

    float ps = r[0] + r[1] + r[2] + r[3] + r[4] + r[5] + r[6] + r[7];
#pragma unroll
    for (int o = 8; o; o >>= 1) ps += __shfl_xor_sync(0xffffffffu, ps, o);
    float mu = ps * (1.f / 128.f);
    float pv = 0.f;
#pragma unroll
    for (int j = 0; j < 8; j++) { float dl = r[j] - mu; pv += dl * dl; }
#pragma unroll
    for (int o = 8; o; o >>= 1) pv += __shfl_xor_sync(0xffffffffu, pv, o);
    float rs = rsqrtf(pv * (1.f / 128.f) + 1e-5f);
    if (hw == 0) {
        float4 g0 = __ldg((const float4*)ln_gp + l16 * 2);
        float4 g1 = __ldg((const float4*)ln_gp + l16 * 2 + 1);
        float4 b0 = __ldg((const float4*)ln_bp + l16 * 2);
        float4 b1 = __ldg((const float4*)ln_bp + l16 * 2 + 1);
        float4 o0, o1;
        o0.x = (r[0] - mu) * rs * g0.x + b0.x;
        o0.y = (r[1] - mu) * rs * g0.y + b0.y;
        o0.z = (r[2] - mu) * rs * g0.z + b0.z;
        o0.w = (r[3] - mu) * rs * g0.w + b0.w;
        o1.x = (r[4] - mu) * rs * g1.x + b1.x;
        o1.y = (r[5] - mu) * rs * g1.y + b1.y;
        o1.z = (r[6] - mu) * rs * g1.z + b1.z;
        o1.w = (r[7] - mu) * rs * g1.w + b1.w;
        if (prev) {
            float w0 = fw[0], w1 = fw[1];
            float iw = 1.f / (w0 + w1);
            float4 p0 = *((const float4*)(prev + (size_t)d * 128 + l16 * 8));
            float4 p1 = *((const float4*)(prev + (size_t)d * 128 + l16 * 8) + 1);
            o0.x = (w0 * p0.x + w1 * o0.x) * iw;
            o0.y = (w0 * p0.y + w1 * o0.y) * iw;
            o0.z = (w0 * p0.z + w1 * o0.z) * iw;
            o0.w = (w0 * p0.w + w1 * o0.w) * iw;
            o1.x = (w0 * p1.x + w1 * o1.x) * iw;
            o1.y = (w0 * p1.y + w1 * o1.y) * iw;
            o1.z = (w0 * p1.z + w1 * o1.z) * iw;
            o1.w = (w0 * p1.w + w1 * o1.w) * iw;
        }
        float4* op = (float4*)(out + (size_t)d * 128 + l16 * 8);
        op[0] = o0; op[1] = o1;
    }
}

// ---------------- semantic softmax ----------------
__global__ void sem_softmax2(const float* __restrict__ q)
{
    __shared__ float sw[8];
    int m = threadIdx.x >> 7, col = threadIdx.x & 127;
    float s = 0.f;
    const float* part = g_sempart + (size_t)m * TG_BLKS * 128 + col;
    for (int b = 0; b < TG_BLKS; b++) s += part[b * 128];
    float v = q[col] * (s / 20000.f);
    int lane = threadIdx.x & 31;
#pragma unroll
    for (int o = 16; o; o >>= 1) v += __shfl_xor_sync(0xffffffffu, v, o);
    if (lane == 0) sw[threadIdx.x >> 5] = v;
    __syncthreads();
    if (threadIdx.x == 0) {
        float s0 = sw[0] + sw[1] + sw[2] + sw[3];
        float s1 = sw[4] + sw[5] + sw[6] + sw[7];
        float mx = fmaxf(s0, s1);
        float e0 = __expf(s0 - mx), e1 = __expf(s1 - mx);
        float inv = 1.f / (e0 + e1);
        g_attn[0] = e0 * inv; g_attn[1] = e1 * inv;
    }
}

// ---------------- gene combine + LayerNorm (+ layer fusion) ----------------
__global__ void __launch_bounds__(256) combine_all(
    const float* __restrict__ ln_gp, const float* __restrict__ ln_bp,
    const float* __restrict__ fw, int layer1)
{
    int idx = blockIdx.x * blockDim.x + threadIdx.x;
    int n = idx >> 5, lane = idx & 31;
    if (n >= N_GENE) return;
    const float* prev = layer1 ? g_out_g0 : nullptr;
    float* out = layer1 ? (g_buf1 + (size_t)N_SNP * 128) : g_out_g0;
    float4 v = *((const float4*)(g_o_sg + (size_t)n * 128) + lane);
    {
        float a0 = g_attn[0], a1 = g_attn[1];
        float4 u = *((const float4*)(g_o_gg + (size_t)n * 128) + lane);
        v.x = a0 * v.x + a1 * u.x;
        v.y = a0 * v.y + a1 * u.y;
        v.z = a0 * v.z + a1 * u.z;
        v.w = a0 * v.w + a1 * u.w;
    }
    float s = v.x + v.y + v.z + v.w;
#pragma unroll
    for (int o = 16; o; o >>= 1) s += __shfl_xor_sync(0xffffffffu, s, o);
    float mu = s * (1.f / 128.f);
    float dx = v.x - mu, dy = v.y - mu, dz = v.z - mu, dw = v.w - mu;
    float qv = dx * dx + dy * dy + dz * dz + dw * dw;
#pragma unroll
    for (int o = 16; o; o >>= 1) qv += __shfl_xor_sync(0xffffffffu, qv, o);
    float rs = rsqrtf(qv * (1.f / 128.f) + 1e-5f);
    float4 g4 = *((const float4*)ln_gp + lane);
    float4 b4 = *((const float4*)ln_bp + lane);
    float4 r;
    r.x = dx * rs * g4.x + b4.x;
    r.y = dy * rs * g4.y + b4.y;
    r.z = dz * rs * g4.z + b4.z;
    r.w = dw * rs * g4.w + b4.w;
    if (prev) {
        float w0 = fw[0], w1 = fw[1];
        float inv = 1.f / (w0 + w1);
        float4 p = *((const float4*)(prev + (size_t)n * 128) + lane);
        r.x = (w0 * p.x + w1 * r.x) * inv;
        r.y = (w0 * p.y + w1 * r.y) * inv;
        r.z = (w0 * p.z + w1 * r.z) * inv;
        r.w = (w0 * p.w + w1 * r.w) * inv;
    }
    *((float4*)(out + (size_t)n * 128) + lane) = r;
}

static inline int cdiv(long a, int b) { return (int)((a + b - 1) / b); }

extern "C" void kernel_launch(void* const* d_in, const int* in_sizes, int n_in,
                              void* d_out, int out_size)
{
    const float* x_snp  = (const float*)d_in[0];
    const float* x_gene = (const float*)d_in[1];
    const float* Wp_snp = (const float*)d_in[2];
    const float* bp_snp = (const float*)d_in[3];
    const float* Wp_gene= (const float*)d_in[4];
    const float* bp_gene= (const float*)d_in[5];
    const float* a_src  = (const float*)d_in[6];
    const float* a_dst  = (const float*)d_in[7];
    const float* Wk     = (const float*)d_in[8];
    const float* bk     = (const float*)d_in[9];
    const float* qvp    = (const float*)d_in[10];
    const float* ln_g   = (const float*)d_in[11];
    const float* ln_b   = (const float*)d_in[12];
    const float* fw     = (const float*)d_in[13];
    const float* Wfp    = (const float*)d_in[14];
    const float* bfp    = (const float*)d_in[15];
    const float* Wo1    = (const float*)d_in[16];
    const float* bo1    = (const float*)d_in[17];
    const float* Wo2    = (const float*)d_in[18];
    const float* bo2    = (const float*)d_in[19];
    const int* sg_s = (const int*)d_in[20];
    const int* sg_d = (const int*)d_in[21];
    const int* gs_s = (const int*)d_in[22];
    const int* gs_d = (const int*)d_in[23];
    const int* gg_s = (const int*)d_in[24];
    const int* gg_d = (const int*)d_in[25];
    const int E_sg = in_sizes[20], E_gs = in_sizes[22], E_gg = in_sizes[24];

    float *out_s0, *out_g0, *buf1;
    unsigned char* wimg;
    cudaGetSymbolAddress((void**)&out_s0, g_out_s0);
    cudaGetSymbolAddress((void**)&out_g0, g_out_g0);
    cudaGetSymbolAddress((void**)&buf1, g_buf1);
    cudaGetSymbolAddress((void**)&wimg, g_wimg);

    cudaFuncSetAttribute(proj_h, cudaFuncAttributeMaxDynamicSharedMemorySize, TG_SMEM1);
    cudaFuncSetAttribute(tgemm_sem, cudaFuncAttributeMaxDynamicSharedMemorySize, TG_SMEM_SEM);
    cudaFuncSetAttribute(final2, cudaFuncAttributeMaxDynamicSharedMemorySize, TG_SMEM_FIN);

    wprep8<<<512, 256>>>(Wp_snp, Wp_snp + 16384, Wp_gene, Wp_gene + 16384,
                         Wk, Wk + 16384, Wfp, Wo1, wimg);

    const int E_tot = E_sg + E_gs + E_gg;
    zero_all<<<cdiv(2 * NSEG_TOT, 256), 256>>>();
    hist3<<<cdiv(E_tot, 256), 256>>>(sg_d, gs_d, gg_d, E_sg, E_gs, E_gg);
    bsum3<<<NB_TOT, 1024>>>();
    bscan3<<<1, 32>>>();
    scan3<<<NB_TOT, 1024>>>();
    scatter3<<<cdiv(E_tot, 256), 256>>>(sg_s, sg_d, gs_s, gs_d, gg_s, gg_d,
                                        E_sg, E_gs, E_gg);

    const int TS = cdiv(N_SNP, 128), TG = cdiv(N_GENE, 128), TA = cdiv(N_ALL, 128);

    for (int l = 0; l < 2; ++l) {
        const float* ins = l ? out_s0 : x_snp;
        const float* ing = l ? out_g0 : x_gene;

        proj_h<<<TS + TG, 256, TG_SMEM1>>>(ins, ing,
            wimg + l * WIMGSZ, wimg + (2 + l) * WIMGSZ,
            bp_snp + l * 128, bp_gene + l * 128, a_src, a_dst, l, TS);

        agg3<<<cdiv(2 * N_GENE + N_SNP, 8), 256>>>(ln_g + l * 128, ln_b + l * 128, fw, l);

        tgemm_sem<<<2 * TG, 256, TG_SMEM_SEM>>>(wimg + (4 + l) * WIMGSZ, bk + l * 128, TG);
        sem_softmax2<<<1, 256>>>(qvp + l * 128);

        combine_all<<<cdiv((long)N_GENE * 32, 256), 256>>>(
            ln_g + l * 128, ln_b + l * 128, fw, l);
    }

    final2<<<TA, 256, TG_SMEM_FIN>>>(buf1, wimg + 6 * WIMGSZ, wimg + 7 * WIMGSZ,
                                     bfp, bo1, Wo2, bo2, (float*)d_out, N_ALL);
}